// round 1
// baseline (speedup 1.0000x reference)
#include <cuda_runtime.h>
#include <math.h>

#define S_LEN 2048
#define E_DIM 1024
#define N_HEADS 16
#define HD 64
#define BATCH 2
#define M_ROWS (BATCH * S_LEN)   // 4096

// Scratch (static __device__ arrays per harness rules)
__device__ float g_q[BATCH * N_HEADS * S_LEN * HD];
__device__ float g_k[BATCH * N_HEADS * S_LEN * HD];
__device__ float g_v[BATCH * N_HEADS * S_LEN * HD];
__device__ float g_ctx[(size_t)M_ROWS * E_DIM];
__device__ float g_cos[S_LEN * 32];
__device__ float g_sin[S_LEN * 32];

// ---------------------------------------------------------------------------
// RoPE cos/sin table: theta = s * 10000^{-j/32}, computed like the reference
// (inv_freq rounded to f32, f32 multiply, f32 cos/sin).
// ---------------------------------------------------------------------------
__global__ void rope_table_kernel() {
    int i = blockIdx.x * blockDim.x + threadIdx.x;
    if (i >= S_LEN * 32) return;
    int s = i >> 5, j = i & 31;
    float inv = (float)pow(10000.0, -(double)j / 32.0);
    float th = (float)s * inv;
    g_cos[i] = cosf(th);
    g_sin[i] = sinf(th);
}

// ---------------------------------------------------------------------------
// fp32 GEMM: C = A[M,K] @ B[K,N] + bias
// MODE 0: C row-major [M,N]
// MODE 1: scatter to [B,H,S,D]
// MODE 2: scatter to [B,H,S,D] with fused RoPE (Q/K projections)
// Tile 64x64, BK=16, 256 threads, 4x4 microtile.
// ---------------------------------------------------------------------------
template <int MODE>
__global__ void gemm_kernel(const float* __restrict__ A, const float* __restrict__ Bw,
                            const float* __restrict__ bias, float* __restrict__ C,
                            int M, int N, int K) {
    __shared__ float As[64][16];
    __shared__ float Bs[16][68];
    const int tid = threadIdx.x;
    const int tx = tid & 15, ty = tid >> 4;
    const int m0 = blockIdx.y << 6, n0 = blockIdx.x << 6;

    const int arow = tid >> 2, acol = (tid & 3) << 2;
    const int brow = tid >> 4, bcol = (tid & 15) << 2;
    const float* Ap = A + (size_t)(m0 + arow) * K + acol;
    const float* Bp = Bw + (size_t)brow * N + n0 + bcol;

    float acc[4][4] = {};

    for (int k0 = 0; k0 < K; k0 += 16) {
        float4 av = *(const float4*)(Ap + k0);
        float4 bv = *(const float4*)(Bp + (size_t)k0 * N);
        *(float4*)&As[arow][acol] = av;
        *(float4*)&Bs[brow][bcol] = bv;
        __syncthreads();
#pragma unroll
        for (int kk = 0; kk < 16; kk++) {
            float a0 = As[(ty << 2) + 0][kk];
            float a1 = As[(ty << 2) + 1][kk];
            float a2 = As[(ty << 2) + 2][kk];
            float a3 = As[(ty << 2) + 3][kk];
            float4 b = *(const float4*)&Bs[kk][tx << 2];
            acc[0][0] += a0 * b.x; acc[0][1] += a0 * b.y; acc[0][2] += a0 * b.z; acc[0][3] += a0 * b.w;
            acc[1][0] += a1 * b.x; acc[1][1] += a1 * b.y; acc[1][2] += a1 * b.z; acc[1][3] += a1 * b.w;
            acc[2][0] += a2 * b.x; acc[2][1] += a2 * b.y; acc[2][2] += a2 * b.z; acc[2][3] += a2 * b.w;
            acc[3][0] += a3 * b.x; acc[3][1] += a3 * b.y; acc[3][2] += a3 * b.z; acc[3][3] += a3 * b.w;
        }
        __syncthreads();
    }

#pragma unroll
    for (int i = 0; i < 4; i++) {
        int m = m0 + (ty << 2) + i;
#pragma unroll
        for (int j = 0; j < 4; j++) {
            int n = n0 + (tx << 2) + j;
            float val = acc[i][j] + bias[n];
            if (MODE == 0) {
                C[(size_t)m * N + n] = val;
            } else {
                int bb = m >> 11;          // m / S_LEN
                int s  = m & (S_LEN - 1);
                int h  = n >> 6;           // head (BN == 64 == one head)
                int d  = n & 63;
                float outv = val;
                if (MODE == 2) {
                    // partner dim d^32 lives exactly 8 lanes away (tx ^ 8)
                    float partner = __shfl_xor_sync(0xffffffffu, val, 8, 16);
                    int jf = d & 31;
                    float c  = g_cos[(s << 5) + jf];
                    float sn = g_sin[(s << 5) + jf];
                    outv = (d < 32) ? fmaf(val, c, -partner * sn)
                                    : fmaf(val, c,  partner * sn);
                }
                C[((((size_t)(bb * N_HEADS + h)) * S_LEN + s) << 6) + d] = outv;
            }
        }
    }
}

// ---------------------------------------------------------------------------
// Flash-attention: one block per (q-tile of 64, b*h). Online softmax,
// causal tile skip, padding mask. 256 threads, 4x4 microtiles.
// ---------------------------------------------------------------------------
__global__ void attn_kernel(const float* __restrict__ q, const float* __restrict__ k,
                            const float* __restrict__ v, const int* __restrict__ mask,
                            float* __restrict__ ctx) {
    extern __shared__ float sm[];
    float* Qs = sm;                 // [64][64]
    float* Ks = sm + 64 * 64;       // [64][65]
    float* Vs = Ks + 64 * 65;       // [64][65]
    float* Ps = Vs + 64 * 65;       // [64][65]
    int*   Ms = (int*)(Ps + 64 * 65);

    const int tid = threadIdx.x;
    const int tx = tid & 15, ty = tid >> 4;
    const int qt = blockIdx.x;
    const int bh = blockIdx.y;
    const int bb = bh >> 4;
    const int hh = bh & 15;
    const int q0 = qt << 6;
    const float* qb = q + (size_t)bh * S_LEN * HD;
    const float* kb = k + (size_t)bh * S_LEN * HD;
    const float* vb = v + (size_t)bh * S_LEN * HD;

    // Load Q tile once (float4, stride 64 -> aligned)
#pragma unroll
    for (int it = 0; it < 4; it++) {
        int idx = tid + it * 256;          // float4 index 0..1023
        int row = idx >> 4, c4 = (idx & 15) << 2;
        *(float4*)&Qs[(row << 6) + c4] = *(const float4*)&qb[((size_t)(q0 + row) << 6) + c4];
    }

    float o[4][4] = {};
    float l[4] = {0.f, 0.f, 0.f, 0.f};
    float mo[4] = {-1e30f, -1e30f, -1e30f, -1e30f};

    for (int t = 0; t <= qt; t++) {
        __syncthreads();  // protect prev-iter reads of Ks/Vs/Ps
        int k0 = t << 6;
#pragma unroll
        for (int it = 0; it < 4; it++) {
            int idx = tid + it * 256;
            int row = idx >> 4, c4 = (idx & 15) << 2;
            float4 kv = *(const float4*)&kb[((size_t)(k0 + row) << 6) + c4];
            float4 vv = *(const float4*)&vb[((size_t)(k0 + row) << 6) + c4];
            float* kd = &Ks[row * 65 + c4];
            kd[0] = kv.x; kd[1] = kv.y; kd[2] = kv.z; kd[3] = kv.w;
            float* vd = &Vs[row * 65 + c4];
            vd[0] = vv.x; vd[1] = vv.y; vd[2] = vv.z; vd[3] = vv.w;
        }
        if (tid < 64) Ms[tid] = mask[bb * S_LEN + k0 + tid];
        __syncthreads();

        // S = Q @ K^T
        float sv[4][4] = {};
#pragma unroll 4
        for (int d = 0; d < 64; d++) {
            float a0 = Qs[(((ty << 2) + 0) << 6) + d];
            float a1 = Qs[(((ty << 2) + 1) << 6) + d];
            float a2 = Qs[(((ty << 2) + 2) << 6) + d];
            float a3 = Qs[(((ty << 2) + 3) << 6) + d];
            float b0 = Ks[((tx << 2) + 0) * 65 + d];
            float b1 = Ks[((tx << 2) + 1) * 65 + d];
            float b2 = Ks[((tx << 2) + 2) * 65 + d];
            float b3 = Ks[((tx << 2) + 3) * 65 + d];
            sv[0][0] += a0 * b0; sv[0][1] += a0 * b1; sv[0][2] += a0 * b2; sv[0][3] += a0 * b3;
            sv[1][0] += a1 * b0; sv[1][1] += a1 * b1; sv[1][2] += a1 * b2; sv[1][3] += a1 * b3;
            sv[2][0] += a2 * b0; sv[2][1] += a2 * b1; sv[2][2] += a2 * b2; sv[2][3] += a2 * b3;
            sv[3][0] += a3 * b0; sv[3][1] += a3 * b1; sv[3][2] += a3 * b2; sv[3][3] += a3 * b3;
        }

        // scale + masks
#pragma unroll
        for (int j = 0; j < 4; j++) {
            int c = (tx << 2) + j;
            bool dead_pad = (Ms[c] == 0);
#pragma unroll
            for (int i = 0; i < 4; i++) {
                float x = sv[i][j] * 0.125f;
                bool dead = dead_pad || (t == qt && c > ((ty << 2) + i));
                sv[i][j] = dead ? -1e30f : x;
            }
        }

        // online softmax update
#pragma unroll
        for (int i = 0; i < 4; i++) {
            float rm = fmaxf(fmaxf(sv[i][0], sv[i][1]), fmaxf(sv[i][2], sv[i][3]));
#pragma unroll
            for (int off = 8; off >= 1; off >>= 1)
                rm = fmaxf(rm, __shfl_xor_sync(0xffffffffu, rm, off, 16));
            float mn = fmaxf(mo[i], rm);
            float alpha = __expf(mo[i] - mn);
            float rs = 0.f;
#pragma unroll
            for (int j = 0; j < 4; j++) {
                float p = __expf(sv[i][j] - mn);
                sv[i][j] = p;
                rs += p;
            }
#pragma unroll
            for (int off = 8; off >= 1; off >>= 1)
                rs += __shfl_xor_sync(0xffffffffu, rs, off, 16);
            l[i] = l[i] * alpha + rs;
            mo[i] = mn;
#pragma unroll
            for (int j = 0; j < 4; j++) o[i][j] *= alpha;
#pragma unroll
            for (int j = 0; j < 4; j++)
                Ps[((ty << 2) + i) * 65 + (tx << 2) + j] = sv[i][j];
        }
        __syncthreads();

        // O += P @ V
#pragma unroll 4
        for (int kk = 0; kk < 64; kk++) {
            float a0 = Ps[(((ty << 2) + 0)) * 65 + kk];
            float a1 = Ps[(((ty << 2) + 1)) * 65 + kk];
            float a2 = Ps[(((ty << 2) + 2)) * 65 + kk];
            float a3 = Ps[(((ty << 2) + 3)) * 65 + kk];
            float b0 = Vs[kk * 65 + (tx << 2) + 0];
            float b1 = Vs[kk * 65 + (tx << 2) + 1];
            float b2 = Vs[kk * 65 + (tx << 2) + 2];
            float b3 = Vs[kk * 65 + (tx << 2) + 3];
            o[0][0] += a0 * b0; o[0][1] += a0 * b1; o[0][2] += a0 * b2; o[0][3] += a0 * b3;
            o[1][0] += a1 * b0; o[1][1] += a1 * b1; o[1][2] += a1 * b2; o[1][3] += a1 * b3;
            o[2][0] += a2 * b0; o[2][1] += a2 * b1; o[2][2] += a2 * b2; o[2][3] += a2 * b3;
            o[3][0] += a3 * b0; o[3][1] += a3 * b1; o[3][2] += a3 * b2; o[3][3] += a3 * b3;
        }
    }

    // write ctx [B, S, H*D]
#pragma unroll
    for (int i = 0; i < 4; i++) {
        float inv_l = 1.0f / l[i];
        int s = q0 + (ty << 2) + i;
#pragma unroll
        for (int j = 0; j < 4; j++) {
            ctx[((size_t)(bb * S_LEN + s)) * E_DIM + (hh << 6) + (tx << 2) + j] = o[i][j] * inv_l;
        }
    }
}

// ---------------------------------------------------------------------------
extern "C" void kernel_launch(void* const* d_in, const int* in_sizes, int n_in,
                              void* d_out, int out_size) {
    const float* x    = (const float*)d_in[0];
    const int*   mask = (const int*)d_in[1];
    const float* Wq   = (const float*)d_in[2];
    const float* bq   = (const float*)d_in[3];
    const float* Wk   = (const float*)d_in[4];
    const float* bk   = (const float*)d_in[5];
    const float* Wv   = (const float*)d_in[6];
    const float* bv   = (const float*)d_in[7];
    const float* Wo   = (const float*)d_in[8];
    const float* bo   = (const float*)d_in[9];
    float* out = (float*)d_out;

    float *pq, *pk, *pv, *pctx;
    cudaGetSymbolAddress((void**)&pq, g_q);
    cudaGetSymbolAddress((void**)&pk, g_k);
    cudaGetSymbolAddress((void**)&pv, g_v);
    cudaGetSymbolAddress((void**)&pctx, g_ctx);

    rope_table_kernel<<<(S_LEN * 32 + 255) / 256, 256>>>();

    dim3 gg(E_DIM / 64, M_ROWS / 64);
    gemm_kernel<2><<<gg, 256>>>(x, Wq, bq, pq, M_ROWS, E_DIM, E_DIM);
    gemm_kernel<2><<<gg, 256>>>(x, Wk, bk, pk, M_ROWS, E_DIM, E_DIM);
    gemm_kernel<1><<<gg, 256>>>(x, Wv, bv, pv, M_ROWS, E_DIM, E_DIM);

    const int SMEM = (64 * 64 + 3 * 64 * 65) * 4 + 64 * 4;
    cudaFuncSetAttribute(attn_kernel, cudaFuncAttributeMaxDynamicSharedMemorySize, SMEM);
    attn_kernel<<<dim3(S_LEN / 64, BATCH * N_HEADS), 256, SMEM>>>(pq, pk, pv, mask, pctx);

    gemm_kernel<0><<<gg, 256>>>(pctx, Wo, bo, out, M_ROWS, E_DIM, E_DIM);
}

// round 2
// speedup vs baseline: 1.0835x; 1.0835x over previous
#include <cuda_runtime.h>
#include <math.h>

#define S_LEN 2048
#define E_DIM 1024
#define N_HEADS 16
#define HD 64
#define BATCH 2
#define M_ROWS (BATCH * S_LEN)   // 4096

// Scratch (static __device__ arrays per harness rules)
__device__ float g_q[BATCH * N_HEADS * S_LEN * HD];
__device__ float g_k[BATCH * N_HEADS * S_LEN * HD];
__device__ float g_v[BATCH * N_HEADS * S_LEN * HD];
__device__ float g_ctx[(size_t)M_ROWS * E_DIM];
__device__ float g_cos[S_LEN * 32];
__device__ float g_sin[S_LEN * 32];

// ---------------------------------------------------------------------------
// RoPE cos/sin table
// ---------------------------------------------------------------------------
__global__ void rope_table_kernel() {
    int i = blockIdx.x * blockDim.x + threadIdx.x;
    if (i >= S_LEN * 32) return;
    int s = i >> 5, j = i & 31;
    float inv = (float)pow(10000.0, -(double)j / 32.0);
    float th = (float)s * inv;
    g_cos[i] = cosf(th);
    g_sin[i] = sinf(th);
}

// ---------------------------------------------------------------------------
// fp32 GEMM: C = A[M,K] @ B[K,N] + bias.  128x128 tile, BK=16, 256 thr, 8x8 micro.
// MODE 0: row-major [M,N]; MODE 1: scatter [B,H,S,D]; MODE 2: scatter + RoPE.
// ---------------------------------------------------------------------------
template <int MODE>
__global__ __launch_bounds__(256)
void gemm_kernel(const float* __restrict__ A, const float* __restrict__ Bw,
                 const float* __restrict__ bias, float* __restrict__ C,
                 int M, int N, int K) {
    __shared__ float As[16][132];   // transposed: As[k][m]
    __shared__ float Bs[16][128];   // Bs[k][n]
    const int tid = threadIdx.x;
    const int tx = tid & 15, ty = tid >> 4;
    const int m0 = blockIdx.y << 7, n0 = blockIdx.x << 7;

    const int arow = tid >> 2;            // 0..63
    const int acol = (tid & 3) << 2;      // 0,4,8,12
    const int brow = tid >> 5;            // 0..7
    const int bcol = (tid & 31) << 2;     // 0..124

    const float* Ap0 = A + (size_t)(m0 + arow) * K + acol;
    const float* Ap1 = Ap0 + (size_t)64 * K;
    const float* Bp0 = Bw + (size_t)brow * N + n0 + bcol;
    const float* Bp1 = Bp0 + (size_t)8 * N;

    float4 a0 = *(const float4*)Ap0;
    float4 a1 = *(const float4*)Ap1;
    float4 b0 = *(const float4*)Bp0;
    float4 b1 = *(const float4*)Bp1;

    float acc[8][8] = {};

    for (int k0 = 0; k0 < K; k0 += 16) {
        As[acol + 0][arow] = a0.x; As[acol + 1][arow] = a0.y;
        As[acol + 2][arow] = a0.z; As[acol + 3][arow] = a0.w;
        As[acol + 0][arow + 64] = a1.x; As[acol + 1][arow + 64] = a1.y;
        As[acol + 2][arow + 64] = a1.z; As[acol + 3][arow + 64] = a1.w;
        *(float4*)&Bs[brow][bcol] = b0;
        *(float4*)&Bs[brow + 8][bcol] = b1;
        __syncthreads();
        if (k0 + 16 < K) {
            a0 = *(const float4*)(Ap0 + k0 + 16);
            a1 = *(const float4*)(Ap1 + k0 + 16);
            b0 = *(const float4*)(Bp0 + (size_t)(k0 + 16) * N);
            b1 = *(const float4*)(Bp1 + (size_t)(k0 + 16) * N);
        }
#pragma unroll
        for (int kk = 0; kk < 16; kk++) {
            float4 af0 = *(const float4*)&As[kk][ty << 2];
            float4 af1 = *(const float4*)&As[kk][64 + (ty << 2)];
            float4 bf0 = *(const float4*)&Bs[kk][tx << 2];
            float4 bf1 = *(const float4*)&Bs[kk][64 + (tx << 2)];
            float a[8] = {af0.x, af0.y, af0.z, af0.w, af1.x, af1.y, af1.z, af1.w};
            float b[8] = {bf0.x, bf0.y, bf0.z, bf0.w, bf1.x, bf1.y, bf1.z, bf1.w};
#pragma unroll
            for (int i = 0; i < 8; i++)
#pragma unroll
                for (int j = 0; j < 8; j++)
                    acc[i][j] = fmaf(a[i], b[j], acc[i][j]);
        }
        __syncthreads();
    }

#pragma unroll
    for (int ri = 0; ri < 2; ri++)
#pragma unroll
    for (int i = 0; i < 4; i++) {
        int m = m0 + ri * 64 + (ty << 2) + i;
        int bb = m >> 11;
        int s = m & (S_LEN - 1);
#pragma unroll
        for (int ci = 0; ci < 2; ci++) {
            int nb = n0 + ci * 64 + (tx << 2);
            float r[4];
#pragma unroll
            for (int j = 0; j < 4; j++) {
                float val = acc[ri * 4 + i][ci * 4 + j] + bias[nb + j];
                if (MODE == 2) {
                    // partner dim d^32 lives 8 lanes away within the 16-lane group
                    float partner = __shfl_xor_sync(0xffffffffu, val, 8, 16);
                    int d = (nb + j) & 63;
                    int jf = d & 31;
                    float c  = g_cos[(s << 5) + jf];
                    float sn = g_sin[(s << 5) + jf];
                    val = (d < 32) ? fmaf(val, c, -partner * sn)
                                   : fmaf(val, c,  partner * sn);
                }
                r[j] = val;
            }
            if (MODE == 0) {
                *(float4*)&C[(size_t)m * N + nb] = make_float4(r[0], r[1], r[2], r[3]);
            } else {
                int h  = nb >> 6;
                int d0 = nb & 63;
                *(float4*)&C[((((size_t)(bb * N_HEADS + h)) * S_LEN + s) << 6) + d0] =
                    make_float4(r[0], r[1], r[2], r[3]);
            }
        }
    }
}

// ---------------------------------------------------------------------------
// Flash-attention: Q-tile 128, KV-tile 64, 256 threads, 8x4 microtiles.
// ---------------------------------------------------------------------------
__global__ __launch_bounds__(256)
void attn_kernel(const float* __restrict__ q, const float* __restrict__ k,
                 const float* __restrict__ v, const int* __restrict__ mask,
                 float* __restrict__ ctx) {
    extern __shared__ float sm[];
    float* Qt = sm;                    // [64][132]  transposed Q
    float* Ks = Qt + 64 * 132;         // [64][65]   row-major K
    float* Vs = Ks + 64 * 65;          // [64][68]   row-major V
    float* Ps = Vs + 64 * 68;          // [128][68]  row-major P
    int*   Ms = (int*)(Ps + 128 * 68); // [64]

    const int tid = threadIdx.x;
    const int tx = tid & 15, ty = tid >> 4;
    const int qt = gridDim.x - 1 - blockIdx.x;   // heavy blocks first
    const int bh = blockIdx.y;
    const int bb = bh >> 4, hh = bh & 15;
    const int q0 = qt << 7;
    const float* qb = q + (size_t)bh * S_LEN * HD;
    const float* kb = k + (size_t)bh * S_LEN * HD;
    const float* vb = v + (size_t)bh * S_LEN * HD;

    // Load + transpose Q tile [128 x 64] -> Qt[d][row]
#pragma unroll
    for (int it = 0; it < 8; it++) {
        int idx = tid + it * 256;
        int row = idx >> 4, c4 = (idx & 15) << 2;
        float4 qv = *(const float4*)&qb[((size_t)(q0 + row) << 6) + c4];
        Qt[(c4 + 0) * 132 + row] = qv.x;
        Qt[(c4 + 1) * 132 + row] = qv.y;
        Qt[(c4 + 2) * 132 + row] = qv.z;
        Qt[(c4 + 3) * 132 + row] = qv.w;
    }

    float o[8][4] = {};
    float l[8] = {};
    float mo[8];
#pragma unroll
    for (int i = 0; i < 8; i++) mo[i] = -1e30f;

    const int nt = 2 * (qt + 1);
    for (int t = 0; t < nt; t++) {
        const int k0 = t << 6;
        __syncthreads();
#pragma unroll
        for (int it = 0; it < 4; it++) {
            int idx = tid + it * 256;
            int row = idx >> 4, c4 = (idx & 15) << 2;
            float4 kv = *(const float4*)&kb[((size_t)(k0 + row) << 6) + c4];
            Ks[row * 65 + c4 + 0] = kv.x;
            Ks[row * 65 + c4 + 1] = kv.y;
            Ks[row * 65 + c4 + 2] = kv.z;
            Ks[row * 65 + c4 + 3] = kv.w;
            float4 vv = *(const float4*)&vb[((size_t)(k0 + row) << 6) + c4];
            *(float4*)&Vs[row * 68 + c4] = vv;
        }
        if (tid < 64) Ms[tid] = mask[bb * S_LEN + k0 + tid];
        __syncthreads();

        // S = Q @ K^T
        float sv[8][4] = {};
#pragma unroll 2
        for (int d = 0; d < 64; d++) {
            float4 af0 = *(const float4*)&Qt[d * 132 + (ty << 2)];
            float4 af1 = *(const float4*)&Qt[d * 132 + 64 + (ty << 2)];
            float a[8] = {af0.x, af0.y, af0.z, af0.w, af1.x, af1.y, af1.z, af1.w};
            float b0 = Ks[((tx << 2) + 0) * 65 + d];
            float b1 = Ks[((tx << 2) + 1) * 65 + d];
            float b2 = Ks[((tx << 2) + 2) * 65 + d];
            float b3 = Ks[((tx << 2) + 3) * 65 + d];
#pragma unroll
            for (int i = 0; i < 8; i++) {
                sv[i][0] = fmaf(a[i], b0, sv[i][0]);
                sv[i][1] = fmaf(a[i], b1, sv[i][1]);
                sv[i][2] = fmaf(a[i], b2, sv[i][2]);
                sv[i][3] = fmaf(a[i], b3, sv[i][3]);
            }
        }

        // scale + masks
        const bool diag = (k0 >= q0);
#pragma unroll
        for (int j = 0; j < 4; j++) {
            int cloc = (tx << 2) + j;
            bool pad_dead = (Ms[cloc] == 0);
            int cg = k0 + cloc;
#pragma unroll
            for (int i = 0; i < 8; i++) {
                int rloc = (i < 4) ? ((ty << 2) + i) : (64 + (ty << 2) + i - 4);
                float x = sv[i][j] * 0.125f;
                bool dead = pad_dead || (diag && cg > q0 + rloc);
                sv[i][j] = dead ? -1e30f : x;
            }
        }

        // online softmax update + write P
#pragma unroll
        for (int i = 0; i < 8; i++) {
            float rm = fmaxf(fmaxf(sv[i][0], sv[i][1]), fmaxf(sv[i][2], sv[i][3]));
            rm = fmaxf(rm, __shfl_xor_sync(0xffffffffu, rm, 8, 16));
            rm = fmaxf(rm, __shfl_xor_sync(0xffffffffu, rm, 4, 16));
            rm = fmaxf(rm, __shfl_xor_sync(0xffffffffu, rm, 2, 16));
            rm = fmaxf(rm, __shfl_xor_sync(0xffffffffu, rm, 1, 16));
            float mn = fmaxf(mo[i], rm);
            float alpha = __expf(mo[i] - mn);
            float rs = 0.f;
#pragma unroll
            for (int j = 0; j < 4; j++) {
                float p = __expf(sv[i][j] - mn);
                sv[i][j] = p;
                rs += p;
            }
            rs += __shfl_xor_sync(0xffffffffu, rs, 8, 16);
            rs += __shfl_xor_sync(0xffffffffu, rs, 4, 16);
            rs += __shfl_xor_sync(0xffffffffu, rs, 2, 16);
            rs += __shfl_xor_sync(0xffffffffu, rs, 1, 16);
            l[i] = l[i] * alpha + rs;
            mo[i] = mn;
#pragma unroll
            for (int j = 0; j < 4; j++) o[i][j] *= alpha;
            int rloc = (i < 4) ? ((ty << 2) + i) : (64 + (ty << 2) + i - 4);
            *(float4*)&Ps[rloc * 68 + (tx << 2)] =
                make_float4(sv[i][0], sv[i][1], sv[i][2], sv[i][3]);
        }
        __syncthreads();

        // O += P @ V  (2-kk chunks, float2 P reads)
#pragma unroll 2
        for (int kk = 0; kk < 64; kk += 2) {
            float4 v0 = *(const float4*)&Vs[kk * 68 + (tx << 2)];
            float4 v1 = *(const float4*)&Vs[(kk + 1) * 68 + (tx << 2)];
#pragma unroll
            for (int i = 0; i < 8; i++) {
                int rloc = (i < 4) ? ((ty << 2) + i) : (64 + (ty << 2) + i - 4);
                float2 p = *(const float2*)&Ps[rloc * 68 + kk];
                o[i][0] = fmaf(p.y, v1.x, fmaf(p.x, v0.x, o[i][0]));
                o[i][1] = fmaf(p.y, v1.y, fmaf(p.x, v0.y, o[i][1]));
                o[i][2] = fmaf(p.y, v1.z, fmaf(p.x, v0.z, o[i][2]));
                o[i][3] = fmaf(p.y, v1.w, fmaf(p.x, v0.w, o[i][3]));
            }
        }
    }

    // write ctx [B, S, H*D]
#pragma unroll
    for (int i = 0; i < 8; i++) {
        float inv_l = 1.0f / l[i];
        int rloc = (i < 4) ? ((ty << 2) + i) : (64 + (ty << 2) + i - 4);
        int s = q0 + rloc;
        float4 ov = make_float4(o[i][0] * inv_l, o[i][1] * inv_l,
                                o[i][2] * inv_l, o[i][3] * inv_l);
        *(float4*)&ctx[((size_t)(bb * S_LEN + s)) * E_DIM + (hh << 6) + (tx << 2)] = ov;
    }
}

// ---------------------------------------------------------------------------
extern "C" void kernel_launch(void* const* d_in, const int* in_sizes, int n_in,
                              void* d_out, int out_size) {
    const float* x    = (const float*)d_in[0];
    const int*   mask = (const int*)d_in[1];
    const float* Wq   = (const float*)d_in[2];
    const float* bq   = (const float*)d_in[3];
    const float* Wk   = (const float*)d_in[4];
    const float* bk   = (const float*)d_in[5];
    const float* Wv   = (const float*)d_in[6];
    const float* bv   = (const float*)d_in[7];
    const float* Wo   = (const float*)d_in[8];
    const float* bo   = (const float*)d_in[9];
    float* out = (float*)d_out;

    float *pq, *pk, *pv, *pctx;
    cudaGetSymbolAddress((void**)&pq, g_q);
    cudaGetSymbolAddress((void**)&pk, g_k);
    cudaGetSymbolAddress((void**)&pv, g_v);
    cudaGetSymbolAddress((void**)&pctx, g_ctx);

    rope_table_kernel<<<(S_LEN * 32 + 255) / 256, 256>>>();

    dim3 gg(E_DIM / 128, M_ROWS / 128);
    gemm_kernel<2><<<gg, 256>>>(x, Wq, bq, pq, M_ROWS, E_DIM, E_DIM);
    gemm_kernel<2><<<gg, 256>>>(x, Wk, bk, pk, M_ROWS, E_DIM, E_DIM);
    gemm_kernel<1><<<gg, 256>>>(x, Wv, bv, pv, M_ROWS, E_DIM, E_DIM);

    const int SMEM = (64 * 132 + 64 * 65 + 64 * 68 + 128 * 68) * 4 + 64 * 4;
    cudaFuncSetAttribute(attn_kernel, cudaFuncAttributeMaxDynamicSharedMemorySize, SMEM);
    attn_kernel<<<dim3(S_LEN / 128, BATCH * N_HEADS), 256, SMEM>>>(pq, pk, pv, mask, pctx);

    gemm_kernel<0><<<gg, 256>>>(pctx, Wo, bo, out, M_ROWS, E_DIM, E_DIM);
}

// round 4
// speedup vs baseline: 1.5722x; 1.4510x over previous
#include <cuda_runtime.h>
#include <cuda_bf16.h>
#include <math.h>
#include <stdint.h>

#define S_LEN 2048
#define E_DIM 1024
#define N_HEADS 16
#define HD 64
#define BATCH 2
#define M_ROWS 4096

// ---------------- scratch (static __device__, per harness rules) -----------
__device__ __align__(256) float g_q[BATCH * N_HEADS * S_LEN * HD];
__device__ __align__(256) float g_k[BATCH * N_HEADS * S_LEN * HD];
__device__ __align__(256) float g_v[BATCH * N_HEADS * S_LEN * HD];
__device__ __align__(256) float g_ctx[(size_t)M_ROWS * E_DIM];
__device__ __align__(256) float g_cos[S_LEN * 32];
__device__ __align__(256) float g_sin[S_LEN * 32];

__device__ __align__(256) __nv_bfloat16 g_xhi[(size_t)M_ROWS * E_DIM];
__device__ __align__(256) __nv_bfloat16 g_xlo[(size_t)M_ROWS * E_DIM];
__device__ __align__(256) __nv_bfloat16 g_chi[(size_t)M_ROWS * E_DIM];
__device__ __align__(256) __nv_bfloat16 g_clo[(size_t)M_ROWS * E_DIM];
__device__ __align__(256) __nv_bfloat16 g_wthi[4][(size_t)E_DIM * E_DIM];  // [N][K]
__device__ __align__(256) __nv_bfloat16 g_wtlo[4][(size_t)E_DIM * E_DIM];

// ---------------- helpers ---------------------------------------------------
__device__ __forceinline__ uint32_t smem_u32(const void* p) {
    uint32_t a;
    asm("{ .reg .u64 t; cvta.to.shared.u64 t, %1; cvt.u32.u64 %0, t; }"
        : "=r"(a) : "l"(p));
    return a;
}
__device__ __forceinline__ void ldmatrix_x4(uint32_t* r, uint32_t addr) {
    asm volatile("ldmatrix.sync.aligned.m8n8.x4.shared.b16 {%0,%1,%2,%3}, [%4];"
                 : "=r"(r[0]), "=r"(r[1]), "=r"(r[2]), "=r"(r[3]) : "r"(addr));
}
__device__ __forceinline__ void mma16816(float* c, const uint32_t* a, const uint32_t* b) {
    asm volatile(
        "mma.sync.aligned.m16n8k16.row.col.f32.bf16.bf16.f32 "
        "{%0,%1,%2,%3}, {%4,%5,%6,%7}, {%8,%9}, {%0,%1,%2,%3};"
        : "+f"(c[0]), "+f"(c[1]), "+f"(c[2]), "+f"(c[3])
        : "r"(a[0]), "r"(a[1]), "r"(a[2]), "r"(a[3]), "r"(b[0]), "r"(b[1]));
}
__device__ __forceinline__ void cp_async16(uint32_t dst, const void* src) {
    asm volatile("cp.async.cg.shared.global [%0], [%1], 16;" :: "r"(dst), "l"(src));
}

// ---------------------------------------------------------------------------
__global__ void rope_table_kernel() {
    int i = blockIdx.x * blockDim.x + threadIdx.x;
    if (i >= S_LEN * 32) return;
    int s = i >> 5, j = i & 31;
    float inv = (float)pow(10000.0, -(double)j / 32.0);
    float th = (float)s * inv;
    g_cos[i] = cosf(th);
    g_sin[i] = sinf(th);
}

// split fp32 -> (hi, lo) bf16
__global__ void cvt_split_kernel(const float4* __restrict__ src,
                                 __nv_bfloat162* __restrict__ hi,
                                 __nv_bfloat162* __restrict__ lo, int n4) {
    int i = blockIdx.x * blockDim.x + threadIdx.x;
    if (i >= n4) return;
    float4 v = src[i];
    __nv_bfloat162 h01 = __floats2bfloat162_rn(v.x, v.y);
    __nv_bfloat162 h23 = __floats2bfloat162_rn(v.z, v.w);
    float2 f01 = __bfloat1622float2(h01);
    float2 f23 = __bfloat1622float2(h23);
    hi[2 * i] = h01;
    hi[2 * i + 1] = h23;
    lo[2 * i] = __floats2bfloat162_rn(v.x - f01.x, v.y - f01.y);
    lo[2 * i + 1] = __floats2bfloat162_rn(v.z - f23.x, v.w - f23.y);
}

// transpose-convert: W[K][N] f32 -> Thi/Tlo [N][K] bf16
__global__ void cvt_transpose_kernel(const float* __restrict__ W,
                                     __nv_bfloat16* __restrict__ Thi,
                                     __nv_bfloat16* __restrict__ Tlo) {
    __shared__ float t[32][33];
    int bx = blockIdx.x, by = blockIdx.y;
    int tid = threadIdx.x;
#pragma unroll
    for (int it = 0; it < 4; it++) {
        int idx = tid + it * 256;
        int r = idx >> 5, c = idx & 31;
        t[r][c] = W[(size_t)(by * 32 + r) * E_DIM + bx * 32 + c];
    }
    __syncthreads();
#pragma unroll
    for (int it = 0; it < 4; it++) {
        int idx = tid + it * 256;
        int r = idx >> 5, c = idx & 31;
        float x = t[c][r];
        __nv_bfloat16 h = __float2bfloat16(x);
        size_t o = (size_t)(bx * 32 + r) * E_DIM + by * 32 + c;
        Thi[o] = h;
        Tlo[o] = __float2bfloat16(x - __bfloat162float(h));
    }
}

// ---------------------------------------------------------------------------
// Split-bf16 mma.sync GEMM: C[M,N] = A @ W  (W transposed [N][K]).
// 128x128 tile, BK=32, 8 warps (4 along M x 2 along N), warp tile 32x64.
// 3 MMA chains: Ahi*Bhi + Ahi*Blo + Alo*Bhi, fp32 accumulate.
// MODE 0: row-major; MODE 1: scatter [B,H,S,D]; MODE 2: scatter + RoPE.
// ---------------------------------------------------------------------------
#define TSTRIDE 40                    // bf16 per smem row (32 + 8 pad)
#define TILE_BYTES (128 * TSTRIDE * 2)  // 10240
#define NCHUNK 32

__device__ __forceinline__ void load_chunk_async(
    const __nv_bfloat16* __restrict__ Ahi, const __nv_bfloat16* __restrict__ Alo,
    const __nv_bfloat16* __restrict__ Bhi, const __nv_bfloat16* __restrict__ Blo,
    int m0, int n0, int k0, uint32_t st, int tid) {
    const __nv_bfloat16* srcs[4] = {Ahi, Alo, Bhi, Blo};
    int r0s[4] = {m0, m0, n0, n0};
#pragma unroll
    for (int tno = 0; tno < 4; tno++) {
        uint32_t sdst = st + tno * TILE_BYTES;
        const __nv_bfloat16* src = srcs[tno];
        int row0 = r0s[tno];
#pragma unroll
        for (int it = 0; it < 2; it++) {
            int idx = tid + it * 256;        // 0..511
            int r = idx >> 2, seg = idx & 3;
            cp_async16(sdst + (uint32_t)(r * TSTRIDE + seg * 8) * 2,
                       src + (size_t)(row0 + r) * E_DIM + k0 + seg * 8);
        }
    }
}

template <int MODE>
__global__ __launch_bounds__(256)
void tgemm_kernel(const __nv_bfloat16* __restrict__ Ahi,
                  const __nv_bfloat16* __restrict__ Alo,
                  const __nv_bfloat16* __restrict__ Bthi,
                  const __nv_bfloat16* __restrict__ Btlo,
                  const float* __restrict__ bias, float* __restrict__ C) {
    extern __shared__ __align__(1024) char dsm[];
    const uint32_t sbase = smem_u32(dsm);
    const int tid = threadIdx.x;
    const int wid = tid >> 5, lane = tid & 31;
    const int wm = wid & 3, wn = wid >> 2;
    const int g = lane >> 2, tg = lane & 3;
    const int m0 = blockIdx.y << 7, n0 = blockIdx.x << 7;

    float acc[2][8][4] = {};

    // prologue
    load_chunk_async(Ahi, Alo, Bthi, Btlo, m0, n0, 0, sbase, tid);
    asm volatile("cp.async.commit_group;");

    for (int c = 0; c < NCHUNK; c++) {
        if (c + 1 < NCHUNK) {
            load_chunk_async(Ahi, Alo, Bthi, Btlo, m0, n0, (c + 1) << 5,
                             sbase + ((c + 1) & 1) * 4 * TILE_BYTES, tid);
            asm volatile("cp.async.commit_group;");
            asm volatile("cp.async.wait_group 1;");
        } else {
            asm volatile("cp.async.wait_group 0;");
        }
        __syncthreads();

        const uint32_t st = sbase + (c & 1) * 4 * TILE_BYTES;
        const uint32_t Ahi_s = st, Alo_s = st + TILE_BYTES;
        const uint32_t Bhi_s = st + 2 * TILE_BYTES, Blo_s = st + 3 * TILE_BYTES;

#pragma unroll
        for (int ks = 0; ks < 2; ks++) {
            uint32_t ah[2][4], al[2][4];
#pragma unroll
            for (int mt = 0; mt < 2; mt++) {
                int row = wm * 32 + mt * 16 + (lane & 15);
                int kb = ks * 16 + ((lane >> 4) << 3);
                uint32_t off = (uint32_t)(row * TSTRIDE + kb) * 2;
                ldmatrix_x4(ah[mt], Ahi_s + off);
                ldmatrix_x4(al[mt], Alo_s + off);
            }
#pragma unroll
            for (int np = 0; np < 4; np++) {
                uint32_t bh[4], bl[4];
                int row = wn * 64 + np * 16 + ((lane >> 4) << 3) + (lane & 7);
                int kb = ks * 16 + (((lane >> 3) & 1) << 3);
                uint32_t off = (uint32_t)(row * TSTRIDE + kb) * 2;
                ldmatrix_x4(bh, Bhi_s + off);
                ldmatrix_x4(bl, Blo_s + off);
#pragma unroll
                for (int half = 0; half < 2; half++) {
                    int nt = 2 * np + half;
#pragma unroll
                    for (int mt = 0; mt < 2; mt++) {
                        mma16816(acc[mt][nt], ah[mt], bh + 2 * half);
                        mma16816(acc[mt][nt], ah[mt], bl + 2 * half);
                        mma16816(acc[mt][nt], al[mt], bh + 2 * half);
                    }
                }
            }
        }
        __syncthreads();
    }

    // epilogue
#pragma unroll
    for (int mt = 0; mt < 2; mt++) {
#pragma unroll
        for (int h2 = 0; h2 < 2; h2++) {
            int m = m0 + wm * 32 + mt * 16 + g + h2 * 8;
            int bb = m >> 11, s = m & (S_LEN - 1);
            if (MODE == 0) {
                float* dst = &C[(size_t)m * E_DIM + n0 + wn * 64];
#pragma unroll
                for (int nt = 0; nt < 8; nt++) {
                    int col = nt * 8 + tg * 2;
                    float2 bv = *(const float2*)&bias[n0 + wn * 64 + col];
                    *(float2*)&dst[col] = make_float2(acc[mt][nt][h2 * 2 + 0] + bv.x,
                                                      acc[mt][nt][h2 * 2 + 1] + bv.y);
                }
            } else {
                int h = (n0 + wn * 64) >> 6;
                float* dst = &C[(((size_t)(bb * N_HEADS + h)) * S_LEN + s) << 6];
                float vals[8][2];
#pragma unroll
                for (int nt = 0; nt < 8; nt++) {
                    int col = nt * 8 + tg * 2;
                    float2 bv = *(const float2*)&bias[n0 + wn * 64 + col];
                    vals[nt][0] = acc[mt][nt][h2 * 2 + 0] + bv.x;
                    vals[nt][1] = acc[mt][nt][h2 * 2 + 1] + bv.y;
                }
                if (MODE == 2) {
#pragma unroll
                    for (int nt = 0; nt < 4; nt++) {
#pragma unroll
                        for (int jj = 0; jj < 2; jj++) {
                            int d = nt * 8 + tg * 2 + jj;
                            float cth = g_cos[(s << 5) + d];
                            float sth = g_sin[(s << 5) + d];
                            float lo = vals[nt][jj], hi = vals[nt + 4][jj];
                            vals[nt][jj]     = fmaf(lo, cth, -hi * sth);
                            vals[nt + 4][jj] = fmaf(hi, cth,  lo * sth);
                        }
                    }
                }
#pragma unroll
                for (int nt = 0; nt < 8; nt++)
                    *(float2*)&dst[nt * 8 + tg * 2] = make_float2(vals[nt][0], vals[nt][1]);
            }
        }
    }
}

// ---------------------------------------------------------------------------
// Flash-attention (proven fp32 path): Q-tile 128, KV-tile 64, 256 thr, 8x4.
// ---------------------------------------------------------------------------
__global__ __launch_bounds__(256)
void attn_kernel(const float* __restrict__ q, const float* __restrict__ k,
                 const float* __restrict__ v, const int* __restrict__ mask,
                 float* __restrict__ ctx) {
    extern __shared__ float sm[];
    float* Qt = sm;                    // [64][132]
    float* Ks = Qt + 64 * 132;         // [64][65]
    float* Vs = Ks + 64 * 65;          // [64][68]
    float* Ps = Vs + 64 * 68;          // [128][68]
    int*   Ms = (int*)(Ps + 128 * 68);

    const int tid = threadIdx.x;
    const int tx = tid & 15, ty = tid >> 4;
    const int qt = gridDim.x - 1 - blockIdx.x;
    const int bh = blockIdx.y;
    const int bb = bh >> 4, hh = bh & 15;
    const int q0 = qt << 7;
    const float* qb = q + (size_t)bh * S_LEN * HD;
    const float* kb = k + (size_t)bh * S_LEN * HD;
    const float* vb = v + (size_t)bh * S_LEN * HD;

#pragma unroll
    for (int it = 0; it < 8; it++) {
        int idx = tid + it * 256;
        int row = idx >> 4, c4 = (idx & 15) << 2;
        float4 qv = *(const float4*)&qb[((size_t)(q0 + row) << 6) + c4];
        Qt[(c4 + 0) * 132 + row] = qv.x;
        Qt[(c4 + 1) * 132 + row] = qv.y;
        Qt[(c4 + 2) * 132 + row] = qv.z;
        Qt[(c4 + 3) * 132 + row] = qv.w;
    }

    float o[8][4] = {};
    float l[8] = {};
    float mo[8];
#pragma unroll
    for (int i = 0; i < 8; i++) mo[i] = -1e30f;

    const int nt = 2 * (qt + 1);
    for (int t = 0; t < nt; t++) {
        const int k0 = t << 6;
        __syncthreads();
#pragma unroll
        for (int it = 0; it < 4; it++) {
            int idx = tid + it * 256;
            int row = idx >> 4, c4 = (idx & 15) << 2;
            float4 kv = *(const float4*)&kb[((size_t)(k0 + row) << 6) + c4];
            Ks[row * 65 + c4 + 0] = kv.x;
            Ks[row * 65 + c4 + 1] = kv.y;
            Ks[row * 65 + c4 + 2] = kv.z;
            Ks[row * 65 + c4 + 3] = kv.w;
            float4 vv = *(const float4*)&vb[((size_t)(k0 + row) << 6) + c4];
            *(float4*)&Vs[row * 68 + c4] = vv;
        }
        if (tid < 64) Ms[tid] = mask[bb * S_LEN + k0 + tid];
        __syncthreads();

        float sv[8][4] = {};
#pragma unroll 2
        for (int d = 0; d < 64; d++) {
            float4 af0 = *(const float4*)&Qt[d * 132 + (ty << 2)];
            float4 af1 = *(const float4*)&Qt[d * 132 + 64 + (ty << 2)];
            float a[8] = {af0.x, af0.y, af0.z, af0.w, af1.x, af1.y, af1.z, af1.w};
            float b0 = Ks[((tx << 2) + 0) * 65 + d];
            float b1 = Ks[((tx << 2) + 1) * 65 + d];
            float b2 = Ks[((tx << 2) + 2) * 65 + d];
            float b3 = Ks[((tx << 2) + 3) * 65 + d];
#pragma unroll
            for (int i = 0; i < 8; i++) {
                sv[i][0] = fmaf(a[i], b0, sv[i][0]);
                sv[i][1] = fmaf(a[i], b1, sv[i][1]);
                sv[i][2] = fmaf(a[i], b2, sv[i][2]);
                sv[i][3] = fmaf(a[i], b3, sv[i][3]);
            }
        }

        const bool diag = (k0 >= q0);
#pragma unroll
        for (int j = 0; j < 4; j++) {
            int cloc = (tx << 2) + j;
            bool pad_dead = (Ms[cloc] == 0);
            int cg = k0 + cloc;
#pragma unroll
            for (int i = 0; i < 8; i++) {
                int rloc = (i < 4) ? ((ty << 2) + i) : (64 + (ty << 2) + i - 4);
                float x = sv[i][j] * 0.125f;
                bool dead = pad_dead || (diag && cg > q0 + rloc);
                sv[i][j] = dead ? -1e30f : x;
            }
        }

#pragma unroll
        for (int i = 0; i < 8; i++) {
            float rm = fmaxf(fmaxf(sv[i][0], sv[i][1]), fmaxf(sv[i][2], sv[i][3]));
            rm = fmaxf(rm, __shfl_xor_sync(0xffffffffu, rm, 8, 16));
            rm = fmaxf(rm, __shfl_xor_sync(0xffffffffu, rm, 4, 16));
            rm = fmaxf(rm, __shfl_xor_sync(0xffffffffu, rm, 2, 16));
            rm = fmaxf(rm, __shfl_xor_sync(0xffffffffu, rm, 1, 16));
            float mn = fmaxf(mo[i], rm);
            float alpha = __expf(mo[i] - mn);
            float rs = 0.f;
#pragma unroll
            for (int j = 0; j < 4; j++) {
                float p = __expf(sv[i][j] - mn);
                sv[i][j] = p;
                rs += p;
            }
            rs += __shfl_xor_sync(0xffffffffu, rs, 8, 16);
            rs += __shfl_xor_sync(0xffffffffu, rs, 4, 16);
            rs += __shfl_xor_sync(0xffffffffu, rs, 2, 16);
            rs += __shfl_xor_sync(0xffffffffu, rs, 1, 16);
            l[i] = l[i] * alpha + rs;
            mo[i] = mn;
#pragma unroll
            for (int j = 0; j < 4; j++) o[i][j] *= alpha;
            int rloc = (i < 4) ? ((ty << 2) + i) : (64 + (ty << 2) + i - 4);
            *(float4*)&Ps[rloc * 68 + (tx << 2)] =
                make_float4(sv[i][0], sv[i][1], sv[i][2], sv[i][3]);
        }
        __syncthreads();

#pragma unroll 2
        for (int kk = 0; kk < 64; kk += 2) {
            float4 v0 = *(const float4*)&Vs[kk * 68 + (tx << 2)];
            float4 v1 = *(const float4*)&Vs[(kk + 1) * 68 + (tx << 2)];
#pragma unroll
            for (int i = 0; i < 8; i++) {
                int rloc = (i < 4) ? ((ty << 2) + i) : (64 + (ty << 2) + i - 4);
                float2 p = *(const float2*)&Ps[rloc * 68 + kk];
                o[i][0] = fmaf(p.y, v1.x, fmaf(p.x, v0.x, o[i][0]));
                o[i][1] = fmaf(p.y, v1.y, fmaf(p.x, v0.y, o[i][1]));
                o[i][2] = fmaf(p.y, v1.z, fmaf(p.x, v0.z, o[i][2]));
                o[i][3] = fmaf(p.y, v1.w, fmaf(p.x, v0.w, o[i][3]));
            }
        }
    }

#pragma unroll
    for (int i = 0; i < 8; i++) {
        float inv_l = 1.0f / l[i];
        int rloc = (i < 4) ? ((ty << 2) + i) : (64 + (ty << 2) + i - 4);
        int s = q0 + rloc;
        float4 ov = make_float4(o[i][0] * inv_l, o[i][1] * inv_l,
                                o[i][2] * inv_l, o[i][3] * inv_l);
        *(float4*)&ctx[((size_t)(bb * S_LEN + s)) * E_DIM + (hh << 6) + (tx << 2)] = ov;
    }
}

// ---------------------------------------------------------------------------
extern "C" void kernel_launch(void* const* d_in, const int* in_sizes, int n_in,
                              void* d_out, int out_size) {
    const float* x    = (const float*)d_in[0];
    const int*   mask = (const int*)d_in[1];
    const float* Wq   = (const float*)d_in[2];
    const float* bq   = (const float*)d_in[3];
    const float* Wk   = (const float*)d_in[4];
    const float* bk   = (const float*)d_in[5];
    const float* Wv   = (const float*)d_in[6];
    const float* bv   = (const float*)d_in[7];
    const float* Wo   = (const float*)d_in[8];
    const float* bo   = (const float*)d_in[9];
    float* out = (float*)d_out;

    float *pq, *pk, *pv, *pctx;
    __nv_bfloat16 *pxhi, *pxlo, *pchi, *pclo, *pwthi, *pwtlo;
    cudaGetSymbolAddress((void**)&pq, g_q);
    cudaGetSymbolAddress((void**)&pk, g_k);
    cudaGetSymbolAddress((void**)&pv, g_v);
    cudaGetSymbolAddress((void**)&pctx, g_ctx);
    cudaGetSymbolAddress((void**)&pxhi, g_xhi);
    cudaGetSymbolAddress((void**)&pxlo, g_xlo);
    cudaGetSymbolAddress((void**)&pchi, g_chi);
    cudaGetSymbolAddress((void**)&pclo, g_clo);
    cudaGetSymbolAddress((void**)&pwthi, g_wthi);
    cudaGetSymbolAddress((void**)&pwtlo, g_wtlo);
    const size_t WSTRIDE = (size_t)E_DIM * E_DIM;

    rope_table_kernel<<<(S_LEN * 32 + 255) / 256, 256>>>();

    const int n4 = M_ROWS * E_DIM / 4;
    cvt_split_kernel<<<(n4 + 255) / 256, 256>>>(
        (const float4*)x, (__nv_bfloat162*)pxhi, (__nv_bfloat162*)pxlo, n4);

    dim3 tg(32, 32);
    cvt_transpose_kernel<<<tg, 256>>>(Wq, pwthi + 0 * WSTRIDE, pwtlo + 0 * WSTRIDE);
    cvt_transpose_kernel<<<tg, 256>>>(Wk, pwthi + 1 * WSTRIDE, pwtlo + 1 * WSTRIDE);
    cvt_transpose_kernel<<<tg, 256>>>(Wv, pwthi + 2 * WSTRIDE, pwtlo + 2 * WSTRIDE);
    cvt_transpose_kernel<<<tg, 256>>>(Wo, pwthi + 3 * WSTRIDE, pwtlo + 3 * WSTRIDE);

    const int GSMEM = 2 * 4 * TILE_BYTES;  // 81920
    cudaFuncSetAttribute(tgemm_kernel<0>, cudaFuncAttributeMaxDynamicSharedMemorySize, GSMEM);
    cudaFuncSetAttribute(tgemm_kernel<1>, cudaFuncAttributeMaxDynamicSharedMemorySize, GSMEM);
    cudaFuncSetAttribute(tgemm_kernel<2>, cudaFuncAttributeMaxDynamicSharedMemorySize, GSMEM);

    dim3 gg(E_DIM / 128, M_ROWS / 128);
    tgemm_kernel<2><<<gg, 256, GSMEM>>>(pxhi, pxlo, pwthi + 0 * WSTRIDE, pwtlo + 0 * WSTRIDE, bq, pq);
    tgemm_kernel<2><<<gg, 256, GSMEM>>>(pxhi, pxlo, pwthi + 1 * WSTRIDE, pwtlo + 1 * WSTRIDE, bk, pk);
    tgemm_kernel<1><<<gg, 256, GSMEM>>>(pxhi, pxlo, pwthi + 2 * WSTRIDE, pwtlo + 2 * WSTRIDE, bv, pv);

    const int SMEM = (64 * 132 + 64 * 65 + 64 * 68 + 128 * 68) * 4 + 64 * 4;
    cudaFuncSetAttribute(attn_kernel, cudaFuncAttributeMaxDynamicSharedMemorySize, SMEM);
    attn_kernel<<<dim3(S_LEN / 128, BATCH * N_HEADS), 256, SMEM>>>(pq, pk, pv, mask, pctx);

    cvt_split_kernel<<<(n4 + 255) / 256, 256>>>(
        (const float4*)pctx, (__nv_bfloat162*)pchi, (__nv_bfloat162*)pclo, n4);
    tgemm_kernel<0><<<gg, 256, GSMEM>>>(pchi, pclo, pwthi + 3 * WSTRIDE, pwtlo + 3 * WSTRIDE, bo, out);
}

// round 5
// speedup vs baseline: 2.8341x; 1.8026x over previous
#include <cuda_runtime.h>
#include <cuda_bf16.h>
#include <math.h>
#include <stdint.h>

#define S_LEN 2048
#define E_DIM 1024
#define N_HEADS 16
#define HD 64
#define BATCH 2
#define M_ROWS 4096
#define SCALE_Q 0.18033688011112042f   // 0.125 * log2(e)

// ---------------- scratch ---------------------------------------------------
__device__ __align__(256) float g_cos[S_LEN * 32];
__device__ __align__(256) float g_sin[S_LEN * 32];
__device__ __align__(256) __nv_bfloat16 g_xhi[(size_t)M_ROWS * E_DIM];
__device__ __align__(256) __nv_bfloat16 g_xlo[(size_t)M_ROWS * E_DIM];
__device__ __align__(256) __nv_bfloat16 g_chi[(size_t)M_ROWS * E_DIM];
__device__ __align__(256) __nv_bfloat16 g_clo[(size_t)M_ROWS * E_DIM];
__device__ __align__(256) __nv_bfloat16 g_qhi[(size_t)M_ROWS * E_DIM];
__device__ __align__(256) __nv_bfloat16 g_qlo[(size_t)M_ROWS * E_DIM];
__device__ __align__(256) __nv_bfloat16 g_khi[(size_t)M_ROWS * E_DIM];
__device__ __align__(256) __nv_bfloat16 g_klo[(size_t)M_ROWS * E_DIM];
__device__ __align__(256) __nv_bfloat16 g_vhi[(size_t)M_ROWS * E_DIM];
__device__ __align__(256) __nv_bfloat16 g_vlo[(size_t)M_ROWS * E_DIM];
__device__ __align__(256) __nv_bfloat16 g_wthi[4][(size_t)E_DIM * E_DIM];  // [N][K]
__device__ __align__(256) __nv_bfloat16 g_wtlo[4][(size_t)E_DIM * E_DIM];

// ---------------- helpers ---------------------------------------------------
__device__ __forceinline__ uint32_t smem_u32(const void* p) {
    uint32_t a;
    asm("{ .reg .u64 t; cvta.to.shared.u64 t, %1; cvt.u32.u64 %0, t; }"
        : "=r"(a) : "l"(p));
    return a;
}
__device__ __forceinline__ void ldmatrix_x4(uint32_t* r, uint32_t addr) {
    asm volatile("ldmatrix.sync.aligned.m8n8.x4.shared.b16 {%0,%1,%2,%3}, [%4];"
                 : "=r"(r[0]), "=r"(r[1]), "=r"(r[2]), "=r"(r[3]) : "r"(addr));
}
__device__ __forceinline__ void ldmatrix_x4_trans(uint32_t* r, uint32_t addr) {
    asm volatile("ldmatrix.sync.aligned.m8n8.x4.trans.shared.b16 {%0,%1,%2,%3}, [%4];"
                 : "=r"(r[0]), "=r"(r[1]), "=r"(r[2]), "=r"(r[3]) : "r"(addr));
}
__device__ __forceinline__ void mma16816(float* c, const uint32_t* a, const uint32_t* b) {
    asm volatile(
        "mma.sync.aligned.m16n8k16.row.col.f32.bf16.bf16.f32 "
        "{%0,%1,%2,%3}, {%4,%5,%6,%7}, {%8,%9}, {%0,%1,%2,%3};"
        : "+f"(c[0]), "+f"(c[1]), "+f"(c[2]), "+f"(c[3])
        : "r"(a[0]), "r"(a[1]), "r"(a[2]), "r"(a[3]), "r"(b[0]), "r"(b[1]));
}
__device__ __forceinline__ void cp_async16(uint32_t dst, const void* src) {
    asm volatile("cp.async.cg.shared.global [%0], [%1], 16;" :: "r"(dst), "l"(src));
}
__device__ __forceinline__ float ex2(float x) {
    float y;
    asm("ex2.approx.f32 %0, %1;" : "=f"(y) : "f"(x));
    return y;
}
__device__ __forceinline__ void split2(float x, float y, uint32_t& h, uint32_t& l) {
    __nv_bfloat162 hb = __floats2bfloat162_rn(x, y);
    float2 hf = __bfloat1622float2(hb);
    __nv_bfloat162 lb = __floats2bfloat162_rn(x - hf.x, y - hf.y);
    h = *(uint32_t*)&hb;
    l = *(uint32_t*)&lb;
}

// ---------------------------------------------------------------------------
__global__ void rope_table_kernel() {
    int i = blockIdx.x * blockDim.x + threadIdx.x;
    if (i >= S_LEN * 32) return;
    int s = i >> 5, j = i & 31;
    float inv = (float)pow(10000.0, -(double)j / 32.0);
    float th = (float)s * inv;
    g_cos[i] = cosf(th);
    g_sin[i] = sinf(th);
}

__global__ void cvt_split_kernel(const float4* __restrict__ src,
                                 __nv_bfloat162* __restrict__ hi,
                                 __nv_bfloat162* __restrict__ lo, int n4) {
    int i = blockIdx.x * blockDim.x + threadIdx.x;
    if (i >= n4) return;
    float4 v = src[i];
    __nv_bfloat162 h01 = __floats2bfloat162_rn(v.x, v.y);
    __nv_bfloat162 h23 = __floats2bfloat162_rn(v.z, v.w);
    float2 f01 = __bfloat1622float2(h01);
    float2 f23 = __bfloat1622float2(h23);
    hi[2 * i] = h01;
    hi[2 * i + 1] = h23;
    lo[2 * i] = __floats2bfloat162_rn(v.x - f01.x, v.y - f01.y);
    lo[2 * i + 1] = __floats2bfloat162_rn(v.z - f23.x, v.w - f23.y);
}

__global__ void cvt_transpose_kernel(const float* __restrict__ W,
                                     __nv_bfloat16* __restrict__ Thi,
                                     __nv_bfloat16* __restrict__ Tlo) {
    __shared__ float t[32][33];
    int bx = blockIdx.x, by = blockIdx.y;
    int tid = threadIdx.x;
#pragma unroll
    for (int it = 0; it < 4; it++) {
        int idx = tid + it * 256;
        int r = idx >> 5, c = idx & 31;
        t[r][c] = W[(size_t)(by * 32 + r) * E_DIM + bx * 32 + c];
    }
    __syncthreads();
#pragma unroll
    for (int it = 0; it < 4; it++) {
        int idx = tid + it * 256;
        int r = idx >> 5, c = idx & 31;
        float x = t[c][r];
        __nv_bfloat16 h = __float2bfloat16(x);
        size_t o = (size_t)(bx * 32 + r) * E_DIM + by * 32 + c;
        Thi[o] = h;
        Tlo[o] = __float2bfloat16(x - __bfloat162float(h));
    }
}

// ---------------------------------------------------------------------------
// Split-bf16 mma.sync GEMM.  128x128 tile, BK=32, 8 warps (4x2), 32x64/warp.
// MODE 0: f32 row-major out.
// MODE 1: bf16 hi/lo scatter [B,H,S,D] (V).
// MODE 2: bf16 hi/lo scatter + RoPE + SCALE_Q (Q).
// MODE 3: bf16 hi/lo scatter + RoPE (K).
// ---------------------------------------------------------------------------
#define TSTRIDE 40
#define TILE_BYTES (128 * TSTRIDE * 2)
#define NCHUNK 32

__device__ __forceinline__ void load_chunk_async(
    const __nv_bfloat16* __restrict__ Ahi, const __nv_bfloat16* __restrict__ Alo,
    const __nv_bfloat16* __restrict__ Bhi, const __nv_bfloat16* __restrict__ Blo,
    int m0, int n0, int k0, uint32_t st, int tid) {
    const __nv_bfloat16* srcs[4] = {Ahi, Alo, Bhi, Blo};
    int r0s[4] = {m0, m0, n0, n0};
#pragma unroll
    for (int tno = 0; tno < 4; tno++) {
        uint32_t sdst = st + tno * TILE_BYTES;
        const __nv_bfloat16* src = srcs[tno];
        int row0 = r0s[tno];
#pragma unroll
        for (int it = 0; it < 2; it++) {
            int idx = tid + it * 256;
            int r = idx >> 2, seg = idx & 3;
            cp_async16(sdst + (uint32_t)(r * TSTRIDE + seg * 8) * 2,
                       src + (size_t)(row0 + r) * E_DIM + k0 + seg * 8);
        }
    }
}

template <int MODE>
__global__ __launch_bounds__(256)
void tgemm_kernel(const __nv_bfloat16* __restrict__ Ahi,
                  const __nv_bfloat16* __restrict__ Alo,
                  const __nv_bfloat16* __restrict__ Bthi,
                  const __nv_bfloat16* __restrict__ Btlo,
                  const float* __restrict__ bias, float* __restrict__ C,
                  __nv_bfloat16* __restrict__ Chi, __nv_bfloat16* __restrict__ Clo) {
    extern __shared__ __align__(1024) char dsm[];
    const uint32_t sbase = smem_u32(dsm);
    const int tid = threadIdx.x;
    const int wid = tid >> 5, lane = tid & 31;
    const int wm = wid & 3, wn = wid >> 2;
    const int g = lane >> 2, tg = lane & 3;
    const int m0 = blockIdx.y << 7, n0 = blockIdx.x << 7;

    float acc[2][8][4] = {};

    load_chunk_async(Ahi, Alo, Bthi, Btlo, m0, n0, 0, sbase, tid);
    asm volatile("cp.async.commit_group;");

    for (int c = 0; c < NCHUNK; c++) {
        if (c + 1 < NCHUNK) {
            load_chunk_async(Ahi, Alo, Bthi, Btlo, m0, n0, (c + 1) << 5,
                             sbase + ((c + 1) & 1) * 4 * TILE_BYTES, tid);
            asm volatile("cp.async.commit_group;");
            asm volatile("cp.async.wait_group 1;");
        } else {
            asm volatile("cp.async.wait_group 0;");
        }
        __syncthreads();

        const uint32_t st = sbase + (c & 1) * 4 * TILE_BYTES;
        const uint32_t Ahi_s = st, Alo_s = st + TILE_BYTES;
        const uint32_t Bhi_s = st + 2 * TILE_BYTES, Blo_s = st + 3 * TILE_BYTES;

#pragma unroll
        for (int ks = 0; ks < 2; ks++) {
            uint32_t ah[2][4], al[2][4];
#pragma unroll
            for (int mt = 0; mt < 2; mt++) {
                int row = wm * 32 + mt * 16 + (lane & 15);
                int kb = ks * 16 + ((lane >> 4) << 3);
                uint32_t off = (uint32_t)(row * TSTRIDE + kb) * 2;
                ldmatrix_x4(ah[mt], Ahi_s + off);
                ldmatrix_x4(al[mt], Alo_s + off);
            }
#pragma unroll
            for (int np = 0; np < 4; np++) {
                uint32_t bh[4], bl[4];
                int row = wn * 64 + np * 16 + ((lane >> 4) << 3) + (lane & 7);
                int kb = ks * 16 + (((lane >> 3) & 1) << 3);
                uint32_t off = (uint32_t)(row * TSTRIDE + kb) * 2;
                ldmatrix_x4(bh, Bhi_s + off);
                ldmatrix_x4(bl, Blo_s + off);
#pragma unroll
                for (int half = 0; half < 2; half++) {
                    int nt = 2 * np + half;
#pragma unroll
                    for (int mt = 0; mt < 2; mt++) {
                        mma16816(acc[mt][nt], ah[mt], bh + 2 * half);
                        mma16816(acc[mt][nt], ah[mt], bl + 2 * half);
                        mma16816(acc[mt][nt], al[mt], bh + 2 * half);
                    }
                }
            }
        }
        __syncthreads();
    }

#pragma unroll
    for (int mt = 0; mt < 2; mt++) {
#pragma unroll
        for (int h2 = 0; h2 < 2; h2++) {
            int m = m0 + wm * 32 + mt * 16 + g + h2 * 8;
            int bb = m >> 11, s = m & (S_LEN - 1);
            if (MODE == 0) {
                float* dst = &C[(size_t)m * E_DIM + n0 + wn * 64];
#pragma unroll
                for (int nt = 0; nt < 8; nt++) {
                    int col = nt * 8 + tg * 2;
                    float2 bv = *(const float2*)&bias[n0 + wn * 64 + col];
                    *(float2*)&dst[col] = make_float2(acc[mt][nt][h2 * 2 + 0] + bv.x,
                                                      acc[mt][nt][h2 * 2 + 1] + bv.y);
                }
            } else {
                int h = (n0 + wn * 64) >> 6;
                size_t rb = (((size_t)(bb * N_HEADS + h)) * S_LEN + s) << 6;
                float vals[8][2];
#pragma unroll
                for (int nt = 0; nt < 8; nt++) {
                    int col = nt * 8 + tg * 2;
                    float2 bv = *(const float2*)&bias[n0 + wn * 64 + col];
                    vals[nt][0] = acc[mt][nt][h2 * 2 + 0] + bv.x;
                    vals[nt][1] = acc[mt][nt][h2 * 2 + 1] + bv.y;
                }
                if (MODE == 2 || MODE == 3) {
#pragma unroll
                    for (int nt = 0; nt < 4; nt++) {
#pragma unroll
                        for (int jj = 0; jj < 2; jj++) {
                            int d = nt * 8 + tg * 2 + jj;
                            float cth = g_cos[(s << 5) + d];
                            float sth = g_sin[(s << 5) + d];
                            float lo = vals[nt][jj], hi = vals[nt + 4][jj];
                            vals[nt][jj]     = fmaf(lo, cth, -hi * sth);
                            vals[nt + 4][jj] = fmaf(hi, cth,  lo * sth);
                        }
                    }
                }
                if (MODE == 2) {
#pragma unroll
                    for (int nt = 0; nt < 8; nt++) {
                        vals[nt][0] *= SCALE_Q;
                        vals[nt][1] *= SCALE_Q;
                    }
                }
#pragma unroll
                for (int nt = 0; nt < 8; nt++) {
                    uint32_t hv, lv;
                    split2(vals[nt][0], vals[nt][1], hv, lv);
                    *(uint32_t*)(Chi + rb + nt * 8 + tg * 2) = hv;
                    *(uint32_t*)(Clo + rb + nt * 8 + tg * 2) = lv;
                }
            }
        }
    }
}

// ---------------------------------------------------------------------------
// Tensorized flash attention. Q-tile 128, KV-tile 64, 8 warps.
// Warp w owns logical rows {w*8..w*8+7} u {64+w*8..64+w*8+7}.
// ---------------------------------------------------------------------------
#define ATT_Q   0
#define ATT_QL  18432
#define ATT_BUF0 36864
#define ATT_BUFSZ 37120
#define ATT_SMEM (36864 + 2 * 37120)   // 111104

__device__ __forceinline__ void attn_issue_kv(
    const __nv_bfloat16* khi, const __nv_bfloat16* klo,
    const __nv_bfloat16* vhi, const __nv_bfloat16* vlo,
    const int* mask, int mask_off, uint32_t sb, int t, int tid) {
    uint32_t bufb = sb + ATT_BUF0 + (t & 1) * ATT_BUFSZ;
    int k0 = t << 6;
    const __nv_bfloat16* srcs[4] = {khi, klo, vhi, vlo};
#pragma unroll
    for (int i = 0; i < 8; i++) {
        int idx = tid + i * 256;          // 0..2047
        int arr = idx >> 9;
        int r = (idx >> 3) & 63, seg = idx & 7;
        cp_async16(bufb + arr * 9216 + (uint32_t)(r * 144 + seg * 16),
                   srcs[arr] + (size_t)(k0 + r) * HD + seg * 8);
    }
    if (tid < 16)
        cp_async16(bufb + 36864 + tid * 16, mask + mask_off + k0 + tid * 4);
}

__global__ __launch_bounds__(256)
void attn_kernel(const __nv_bfloat16* __restrict__ qhi, const __nv_bfloat16* __restrict__ qlo,
                 const __nv_bfloat16* __restrict__ khi, const __nv_bfloat16* __restrict__ klo,
                 const __nv_bfloat16* __restrict__ vhi, const __nv_bfloat16* __restrict__ vlo,
                 const int* __restrict__ mask,
                 __nv_bfloat16* __restrict__ chi, __nv_bfloat16* __restrict__ clo) {
    extern __shared__ __align__(1024) char sm_[];
    const uint32_t sb = smem_u32(sm_);
    const int tid = threadIdx.x, w = tid >> 5, lane = tid & 31;
    const int g = lane >> 2, tg = lane & 3;
    const int qt = gridDim.x - 1 - blockIdx.x;
    const int bh = blockIdx.y, bb = bh >> 4, hh = bh & 15;
    const int q0 = qt << 7;
    const size_t base = (size_t)bh * S_LEN * HD;

    // load Q hi/lo into smem rows [0..127][72]
    {
        const __nv_bfloat16* s0 = qhi + base + (size_t)q0 * HD;
        const __nv_bfloat16* s1 = qlo + base + (size_t)q0 * HD;
#pragma unroll
        for (int i = 0; i < 8; i++) {
            int idx = tid + i * 256;       // 0..2047
            int arr = idx >> 10;
            int r = (idx >> 3) & 127, seg = idx & 7;
            uint4 v = *(const uint4*)((arr ? s1 : s0) + (size_t)r * HD + seg * 8);
            *(uint4*)(sm_ + (arr ? ATT_QL : ATT_Q) + r * 144 + seg * 16) = v;
        }
    }

    const int ntile = 2 * (qt + 1);
    attn_issue_kv(khi + base, klo + base, vhi + base, vlo + base,
                  mask, bb * S_LEN, sb, 0, tid);
    asm volatile("cp.async.commit_group;");
    __syncthreads();   // Q visible for ldmatrix

    // hoisted Q fragments
    uint32_t qfh[4][4], qfl[4][4];
    {
        int i = lane & 15;
        int prow = (i < 8) ? (w * 8 + i) : (64 + w * 8 + (i - 8));
        int kb = ((lane >> 4) << 3);
#pragma unroll
        for (int ks = 0; ks < 4; ks++) {
            uint32_t off = (uint32_t)(prow * 144 + (ks * 16 + kb) * 2);
            ldmatrix_x4(qfh[ks], sb + ATT_Q + off);
            ldmatrix_x4(qfl[ks], sb + ATT_QL + off);
        }
    }
    const int row0 = q0 + w * 8 + g;
    const int row1 = q0 + 64 + w * 8 + g;

    float oacc[8][4] = {};
    float l0 = 0.f, l1 = 0.f, mo0 = -1e30f, mo1 = -1e30f;

    for (int t = 0; t < ntile; t++) {
        if (t + 1 < ntile) {
            attn_issue_kv(khi + base, klo + base, vhi + base, vlo + base,
                          mask, bb * S_LEN, sb, t + 1, tid);
            asm volatile("cp.async.commit_group;");
            asm volatile("cp.async.wait_group 1;");
        } else {
            asm volatile("cp.async.wait_group 0;");
        }
        __syncthreads();
        const uint32_t bufb = sb + ATT_BUF0 + (t & 1) * ATT_BUFSZ;
        const int k0 = t << 6;

        // S = Q @ K^T  (scores pre-scaled by 0.125*log2e via Q)
        float sc[8][4] = {};
#pragma unroll
        for (int ks = 0; ks < 4; ks++) {
#pragma unroll
            for (int ntp = 0; ntp < 4; ntp++) {
                uint32_t kh[4], kl[4];
                int row = ntp * 16 + ((lane >> 4) << 3) + (lane & 7);
                int kb = ks * 16 + (((lane >> 3) & 1) << 3);
                uint32_t off = (uint32_t)(row * 144 + kb * 2);
                ldmatrix_x4(kh, bufb + off);
                ldmatrix_x4(kl, bufb + 9216 + off);
#pragma unroll
                for (int hf = 0; hf < 2; hf++) {
                    int nt = 2 * ntp + hf;
                    mma16816(sc[nt], qfh[ks], kh + 2 * hf);
                    mma16816(sc[nt], qfh[ks], kl + 2 * hf);
                    mma16816(sc[nt], qfl[ks], kh + 2 * hf);
                }
            }
        }

        // padding mask via ballot
        const int* Ms = (const int*)(sm_ + ATT_BUF0 + (t & 1) * ATT_BUFSZ + 36864);
        uint32_t pb0 = __ballot_sync(0xffffffffu, Ms[lane] != 0);
        uint32_t pb1 = __ballot_sync(0xffffffffu, Ms[lane + 32] != 0);
        if ((pb0 & pb1) != 0xffffffffu) {
#pragma unroll
            for (int nt = 0; nt < 8; nt++)
#pragma unroll
                for (int j = 0; j < 2; j++) {
                    int cl = nt * 8 + tg * 2 + j;
                    uint32_t bit = (cl < 32) ? (pb0 >> cl) : (pb1 >> (cl - 32));
                    if (!(bit & 1)) { sc[nt][j] = -1e30f; sc[nt][2 + j] = -1e30f; }
                }
        }
        // causal mask
        if (k0 + 63 > row0) {
#pragma unroll
            for (int nt = 0; nt < 8; nt++)
#pragma unroll
                for (int j = 0; j < 2; j++) {
                    int cg = k0 + nt * 8 + tg * 2 + j;
                    if (cg > row0) sc[nt][j] = -1e30f;
                    if (cg > row1) sc[nt][2 + j] = -1e30f;
                }
        }

        // online softmax (base-2 domain)
        float mx0 = -1e30f, mx1 = -1e30f;
#pragma unroll
        for (int nt = 0; nt < 8; nt++) {
            mx0 = fmaxf(mx0, fmaxf(sc[nt][0], sc[nt][1]));
            mx1 = fmaxf(mx1, fmaxf(sc[nt][2], sc[nt][3]));
        }
        mx0 = fmaxf(mx0, __shfl_xor_sync(0xffffffffu, mx0, 1));
        mx0 = fmaxf(mx0, __shfl_xor_sync(0xffffffffu, mx0, 2));
        mx1 = fmaxf(mx1, __shfl_xor_sync(0xffffffffu, mx1, 1));
        mx1 = fmaxf(mx1, __shfl_xor_sync(0xffffffffu, mx1, 2));
        float mn0 = fmaxf(mo0, mx0), mn1 = fmaxf(mo1, mx1);
        float al0 = ex2(mo0 - mn0), al1 = ex2(mo1 - mn1);
        float rs0 = 0.f, rs1 = 0.f;
#pragma unroll
        for (int nt = 0; nt < 8; nt++) {
            sc[nt][0] = ex2(sc[nt][0] - mn0);
            sc[nt][1] = ex2(sc[nt][1] - mn0);
            sc[nt][2] = ex2(sc[nt][2] - mn1);
            sc[nt][3] = ex2(sc[nt][3] - mn1);
            rs0 += sc[nt][0] + sc[nt][1];
            rs1 += sc[nt][2] + sc[nt][3];
        }
        rs0 += __shfl_xor_sync(0xffffffffu, rs0, 1);
        rs0 += __shfl_xor_sync(0xffffffffu, rs0, 2);
        rs1 += __shfl_xor_sync(0xffffffffu, rs1, 1);
        rs1 += __shfl_xor_sync(0xffffffffu, rs1, 2);
        l0 = l0 * al0 + rs0;
        l1 = l1 * al1 + rs1;
        mo0 = mn0; mo1 = mn1;
#pragma unroll
        for (int nt = 0; nt < 8; nt++) {
            oacc[nt][0] *= al0; oacc[nt][1] *= al0;
            oacc[nt][2] *= al1; oacc[nt][3] *= al1;
        }

        // O += P @ V   (P repacked from registers, split hi/lo)
#pragma unroll
        for (int ks = 0; ks < 4; ks++) {
            uint32_t pa[4], pl[4];
            split2(sc[2 * ks][0], sc[2 * ks][1], pa[0], pl[0]);
            split2(sc[2 * ks][2], sc[2 * ks][3], pa[1], pl[1]);
            split2(sc[2 * ks + 1][0], sc[2 * ks + 1][1], pa[2], pl[2]);
            split2(sc[2 * ks + 1][2], sc[2 * ks + 1][3], pa[3], pl[3]);
#pragma unroll
            for (int dtp = 0; dtp < 4; dtp++) {
                uint32_t vh[4], vl[4];
                int rkv = ks * 16 + ((lane >> 3) & 1) * 8 + (lane & 7);
                int cd = dtp * 16 + (lane >> 4) * 8;
                uint32_t off = (uint32_t)(rkv * 144 + cd * 2);
                ldmatrix_x4_trans(vh, bufb + 18432 + off);
                ldmatrix_x4_trans(vl, bufb + 27648 + off);
#pragma unroll
                for (int hf = 0; hf < 2; hf++) {
                    int nt = 2 * dtp + hf;
                    mma16816(oacc[nt], pa, vh + 2 * hf);
                    mma16816(oacc[nt], pa, vl + 2 * hf);
                    mma16816(oacc[nt], pl, vh + 2 * hf);
                }
            }
        }
        __syncthreads();
    }

    // epilogue: write ctx hi/lo bf16 [B,S,H*D]
    float inv0 = 1.0f / l0, inv1 = 1.0f / l1;
    __nv_bfloat16* dh0 = chi + ((size_t)(bb * S_LEN + row0)) * E_DIM + hh * 64;
    __nv_bfloat16* dl0 = clo + ((size_t)(bb * S_LEN + row0)) * E_DIM + hh * 64;
    __nv_bfloat16* dh1 = chi + ((size_t)(bb * S_LEN + row1)) * E_DIM + hh * 64;
    __nv_bfloat16* dl1 = clo + ((size_t)(bb * S_LEN + row1)) * E_DIM + hh * 64;
#pragma unroll
    for (int nt = 0; nt < 8; nt++) {
        int d = nt * 8 + tg * 2;
        uint32_t hv, lv;
        split2(oacc[nt][0] * inv0, oacc[nt][1] * inv0, hv, lv);
        *(uint32_t*)(dh0 + d) = hv;
        *(uint32_t*)(dl0 + d) = lv;
        split2(oacc[nt][2] * inv1, oacc[nt][3] * inv1, hv, lv);
        *(uint32_t*)(dh1 + d) = hv;
        *(uint32_t*)(dl1 + d) = lv;
    }
}

// ---------------------------------------------------------------------------
extern "C" void kernel_launch(void* const* d_in, const int* in_sizes, int n_in,
                              void* d_out, int out_size) {
    const float* x    = (const float*)d_in[0];
    const int*   mask = (const int*)d_in[1];
    const float* Wq   = (const float*)d_in[2];
    const float* bq   = (const float*)d_in[3];
    const float* Wk   = (const float*)d_in[4];
    const float* bk   = (const float*)d_in[5];
    const float* Wv   = (const float*)d_in[6];
    const float* bv   = (const float*)d_in[7];
    const float* Wo   = (const float*)d_in[8];
    const float* bo   = (const float*)d_in[9];
    float* out = (float*)d_out;

    __nv_bfloat16 *pxhi, *pxlo, *pchi, *pclo, *pwthi, *pwtlo;
    __nv_bfloat16 *pqhi, *pqlo, *pkhi, *pklo, *pvhi, *pvlo;
    cudaGetSymbolAddress((void**)&pxhi, g_xhi);
    cudaGetSymbolAddress((void**)&pxlo, g_xlo);
    cudaGetSymbolAddress((void**)&pchi, g_chi);
    cudaGetSymbolAddress((void**)&pclo, g_clo);
    cudaGetSymbolAddress((void**)&pqhi, g_qhi);
    cudaGetSymbolAddress((void**)&pqlo, g_qlo);
    cudaGetSymbolAddress((void**)&pkhi, g_khi);
    cudaGetSymbolAddress((void**)&pklo, g_klo);
    cudaGetSymbolAddress((void**)&pvhi, g_vhi);
    cudaGetSymbolAddress((void**)&pvlo, g_vlo);
    cudaGetSymbolAddress((void**)&pwthi, g_wthi);
    cudaGetSymbolAddress((void**)&pwtlo, g_wtlo);
    const size_t WSTRIDE = (size_t)E_DIM * E_DIM;

    rope_table_kernel<<<(S_LEN * 32 + 255) / 256, 256>>>();

    const int n4 = M_ROWS * E_DIM / 4;
    cvt_split_kernel<<<(n4 + 255) / 256, 256>>>(
        (const float4*)x, (__nv_bfloat162*)pxhi, (__nv_bfloat162*)pxlo, n4);

    dim3 tg(32, 32);
    cvt_transpose_kernel<<<tg, 256>>>(Wq, pwthi + 0 * WSTRIDE, pwtlo + 0 * WSTRIDE);
    cvt_transpose_kernel<<<tg, 256>>>(Wk, pwthi + 1 * WSTRIDE, pwtlo + 1 * WSTRIDE);
    cvt_transpose_kernel<<<tg, 256>>>(Wv, pwthi + 2 * WSTRIDE, pwtlo + 2 * WSTRIDE);
    cvt_transpose_kernel<<<tg, 256>>>(Wo, pwthi + 3 * WSTRIDE, pwtlo + 3 * WSTRIDE);

    const int GSMEM = 2 * 4 * TILE_BYTES;
    cudaFuncSetAttribute(tgemm_kernel<0>, cudaFuncAttributeMaxDynamicSharedMemorySize, GSMEM);
    cudaFuncSetAttribute(tgemm_kernel<1>, cudaFuncAttributeMaxDynamicSharedMemorySize, GSMEM);
    cudaFuncSetAttribute(tgemm_kernel<2>, cudaFuncAttributeMaxDynamicSharedMemorySize, GSMEM);
    cudaFuncSetAttribute(tgemm_kernel<3>, cudaFuncAttributeMaxDynamicSharedMemorySize, GSMEM);

    dim3 gg(E_DIM / 128, M_ROWS / 128);
    tgemm_kernel<2><<<gg, 256, GSMEM>>>(pxhi, pxlo, pwthi + 0 * WSTRIDE, pwtlo + 0 * WSTRIDE,
                                        bq, nullptr, pqhi, pqlo);
    tgemm_kernel<3><<<gg, 256, GSMEM>>>(pxhi, pxlo, pwthi + 1 * WSTRIDE, pwtlo + 1 * WSTRIDE,
                                        bk, nullptr, pkhi, pklo);
    tgemm_kernel<1><<<gg, 256, GSMEM>>>(pxhi, pxlo, pwthi + 2 * WSTRIDE, pwtlo + 2 * WSTRIDE,
                                        bv, nullptr, pvhi, pvlo);

    cudaFuncSetAttribute(attn_kernel, cudaFuncAttributeMaxDynamicSharedMemorySize, ATT_SMEM);
    attn_kernel<<<dim3(S_LEN / 128, BATCH * N_HEADS), 256, ATT_SMEM>>>(
        pqhi, pqlo, pkhi, pklo, pvhi, pvlo, mask, pchi, pclo);

    tgemm_kernel<0><<<gg, 256, GSMEM>>>(pchi, pclo, pwthi + 3 * WSTRIDE, pwtlo + 3 * WSTRIDE,
                                        bo, out, nullptr, nullptr);
}

// round 6
// speedup vs baseline: 2.8685x; 1.0121x over previous
#include <cuda_runtime.h>
#include <cuda_bf16.h>
#include <math.h>
#include <stdint.h>

#define S_LEN 2048
#define E_DIM 1024
#define N_HEADS 16
#define HD 64
#define BATCH 2
#define M_ROWS 4096
#define SCALE_Q 0.18033688011112042f   // 0.125 * log2(e)

// ---------------- scratch ---------------------------------------------------
__device__ __align__(256) float g_cos[S_LEN * 32];
__device__ __align__(256) float g_sin[S_LEN * 32];
__device__ __align__(256) __nv_bfloat16 g_xhi[(size_t)M_ROWS * E_DIM];
__device__ __align__(256) __nv_bfloat16 g_xlo[(size_t)M_ROWS * E_DIM];
__device__ __align__(256) __nv_bfloat16 g_chi[(size_t)M_ROWS * E_DIM];
__device__ __align__(256) __nv_bfloat16 g_clo[(size_t)M_ROWS * E_DIM];
__device__ __align__(256) __nv_bfloat16 g_qhi[(size_t)M_ROWS * E_DIM];
__device__ __align__(256) __nv_bfloat16 g_qlo[(size_t)M_ROWS * E_DIM];
__device__ __align__(256) __nv_bfloat16 g_khi[(size_t)M_ROWS * E_DIM];
__device__ __align__(256) __nv_bfloat16 g_klo[(size_t)M_ROWS * E_DIM];
__device__ __align__(256) __nv_bfloat16 g_vhi[(size_t)M_ROWS * E_DIM];
__device__ __align__(256) __nv_bfloat16 g_vlo[(size_t)M_ROWS * E_DIM];
__device__ __align__(256) __nv_bfloat16 g_wthi[4][(size_t)E_DIM * E_DIM];  // [N][K]
__device__ __align__(256) __nv_bfloat16 g_wtlo[4][(size_t)E_DIM * E_DIM];

// ---------------- helpers ---------------------------------------------------
__device__ __forceinline__ uint32_t smem_u32(const void* p) {
    uint32_t a;
    asm("{ .reg .u64 t; cvta.to.shared.u64 t, %1; cvt.u32.u64 %0, t; }"
        : "=r"(a) : "l"(p));
    return a;
}
__device__ __forceinline__ void ldmatrix_x4(uint32_t* r, uint32_t addr) {
    asm volatile("ldmatrix.sync.aligned.m8n8.x4.shared.b16 {%0,%1,%2,%3}, [%4];"
                 : "=r"(r[0]), "=r"(r[1]), "=r"(r[2]), "=r"(r[3]) : "r"(addr));
}
__device__ __forceinline__ void ldmatrix_x4_trans(uint32_t* r, uint32_t addr) {
    asm volatile("ldmatrix.sync.aligned.m8n8.x4.trans.shared.b16 {%0,%1,%2,%3}, [%4];"
                 : "=r"(r[0]), "=r"(r[1]), "=r"(r[2]), "=r"(r[3]) : "r"(addr));
}
__device__ __forceinline__ void mma16816(float* c, const uint32_t* a, const uint32_t* b) {
    asm volatile(
        "mma.sync.aligned.m16n8k16.row.col.f32.bf16.bf16.f32 "
        "{%0,%1,%2,%3}, {%4,%5,%6,%7}, {%8,%9}, {%0,%1,%2,%3};"
        : "+f"(c[0]), "+f"(c[1]), "+f"(c[2]), "+f"(c[3])
        : "r"(a[0]), "r"(a[1]), "r"(a[2]), "r"(a[3]), "r"(b[0]), "r"(b[1]));
}
__device__ __forceinline__ void cp_async16(uint32_t dst, const void* src) {
    asm volatile("cp.async.cg.shared.global [%0], [%1], 16;" :: "r"(dst), "l"(src));
}
__device__ __forceinline__ float ex2(float x) {
    float y;
    asm("ex2.approx.f32 %0, %1;" : "=f"(y) : "f"(x));
    return y;
}
__device__ __forceinline__ void split2(float x, float y, uint32_t& h, uint32_t& l) {
    __nv_bfloat162 hb = __floats2bfloat162_rn(x, y);
    float2 hf = __bfloat1622float2(hb);
    __nv_bfloat162 lb = __floats2bfloat162_rn(x - hf.x, y - hf.y);
    h = *(uint32_t*)&hb;
    l = *(uint32_t*)&lb;
}

// ---------------------------------------------------------------------------
__global__ void rope_table_kernel() {
    int i = blockIdx.x * blockDim.x + threadIdx.x;
    if (i >= S_LEN * 32) return;
    int s = i >> 5, j = i & 31;
    float inv = (float)pow(10000.0, -(double)j / 32.0);
    float th = (float)s * inv;
    g_cos[i] = cosf(th);
    g_sin[i] = sinf(th);
}

__global__ void cvt_split_kernel(const float4* __restrict__ src,
                                 __nv_bfloat162* __restrict__ hi,
                                 __nv_bfloat162* __restrict__ lo, int n4) {
    int i = blockIdx.x * blockDim.x + threadIdx.x;
    if (i >= n4) return;
    float4 v = src[i];
    __nv_bfloat162 h01 = __floats2bfloat162_rn(v.x, v.y);
    __nv_bfloat162 h23 = __floats2bfloat162_rn(v.z, v.w);
    float2 f01 = __bfloat1622float2(h01);
    float2 f23 = __bfloat1622float2(h23);
    hi[2 * i] = h01;
    hi[2 * i + 1] = h23;
    lo[2 * i] = __floats2bfloat162_rn(v.x - f01.x, v.y - f01.y);
    lo[2 * i + 1] = __floats2bfloat162_rn(v.z - f23.x, v.w - f23.y);
}

// fused 4-way transpose-convert: W[K][N] f32 -> Thi/Tlo [N][K] bf16 (z picks W)
__global__ void cvt_transpose4_kernel(const float* __restrict__ W0,
                                      const float* __restrict__ W1,
                                      const float* __restrict__ W2,
                                      const float* __restrict__ W3,
                                      __nv_bfloat16* __restrict__ Thi,
                                      __nv_bfloat16* __restrict__ Tlo) {
    __shared__ float t[32][33];
    const float* Ws[4] = {W0, W1, W2, W3};
    const float* W = Ws[blockIdx.z];
    __nv_bfloat16* thiz = Thi + (size_t)blockIdx.z * E_DIM * E_DIM;
    __nv_bfloat16* tloz = Tlo + (size_t)blockIdx.z * E_DIM * E_DIM;
    int bx = blockIdx.x, by = blockIdx.y;
    int tid = threadIdx.x;
#pragma unroll
    for (int it = 0; it < 4; it++) {
        int idx = tid + it * 256;
        int r = idx >> 5, c = idx & 31;
        t[r][c] = W[(size_t)(by * 32 + r) * E_DIM + bx * 32 + c];
    }
    __syncthreads();
#pragma unroll
    for (int it = 0; it < 4; it++) {
        int idx = tid + it * 256;
        int r = idx >> 5, c = idx & 31;
        float x = t[c][r];
        __nv_bfloat16 h = __float2bfloat16(x);
        size_t o = (size_t)(bx * 32 + r) * E_DIM + by * 32 + c;
        thiz[o] = h;
        tloz[o] = __float2bfloat16(x - __bfloat162float(h));
    }
}

// ---------------------------------------------------------------------------
// Split-bf16 mma.sync GEMM.  128x128 tile, BK=32, 8 warps (4x2), 32x64/warp.
// MODE 0: f32 row-major out.  MODE 1: bf16 hi/lo scatter [B,H,S,D] (V).
// MODE 2: + RoPE + SCALE_Q (Q).  MODE 3: + RoPE (K).
// ---------------------------------------------------------------------------
#define TSTRIDE 40
#define TILE_BYTES (128 * TSTRIDE * 2)
#define NCHUNK 32

__device__ __forceinline__ void load_chunk_async(
    const __nv_bfloat16* __restrict__ Ahi, const __nv_bfloat16* __restrict__ Alo,
    const __nv_bfloat16* __restrict__ Bhi, const __nv_bfloat16* __restrict__ Blo,
    int m0, int n0, int k0, uint32_t st, int tid) {
    const __nv_bfloat16* srcs[4] = {Ahi, Alo, Bhi, Blo};
    int r0s[4] = {m0, m0, n0, n0};
#pragma unroll
    for (int tno = 0; tno < 4; tno++) {
        uint32_t sdst = st + tno * TILE_BYTES;
        const __nv_bfloat16* src = srcs[tno];
        int row0 = r0s[tno];
#pragma unroll
        for (int it = 0; it < 2; it++) {
            int idx = tid + it * 256;
            int r = idx >> 2, seg = idx & 3;
            cp_async16(sdst + (uint32_t)(r * TSTRIDE + seg * 8) * 2,
                       src + (size_t)(row0 + r) * E_DIM + k0 + seg * 8);
        }
    }
}

template <int MODE>
__global__ __launch_bounds__(256)
void tgemm_kernel(const __nv_bfloat16* __restrict__ Ahi,
                  const __nv_bfloat16* __restrict__ Alo,
                  const __nv_bfloat16* __restrict__ Bthi,
                  const __nv_bfloat16* __restrict__ Btlo,
                  const float* __restrict__ bias, float* __restrict__ C,
                  __nv_bfloat16* __restrict__ Chi, __nv_bfloat16* __restrict__ Clo) {
    extern __shared__ __align__(1024) char dsm[];
    const uint32_t sbase = smem_u32(dsm);
    const int tid = threadIdx.x;
    const int wid = tid >> 5, lane = tid & 31;
    const int wm = wid & 3, wn = wid >> 2;
    const int g = lane >> 2, tg = lane & 3;
    const int m0 = blockIdx.y << 7, n0 = blockIdx.x << 7;

    float acc[2][8][4] = {};

    load_chunk_async(Ahi, Alo, Bthi, Btlo, m0, n0, 0, sbase, tid);
    asm volatile("cp.async.commit_group;");

    for (int c = 0; c < NCHUNK; c++) {
        if (c + 1 < NCHUNK) {
            load_chunk_async(Ahi, Alo, Bthi, Btlo, m0, n0, (c + 1) << 5,
                             sbase + ((c + 1) & 1) * 4 * TILE_BYTES, tid);
            asm volatile("cp.async.commit_group;");
            asm volatile("cp.async.wait_group 1;");
        } else {
            asm volatile("cp.async.wait_group 0;");
        }
        __syncthreads();

        const uint32_t st = sbase + (c & 1) * 4 * TILE_BYTES;
        const uint32_t Ahi_s = st, Alo_s = st + TILE_BYTES;
        const uint32_t Bhi_s = st + 2 * TILE_BYTES, Blo_s = st + 3 * TILE_BYTES;

#pragma unroll
        for (int ks = 0; ks < 2; ks++) {
            uint32_t ah[2][4], al[2][4];
#pragma unroll
            for (int mt = 0; mt < 2; mt++) {
                int row = wm * 32 + mt * 16 + (lane & 15);
                int kb = ks * 16 + ((lane >> 4) << 3);
                uint32_t off = (uint32_t)(row * TSTRIDE + kb) * 2;
                ldmatrix_x4(ah[mt], Ahi_s + off);
                ldmatrix_x4(al[mt], Alo_s + off);
            }
#pragma unroll
            for (int np = 0; np < 4; np++) {
                uint32_t bh[4], bl[4];
                int row = wn * 64 + np * 16 + ((lane >> 4) << 3) + (lane & 7);
                int kb = ks * 16 + (((lane >> 3) & 1) << 3);
                uint32_t off = (uint32_t)(row * TSTRIDE + kb) * 2;
                ldmatrix_x4(bh, Bhi_s + off);
                ldmatrix_x4(bl, Blo_s + off);
#pragma unroll
                for (int half = 0; half < 2; half++) {
                    int nt = 2 * np + half;
#pragma unroll
                    for (int mt = 0; mt < 2; mt++) {
                        mma16816(acc[mt][nt], ah[mt], bh + 2 * half);
                        mma16816(acc[mt][nt], ah[mt], bl + 2 * half);
                        mma16816(acc[mt][nt], al[mt], bh + 2 * half);
                    }
                }
            }
        }
        __syncthreads();
    }

#pragma unroll
    for (int mt = 0; mt < 2; mt++) {
#pragma unroll
        for (int h2 = 0; h2 < 2; h2++) {
            int m = m0 + wm * 32 + mt * 16 + g + h2 * 8;
            int bb = m >> 11, s = m & (S_LEN - 1);
            if (MODE == 0) {
                float* dst = &C[(size_t)m * E_DIM + n0 + wn * 64];
#pragma unroll
                for (int nt = 0; nt < 8; nt++) {
                    int col = nt * 8 + tg * 2;
                    float2 bv = *(const float2*)&bias[n0 + wn * 64 + col];
                    *(float2*)&dst[col] = make_float2(acc[mt][nt][h2 * 2 + 0] + bv.x,
                                                      acc[mt][nt][h2 * 2 + 1] + bv.y);
                }
            } else {
                int h = (n0 + wn * 64) >> 6;
                size_t rb = (((size_t)(bb * N_HEADS + h)) * S_LEN + s) << 6;
                float vals[8][2];
#pragma unroll
                for (int nt = 0; nt < 8; nt++) {
                    int col = nt * 8 + tg * 2;
                    float2 bv = *(const float2*)&bias[n0 + wn * 64 + col];
                    vals[nt][0] = acc[mt][nt][h2 * 2 + 0] + bv.x;
                    vals[nt][1] = acc[mt][nt][h2 * 2 + 1] + bv.y;
                }
                if (MODE == 2 || MODE == 3) {
#pragma unroll
                    for (int nt = 0; nt < 4; nt++) {
#pragma unroll
                        for (int jj = 0; jj < 2; jj++) {
                            int d = nt * 8 + tg * 2 + jj;
                            float cth = g_cos[(s << 5) + d];
                            float sth = g_sin[(s << 5) + d];
                            float lo = vals[nt][jj], hi = vals[nt + 4][jj];
                            vals[nt][jj]     = fmaf(lo, cth, -hi * sth);
                            vals[nt + 4][jj] = fmaf(hi, cth,  lo * sth);
                        }
                    }
                }
                if (MODE == 2) {
#pragma unroll
                    for (int nt = 0; nt < 8; nt++) {
                        vals[nt][0] *= SCALE_Q;
                        vals[nt][1] *= SCALE_Q;
                    }
                }
#pragma unroll
                for (int nt = 0; nt < 8; nt++) {
                    uint32_t hv, lv;
                    split2(vals[nt][0], vals[nt][1], hv, lv);
                    *(uint32_t*)(Chi + rb + nt * 8 + tg * 2) = hv;
                    *(uint32_t*)(Clo + rb + nt * 8 + tg * 2) = lv;
                }
            }
        }
    }
}

// ---------------------------------------------------------------------------
// Tensorized flash attention. Q-tile 128, KV-tile 128, 8 warps.
// Warp w owns rows {w*8..w*8+7} u {64+w*8..64+w*8+7}.
// smem: Qhi[128][144B] Qlo | 2 x (Khi Klo Vhi Vlo [128][144B] + mask[128])
// ---------------------------------------------------------------------------
#define ATT_Q    0
#define ATT_QL   18432
#define ATT_BUF0 36864
#define ATT_BUFSZ 74240                  // 4*18432 + 512
#define ATT_SMEM (36864 + 2 * ATT_BUFSZ) // 185344

__device__ __forceinline__ void attn_issue_kv(
    const __nv_bfloat16* khi, const __nv_bfloat16* klo,
    const __nv_bfloat16* vhi, const __nv_bfloat16* vlo,
    const int* mask, int mask_off, uint32_t sb, int t, int tid) {
    uint32_t bufb = sb + ATT_BUF0 + (t & 1) * ATT_BUFSZ;
    int k0 = t << 7;
    const __nv_bfloat16* srcs[4] = {khi, klo, vhi, vlo};
#pragma unroll
    for (int i = 0; i < 16; i++) {
        int idx = tid + i * 256;           // 0..4095
        int arr = idx >> 10;
        int r = (idx >> 3) & 127, seg = idx & 7;
        cp_async16(bufb + arr * 18432 + (uint32_t)(r * 144 + seg * 16),
                   srcs[arr] + (size_t)(k0 + r) * HD + seg * 8);
    }
    if (tid < 32)
        cp_async16(bufb + 73728 + tid * 16, mask + mask_off + k0 + tid * 4);
}

__global__ __launch_bounds__(256)
void attn_kernel(const __nv_bfloat16* __restrict__ qhi, const __nv_bfloat16* __restrict__ qlo,
                 const __nv_bfloat16* __restrict__ khi, const __nv_bfloat16* __restrict__ klo,
                 const __nv_bfloat16* __restrict__ vhi, const __nv_bfloat16* __restrict__ vlo,
                 const int* __restrict__ mask,
                 __nv_bfloat16* __restrict__ chi, __nv_bfloat16* __restrict__ clo) {
    extern __shared__ __align__(1024) char sm_[];
    const uint32_t sb = smem_u32(sm_);
    const int tid = threadIdx.x, w = tid >> 5, lane = tid & 31;
    const int g = lane >> 2, tg = lane & 3;
    const int qt = gridDim.x - 1 - blockIdx.x;
    const int bh = blockIdx.y, bb = bh >> 4, hh = bh & 15;
    const int q0 = qt << 7;
    const size_t base = (size_t)bh * S_LEN * HD;

    // load Q hi/lo
    {
        const __nv_bfloat16* s0 = qhi + base + (size_t)q0 * HD;
        const __nv_bfloat16* s1 = qlo + base + (size_t)q0 * HD;
#pragma unroll
        for (int i = 0; i < 8; i++) {
            int idx = tid + i * 256;
            int arr = idx >> 10;
            int r = (idx >> 3) & 127, seg = idx & 7;
            uint4 v = *(const uint4*)((arr ? s1 : s0) + (size_t)r * HD + seg * 8);
            *(uint4*)(sm_ + (arr ? ATT_QL : ATT_Q) + r * 144 + seg * 16) = v;
        }
    }

    const int ntile = qt + 1;
    attn_issue_kv(khi + base, klo + base, vhi + base, vlo + base,
                  mask, bb * S_LEN, sb, 0, tid);
    asm volatile("cp.async.commit_group;");
    __syncthreads();

    // hoisted Q fragments
    uint32_t qfh[4][4], qfl[4][4];
    {
        int i = lane & 15;
        int prow = (i < 8) ? (w * 8 + i) : (64 + w * 8 + (i - 8));
        int kb = ((lane >> 4) << 3);
#pragma unroll
        for (int ks = 0; ks < 4; ks++) {
            uint32_t off = (uint32_t)(prow * 144 + (ks * 16 + kb) * 2);
            ldmatrix_x4(qfh[ks], sb + ATT_Q + off);
            ldmatrix_x4(qfl[ks], sb + ATT_QL + off);
        }
    }
    const int row0 = q0 + w * 8 + g;
    const int row1 = q0 + 64 + w * 8 + g;

    float oacc[8][4] = {};
    float l0 = 0.f, l1 = 0.f, mo0 = -1e30f, mo1 = -1e30f;

    for (int t = 0; t < ntile; t++) {
        if (t + 1 < ntile) {
            attn_issue_kv(khi + base, klo + base, vhi + base, vlo + base,
                          mask, bb * S_LEN, sb, t + 1, tid);
            asm volatile("cp.async.commit_group;");
            asm volatile("cp.async.wait_group 1;");
        } else {
            asm volatile("cp.async.wait_group 0;");
        }
        __syncthreads();
        const uint32_t bufb = sb + ATT_BUF0 + (t & 1) * ATT_BUFSZ;
        const int k0 = t << 7;

        // S = Q @ K^T over 128 columns
        float sc[16][4] = {};
#pragma unroll
        for (int ks = 0; ks < 4; ks++) {
#pragma unroll
            for (int ntp = 0; ntp < 8; ntp++) {
                uint32_t kh[4], kl[4];
                int row = ntp * 16 + ((lane >> 4) << 3) + (lane & 7);
                int kb = ks * 16 + (((lane >> 3) & 1) << 3);
                uint32_t off = (uint32_t)(row * 144 + kb * 2);
                ldmatrix_x4(kh, bufb + off);
                ldmatrix_x4(kl, bufb + 18432 + off);
#pragma unroll
                for (int hf = 0; hf < 2; hf++) {
                    int nt = 2 * ntp + hf;
                    mma16816(sc[nt], qfh[ks], kh + 2 * hf);
                    mma16816(sc[nt], qfh[ks], kl + 2 * hf);
                    mma16816(sc[nt], qfl[ks], kh + 2 * hf);
                }
            }
        }

        // padding mask (4 ballots for 128 columns)
        const int* Ms = (const int*)(sm_ + ATT_BUF0 + (t & 1) * ATT_BUFSZ + 73728);
        uint32_t pb[4];
        pb[0] = __ballot_sync(0xffffffffu, Ms[lane] != 0);
        pb[1] = __ballot_sync(0xffffffffu, Ms[lane + 32] != 0);
        pb[2] = __ballot_sync(0xffffffffu, Ms[lane + 64] != 0);
        pb[3] = __ballot_sync(0xffffffffu, Ms[lane + 96] != 0);
        if ((pb[0] & pb[1] & pb[2] & pb[3]) != 0xffffffffu) {
#pragma unroll
            for (int nt = 0; nt < 16; nt++)
#pragma unroll
                for (int j = 0; j < 2; j++) {
                    int cl = nt * 8 + tg * 2 + j;
                    if (!((pb[cl >> 5] >> (cl & 31)) & 1)) {
                        sc[nt][j] = -1e30f;
                        sc[nt][2 + j] = -1e30f;
                    }
                }
        }
        // causal mask (only the diagonal tile needs it)
        if (k0 + 127 > row0) {
#pragma unroll
            for (int nt = 0; nt < 16; nt++)
#pragma unroll
                for (int j = 0; j < 2; j++) {
                    int cg = k0 + nt * 8 + tg * 2 + j;
                    if (cg > row0) sc[nt][j] = -1e30f;
                    if (cg > row1) sc[nt][2 + j] = -1e30f;
                }
        }

        // online softmax (base-2 domain)
        float mx0 = -1e30f, mx1 = -1e30f;
#pragma unroll
        for (int nt = 0; nt < 16; nt++) {
            mx0 = fmaxf(mx0, fmaxf(sc[nt][0], sc[nt][1]));
            mx1 = fmaxf(mx1, fmaxf(sc[nt][2], sc[nt][3]));
        }
        mx0 = fmaxf(mx0, __shfl_xor_sync(0xffffffffu, mx0, 1));
        mx0 = fmaxf(mx0, __shfl_xor_sync(0xffffffffu, mx0, 2));
        mx1 = fmaxf(mx1, __shfl_xor_sync(0xffffffffu, mx1, 1));
        mx1 = fmaxf(mx1, __shfl_xor_sync(0xffffffffu, mx1, 2));
        float mn0 = fmaxf(mo0, mx0), mn1 = fmaxf(mo1, mx1);
        float al0 = ex2(mo0 - mn0), al1 = ex2(mo1 - mn1);
        float rs0 = 0.f, rs1 = 0.f;
#pragma unroll
        for (int nt = 0; nt < 16; nt++) {
            sc[nt][0] = ex2(sc[nt][0] - mn0);
            sc[nt][1] = ex2(sc[nt][1] - mn0);
            sc[nt][2] = ex2(sc[nt][2] - mn1);
            sc[nt][3] = ex2(sc[nt][3] - mn1);
            rs0 += sc[nt][0] + sc[nt][1];
            rs1 += sc[nt][2] + sc[nt][3];
        }
        rs0 += __shfl_xor_sync(0xffffffffu, rs0, 1);
        rs0 += __shfl_xor_sync(0xffffffffu, rs0, 2);
        rs1 += __shfl_xor_sync(0xffffffffu, rs1, 1);
        rs1 += __shfl_xor_sync(0xffffffffu, rs1, 2);
        l0 = l0 * al0 + rs0;
        l1 = l1 * al1 + rs1;
        mo0 = mn0; mo1 = mn1;
#pragma unroll
        for (int nt = 0; nt < 8; nt++) {
            oacc[nt][0] *= al0; oacc[nt][1] *= al0;
            oacc[nt][2] *= al1; oacc[nt][3] *= al1;
        }

        // O += P @ V  (P repacked from registers, split hi/lo; k-dim 128)
#pragma unroll
        for (int ks = 0; ks < 8; ks++) {
            uint32_t pa[4], pl[4];
            split2(sc[2 * ks][0], sc[2 * ks][1], pa[0], pl[0]);
            split2(sc[2 * ks][2], sc[2 * ks][3], pa[1], pl[1]);
            split2(sc[2 * ks + 1][0], sc[2 * ks + 1][1], pa[2], pl[2]);
            split2(sc[2 * ks + 1][2], sc[2 * ks + 1][3], pa[3], pl[3]);
#pragma unroll
            for (int dtp = 0; dtp < 4; dtp++) {
                uint32_t vh[4], vl[4];
                int rkv = ks * 16 + ((lane >> 3) & 1) * 8 + (lane & 7);
                int cd = dtp * 16 + (lane >> 4) * 8;
                uint32_t off = (uint32_t)(rkv * 144 + cd * 2);
                ldmatrix_x4_trans(vh, bufb + 36864 + off);
                ldmatrix_x4_trans(vl, bufb + 55296 + off);
#pragma unroll
                for (int hf = 0; hf < 2; hf++) {
                    int nt = 2 * dtp + hf;
                    mma16816(oacc[nt], pa, vh + 2 * hf);
                    mma16816(oacc[nt], pa, vl + 2 * hf);
                    mma16816(oacc[nt], pl, vh + 2 * hf);
                }
            }
        }
        __syncthreads();
    }

    // epilogue
    float inv0 = 1.0f / l0, inv1 = 1.0f / l1;
    __nv_bfloat16* dh0 = chi + ((size_t)(bb * S_LEN + row0)) * E_DIM + hh * 64;
    __nv_bfloat16* dl0 = clo + ((size_t)(bb * S_LEN + row0)) * E_DIM + hh * 64;
    __nv_bfloat16* dh1 = chi + ((size_t)(bb * S_LEN + row1)) * E_DIM + hh * 64;
    __nv_bfloat16* dl1 = clo + ((size_t)(bb * S_LEN + row1)) * E_DIM + hh * 64;
#pragma unroll
    for (int nt = 0; nt < 8; nt++) {
        int d = nt * 8 + tg * 2;
        uint32_t hv, lv;
        split2(oacc[nt][0] * inv0, oacc[nt][1] * inv0, hv, lv);
        *(uint32_t*)(dh0 + d) = hv;
        *(uint32_t*)(dl0 + d) = lv;
        split2(oacc[nt][2] * inv1, oacc[nt][3] * inv1, hv, lv);
        *(uint32_t*)(dh1 + d) = hv;
        *(uint32_t*)(dl1 + d) = lv;
    }
}

// ---------------------------------------------------------------------------
extern "C" void kernel_launch(void* const* d_in, const int* in_sizes, int n_in,
                              void* d_out, int out_size) {
    const float* x    = (const float*)d_in[0];
    const int*   mask = (const int*)d_in[1];
    const float* Wq   = (const float*)d_in[2];
    const float* bq   = (const float*)d_in[3];
    const float* Wk   = (const float*)d_in[4];
    const float* bk   = (const float*)d_in[5];
    const float* Wv   = (const float*)d_in[6];
    const float* bv   = (const float*)d_in[7];
    const float* Wo   = (const float*)d_in[8];
    const float* bo   = (const float*)d_in[9];
    float* out = (float*)d_out;

    __nv_bfloat16 *pxhi, *pxlo, *pchi, *pclo, *pwthi, *pwtlo;
    __nv_bfloat16 *pqhi, *pqlo, *pkhi, *pklo, *pvhi, *pvlo;
    cudaGetSymbolAddress((void**)&pxhi, g_xhi);
    cudaGetSymbolAddress((void**)&pxlo, g_xlo);
    cudaGetSymbolAddress((void**)&pchi, g_chi);
    cudaGetSymbolAddress((void**)&pclo, g_clo);
    cudaGetSymbolAddress((void**)&pqhi, g_qhi);
    cudaGetSymbolAddress((void**)&pqlo, g_qlo);
    cudaGetSymbolAddress((void**)&pkhi, g_khi);
    cudaGetSymbolAddress((void**)&pklo, g_klo);
    cudaGetSymbolAddress((void**)&pvhi, g_vhi);
    cudaGetSymbolAddress((void**)&pvlo, g_vlo);
    cudaGetSymbolAddress((void**)&pwthi, g_wthi);
    cudaGetSymbolAddress((void**)&pwtlo, g_wtlo);
    const size_t WSTRIDE = (size_t)E_DIM * E_DIM;

    rope_table_kernel<<<(S_LEN * 32 + 255) / 256, 256>>>();

    const int n4 = M_ROWS * E_DIM / 4;
    cvt_split_kernel<<<(n4 + 255) / 256, 256>>>(
        (const float4*)x, (__nv_bfloat162*)pxhi, (__nv_bfloat162*)pxlo, n4);

    cvt_transpose4_kernel<<<dim3(32, 32, 4), 256>>>(Wq, Wk, Wv, Wo, pwthi, pwtlo);

    const int GSMEM = 2 * 4 * TILE_BYTES;
    cudaFuncSetAttribute(tgemm_kernel<0>, cudaFuncAttributeMaxDynamicSharedMemorySize, GSMEM);
    cudaFuncSetAttribute(tgemm_kernel<1>, cudaFuncAttributeMaxDynamicSharedMemorySize, GSMEM);
    cudaFuncSetAttribute(tgemm_kernel<2>, cudaFuncAttributeMaxDynamicSharedMemorySize, GSMEM);
    cudaFuncSetAttribute(tgemm_kernel<3>, cudaFuncAttributeMaxDynamicSharedMemorySize, GSMEM);

    dim3 gg(E_DIM / 128, M_ROWS / 128);
    tgemm_kernel<2><<<gg, 256, GSMEM>>>(pxhi, pxlo, pwthi + 0 * WSTRIDE, pwtlo + 0 * WSTRIDE,
                                        bq, nullptr, pqhi, pqlo);
    tgemm_kernel<3><<<gg, 256, GSMEM>>>(pxhi, pxlo, pwthi + 1 * WSTRIDE, pwtlo + 1 * WSTRIDE,
                                        bk, nullptr, pkhi, pklo);
    tgemm_kernel<1><<<gg, 256, GSMEM>>>(pxhi, pxlo, pwthi + 2 * WSTRIDE, pwtlo + 2 * WSTRIDE,
                                        bv, nullptr, pvhi, pvlo);

    cudaFuncSetAttribute(attn_kernel, cudaFuncAttributeMaxDynamicSharedMemorySize, ATT_SMEM);
    attn_kernel<<<dim3(S_LEN / 128, BATCH * N_HEADS), 256, ATT_SMEM>>>(
        pqhi, pqlo, pkhi, pklo, pvhi, pvlo, mask, pchi, pclo);

    tgemm_kernel<0><<<gg, 256, GSMEM>>>(pchi, pclo, pwthi + 3 * WSTRIDE, pwtlo + 3 * WSTRIDE,
                                        bo, out, nullptr, nullptr);
}

// round 7
// speedup vs baseline: 2.9281x; 1.0208x over previous
#include <cuda_runtime.h>
#include <cuda_bf16.h>
#include <math.h>
#include <stdint.h>

#define S_LEN 2048
#define E_DIM 1024
#define N_HEADS 16
#define HD 64
#define BATCH 2
#define M_ROWS 4096
#define SCALE_Q 0.18033688011112042f   // 0.125 * log2(e)

// ---------------- scratch ---------------------------------------------------
__device__ __align__(256) float g_cos[S_LEN * 32];
__device__ __align__(256) float g_sin[S_LEN * 32];
__device__ __align__(256) float g_bias[3 * E_DIM];
__device__ __align__(256) __nv_bfloat16 g_xhi[(size_t)M_ROWS * E_DIM];
__device__ __align__(256) __nv_bfloat16 g_xlo[(size_t)M_ROWS * E_DIM];
__device__ __align__(256) __nv_bfloat16 g_chi[(size_t)M_ROWS * E_DIM];
__device__ __align__(256) __nv_bfloat16 g_clo[(size_t)M_ROWS * E_DIM];
__device__ __align__(256) __nv_bfloat16 g_qhi[(size_t)M_ROWS * E_DIM];
__device__ __align__(256) __nv_bfloat16 g_qlo[(size_t)M_ROWS * E_DIM];
__device__ __align__(256) __nv_bfloat16 g_khi[(size_t)M_ROWS * E_DIM];
__device__ __align__(256) __nv_bfloat16 g_klo[(size_t)M_ROWS * E_DIM];
__device__ __align__(256) __nv_bfloat16 g_vhi[(size_t)M_ROWS * E_DIM];
__device__ __align__(256) __nv_bfloat16 g_vlo[(size_t)M_ROWS * E_DIM];
__device__ __align__(256) __nv_bfloat16 g_wthi[4][(size_t)E_DIM * E_DIM];  // [N][K]
__device__ __align__(256) __nv_bfloat16 g_wtlo[4][(size_t)E_DIM * E_DIM];

// ---------------- helpers ---------------------------------------------------
__device__ __forceinline__ uint32_t smem_u32(const void* p) {
    uint32_t a;
    asm("{ .reg .u64 t; cvta.to.shared.u64 t, %1; cvt.u32.u64 %0, t; }"
        : "=r"(a) : "l"(p));
    return a;
}
__device__ __forceinline__ void ldmatrix_x4(uint32_t* r, uint32_t addr) {
    asm volatile("ldmatrix.sync.aligned.m8n8.x4.shared.b16 {%0,%1,%2,%3}, [%4];"
                 : "=r"(r[0]), "=r"(r[1]), "=r"(r[2]), "=r"(r[3]) : "r"(addr));
}
__device__ __forceinline__ void ldmatrix_x4_trans(uint32_t* r, uint32_t addr) {
    asm volatile("ldmatrix.sync.aligned.m8n8.x4.trans.shared.b16 {%0,%1,%2,%3}, [%4];"
                 : "=r"(r[0]), "=r"(r[1]), "=r"(r[2]), "=r"(r[3]) : "r"(addr));
}
// Non-volatile: pure register op; lets ptxas interleave independent acc chains.
__device__ __forceinline__ void mma16816(float* c, const uint32_t* a, const uint32_t* b) {
    asm("mma.sync.aligned.m16n8k16.row.col.f32.bf16.bf16.f32 "
        "{%0,%1,%2,%3}, {%4,%5,%6,%7}, {%8,%9}, {%0,%1,%2,%3};"
        : "+f"(c[0]), "+f"(c[1]), "+f"(c[2]), "+f"(c[3])
        : "r"(a[0]), "r"(a[1]), "r"(a[2]), "r"(a[3]), "r"(b[0]), "r"(b[1]));
}
__device__ __forceinline__ void cp_async16(uint32_t dst, const void* src) {
    asm volatile("cp.async.cg.shared.global [%0], [%1], 16;" :: "r"(dst), "l"(src));
}
__device__ __forceinline__ float ex2(float x) {
    float y;
    asm("ex2.approx.f32 %0, %1;" : "=f"(y) : "f"(x));
    return y;
}
__device__ __forceinline__ void split2(float x, float y, uint32_t& h, uint32_t& l) {
    __nv_bfloat162 hb = __floats2bfloat162_rn(x, y);
    float2 hf = __bfloat1622float2(hb);
    __nv_bfloat162 lb = __floats2bfloat162_rn(x - hf.x, y - hf.y);
    h = *(uint32_t*)&hb;
    l = *(uint32_t*)&lb;
}

// ---------------------------------------------------------------------------
__global__ void rope_table_kernel(const float* __restrict__ bq,
                                  const float* __restrict__ bk,
                                  const float* __restrict__ bv) {
    int i = blockIdx.x * blockDim.x + threadIdx.x;
    if (i < 3 * E_DIM) {
        const float* b = (i < E_DIM) ? bq : (i < 2 * E_DIM) ? bk : bv;
        g_bias[i] = b[i & (E_DIM - 1)];
    }
    if (i >= S_LEN * 32) return;
    int s = i >> 5, j = i & 31;
    float inv = (float)pow(10000.0, -(double)j / 32.0);
    float th = (float)s * inv;
    g_cos[i] = cosf(th);
    g_sin[i] = sinf(th);
}

__global__ void cvt_split_kernel(const float4* __restrict__ src,
                                 __nv_bfloat162* __restrict__ hi,
                                 __nv_bfloat162* __restrict__ lo, int n4) {
    int i = blockIdx.x * blockDim.x + threadIdx.x;
    if (i >= n4) return;
    float4 v = src[i];
    __nv_bfloat162 h01 = __floats2bfloat162_rn(v.x, v.y);
    __nv_bfloat162 h23 = __floats2bfloat162_rn(v.z, v.w);
    float2 f01 = __bfloat1622float2(h01);
    float2 f23 = __bfloat1622float2(h23);
    hi[2 * i] = h01;
    hi[2 * i + 1] = h23;
    lo[2 * i] = __floats2bfloat162_rn(v.x - f01.x, v.y - f01.y);
    lo[2 * i + 1] = __floats2bfloat162_rn(v.z - f23.x, v.w - f23.y);
}

__global__ void cvt_transpose4_kernel(const float* __restrict__ W0,
                                      const float* __restrict__ W1,
                                      const float* __restrict__ W2,
                                      const float* __restrict__ W3) {
    __shared__ float t[32][33];
    const float* Ws[4] = {W0, W1, W2, W3};
    const float* W = Ws[blockIdx.z];
    __nv_bfloat16* thiz = g_wthi[blockIdx.z];
    __nv_bfloat16* tloz = g_wtlo[blockIdx.z];
    int bx = blockIdx.x, by = blockIdx.y;
    int tid = threadIdx.x;
#pragma unroll
    for (int it = 0; it < 4; it++) {
        int idx = tid + it * 256;
        int r = idx >> 5, c = idx & 31;
        t[r][c] = W[(size_t)(by * 32 + r) * E_DIM + bx * 32 + c];
    }
    __syncthreads();
#pragma unroll
    for (int it = 0; it < 4; it++) {
        int idx = tid + it * 256;
        int r = idx >> 5, c = idx & 31;
        float x = t[c][r];
        __nv_bfloat16 h = __float2bfloat16(x);
        size_t o = (size_t)(bx * 32 + r) * E_DIM + by * 32 + c;
        thiz[o] = h;
        tloz[o] = __float2bfloat16(x - __bfloat162float(h));
    }
}

// ---------------------------------------------------------------------------
// Shared split-bf16 mma.sync GEMM mainloop. 128x128 tile, BK=32, 8 warps.
// Term-major MMA ordering: dependent MMAs are 4 independent MMAs apart.
// ---------------------------------------------------------------------------
#define TSTRIDE 40
#define TILE_BYTES (128 * TSTRIDE * 2)
#define NCHUNK 32
#define GSMEM (2 * 4 * TILE_BYTES)

__device__ __forceinline__ void load_chunk_async(
    const __nv_bfloat16* __restrict__ Ahi, const __nv_bfloat16* __restrict__ Alo,
    const __nv_bfloat16* __restrict__ Bhi, const __nv_bfloat16* __restrict__ Blo,
    int m0, int n0, int k0, uint32_t st, int tid) {
    const __nv_bfloat16* srcs[4] = {Ahi, Alo, Bhi, Blo};
    int r0s[4] = {m0, m0, n0, n0};
#pragma unroll
    for (int tno = 0; tno < 4; tno++) {
        uint32_t sdst = st + tno * TILE_BYTES;
        const __nv_bfloat16* src = srcs[tno];
        int row0 = r0s[tno];
#pragma unroll
        for (int it = 0; it < 2; it++) {
            int idx = tid + it * 256;
            int r = idx >> 2, seg = idx & 3;
            cp_async16(sdst + (uint32_t)(r * TSTRIDE + seg * 8) * 2,
                       src + (size_t)(row0 + r) * E_DIM + k0 + seg * 8);
        }
    }
}

__device__ __forceinline__ void gemm_mainloop(
    const __nv_bfloat16* __restrict__ Ahi, const __nv_bfloat16* __restrict__ Alo,
    const __nv_bfloat16* __restrict__ Bthi, const __nv_bfloat16* __restrict__ Btlo,
    int m0, int n0, uint32_t sbase, int tid, int wm, int wn, int lane,
    float acc[2][8][4]) {

    load_chunk_async(Ahi, Alo, Bthi, Btlo, m0, n0, 0, sbase, tid);
    asm volatile("cp.async.commit_group;");

    for (int c = 0; c < NCHUNK; c++) {
        if (c + 1 < NCHUNK) {
            load_chunk_async(Ahi, Alo, Bthi, Btlo, m0, n0, (c + 1) << 5,
                             sbase + ((c + 1) & 1) * 4 * TILE_BYTES, tid);
            asm volatile("cp.async.commit_group;");
            asm volatile("cp.async.wait_group 1;");
        } else {
            asm volatile("cp.async.wait_group 0;");
        }
        __syncthreads();

        const uint32_t st = sbase + (c & 1) * 4 * TILE_BYTES;
        const uint32_t Ahi_s = st, Alo_s = st + TILE_BYTES;
        const uint32_t Bhi_s = st + 2 * TILE_BYTES, Blo_s = st + 3 * TILE_BYTES;

#pragma unroll
        for (int ks = 0; ks < 2; ks++) {
            uint32_t ah[2][4], al[2][4];
#pragma unroll
            for (int mt = 0; mt < 2; mt++) {
                int row = wm * 32 + mt * 16 + (lane & 15);
                int kb = ks * 16 + ((lane >> 4) << 3);
                uint32_t off = (uint32_t)(row * TSTRIDE + kb) * 2;
                ldmatrix_x4(ah[mt], Ahi_s + off);
                ldmatrix_x4(al[mt], Alo_s + off);
            }
#pragma unroll
            for (int np = 0; np < 4; np++) {
                uint32_t bh[4], bl[4];
                int row = wn * 64 + np * 16 + ((lane >> 4) << 3) + (lane & 7);
                int kb = ks * 16 + (((lane >> 3) & 1) << 3);
                uint32_t off = (uint32_t)(row * TSTRIDE + kb) * 2;
                ldmatrix_x4(bh, Bhi_s + off);
                ldmatrix_x4(bl, Blo_s + off);
#pragma unroll
                for (int half = 0; half < 2; half++)
#pragma unroll
                    for (int mt = 0; mt < 2; mt++)
                        mma16816(acc[mt][2 * np + half], ah[mt], bh + 2 * half);
#pragma unroll
                for (int half = 0; half < 2; half++)
#pragma unroll
                    for (int mt = 0; mt < 2; mt++)
                        mma16816(acc[mt][2 * np + half], ah[mt], bl + 2 * half);
#pragma unroll
                for (int half = 0; half < 2; half++)
#pragma unroll
                    for (int mt = 0; mt < 2; mt++)
                        mma16816(acc[mt][2 * np + half], al[mt], bh + 2 * half);
            }
        }
        __syncthreads();
    }
}

// Fused QKV projection: z = 0:Q(+RoPE+scale) 1:K(+RoPE) 2:V
__global__ __launch_bounds__(256)
void tgemm_qkv_kernel() {
    extern __shared__ __align__(1024) char dsm[];
    const uint32_t sbase = smem_u32(dsm);
    const int tid = threadIdx.x;
    const int wid = tid >> 5, lane = tid & 31;
    const int wm = wid & 3, wn = wid >> 2;
    const int g = lane >> 2, tg = lane & 3;
    const int m0 = blockIdx.y << 7, n0 = blockIdx.x << 7;
    const int z = blockIdx.z;

    const __nv_bfloat16* Bthi = g_wthi[z];
    const __nv_bfloat16* Btlo = g_wtlo[z];
    const float* bias = g_bias + (z << 10);
    __nv_bfloat16* Chi = (z == 0) ? g_qhi : (z == 1) ? g_khi : g_vhi;
    __nv_bfloat16* Clo = (z == 0) ? g_qlo : (z == 1) ? g_klo : g_vlo;

    float acc[2][8][4] = {};
    gemm_mainloop(g_xhi, g_xlo, Bthi, Btlo, m0, n0, sbase, tid, wm, wn, lane, acc);

#pragma unroll
    for (int mt = 0; mt < 2; mt++) {
#pragma unroll
        for (int h2 = 0; h2 < 2; h2++) {
            int m = m0 + wm * 32 + mt * 16 + g + h2 * 8;
            int bb = m >> 11, s = m & (S_LEN - 1);
            int h = (n0 + wn * 64) >> 6;
            size_t rb = (((size_t)(bb * N_HEADS + h)) * S_LEN + s) << 6;
            float vals[8][2];
#pragma unroll
            for (int nt = 0; nt < 8; nt++) {
                int col = nt * 8 + tg * 2;
                float2 bv = *(const float2*)&bias[n0 + wn * 64 + col];
                vals[nt][0] = acc[mt][nt][h2 * 2 + 0] + bv.x;
                vals[nt][1] = acc[mt][nt][h2 * 2 + 1] + bv.y;
            }
            if (z < 2) {
#pragma unroll
                for (int nt = 0; nt < 4; nt++) {
#pragma unroll
                    for (int jj = 0; jj < 2; jj++) {
                        int d = nt * 8 + tg * 2 + jj;
                        float cth = g_cos[(s << 5) + d];
                        float sth = g_sin[(s << 5) + d];
                        float lo = vals[nt][jj], hi = vals[nt + 4][jj];
                        vals[nt][jj]     = fmaf(lo, cth, -hi * sth);
                        vals[nt + 4][jj] = fmaf(hi, cth,  lo * sth);
                    }
                }
            }
            if (z == 0) {
#pragma unroll
                for (int nt = 0; nt < 8; nt++) {
                    vals[nt][0] *= SCALE_Q;
                    vals[nt][1] *= SCALE_Q;
                }
            }
#pragma unroll
            for (int nt = 0; nt < 8; nt++) {
                uint32_t hv, lv;
                split2(vals[nt][0], vals[nt][1], hv, lv);
                *(uint32_t*)(Chi + rb + nt * 8 + tg * 2) = hv;
                *(uint32_t*)(Clo + rb + nt * 8 + tg * 2) = lv;
            }
        }
    }
}

// Output projection
__global__ __launch_bounds__(256)
void tgemm_out_kernel(const float* __restrict__ bias, float* __restrict__ C) {
    extern __shared__ __align__(1024) char dsm[];
    const uint32_t sbase = smem_u32(dsm);
    const int tid = threadIdx.x;
    const int wid = tid >> 5, lane = tid & 31;
    const int wm = wid & 3, wn = wid >> 2;
    const int g = lane >> 2, tg = lane & 3;
    const int m0 = blockIdx.y << 7, n0 = blockIdx.x << 7;

    float acc[2][8][4] = {};
    gemm_mainloop(g_chi, g_clo, g_wthi[3], g_wtlo[3], m0, n0, sbase, tid, wm, wn, lane, acc);

#pragma unroll
    for (int mt = 0; mt < 2; mt++) {
#pragma unroll
        for (int h2 = 0; h2 < 2; h2++) {
            int m = m0 + wm * 32 + mt * 16 + g + h2 * 8;
            float* dst = &C[(size_t)m * E_DIM + n0 + wn * 64];
#pragma unroll
            for (int nt = 0; nt < 8; nt++) {
                int col = nt * 8 + tg * 2;
                float2 bv = *(const float2*)&bias[n0 + wn * 64 + col];
                *(float2*)&dst[col] = make_float2(acc[mt][nt][h2 * 2 + 0] + bv.x,
                                                  acc[mt][nt][h2 * 2 + 1] + bv.y);
            }
        }
    }
}

// ---------------------------------------------------------------------------
// Tensorized flash attention. Q-tile 128, KV-tile 128, 8 warps.
// ---------------------------------------------------------------------------
#define ATT_Q    0
#define ATT_QL   18432
#define ATT_BUF0 36864
#define ATT_BUFSZ 74240
#define ATT_SMEM (36864 + 2 * ATT_BUFSZ)

__device__ __forceinline__ void attn_issue_kv(
    const __nv_bfloat16* khi, const __nv_bfloat16* klo,
    const __nv_bfloat16* vhi, const __nv_bfloat16* vlo,
    const int* mask, int mask_off, uint32_t sb, int t, int tid) {
    uint32_t bufb = sb + ATT_BUF0 + (t & 1) * ATT_BUFSZ;
    int k0 = t << 7;
    const __nv_bfloat16* srcs[4] = {khi, klo, vhi, vlo};
#pragma unroll
    for (int i = 0; i < 16; i++) {
        int idx = tid + i * 256;
        int arr = idx >> 10;
        int r = (idx >> 3) & 127, seg = idx & 7;
        cp_async16(bufb + arr * 18432 + (uint32_t)(r * 144 + seg * 16),
                   srcs[arr] + (size_t)(k0 + r) * HD + seg * 8);
    }
    if (tid < 32)
        cp_async16(bufb + 73728 + tid * 16, mask + mask_off + k0 + tid * 4);
}

__global__ __launch_bounds__(256)
void attn_kernel(const int* __restrict__ mask) {
    extern __shared__ __align__(1024) char sm_[];
    const uint32_t sb = smem_u32(sm_);
    const int tid = threadIdx.x, w = tid >> 5, lane = tid & 31;
    const int g = lane >> 2, tg = lane & 3;
    const int qt = gridDim.x - 1 - blockIdx.x;
    const int bh = blockIdx.y, bb = bh >> 4, hh = bh & 15;
    const int q0 = qt << 7;
    const size_t base = (size_t)bh * S_LEN * HD;

    {
        const __nv_bfloat16* s0 = g_qhi + base + (size_t)q0 * HD;
        const __nv_bfloat16* s1 = g_qlo + base + (size_t)q0 * HD;
#pragma unroll
        for (int i = 0; i < 8; i++) {
            int idx = tid + i * 256;
            int arr = idx >> 10;
            int r = (idx >> 3) & 127, seg = idx & 7;
            uint4 v = *(const uint4*)((arr ? s1 : s0) + (size_t)r * HD + seg * 8);
            *(uint4*)(sm_ + (arr ? ATT_QL : ATT_Q) + r * 144 + seg * 16) = v;
        }
    }

    const int ntile = qt + 1;
    attn_issue_kv(g_khi + base, g_klo + base, g_vhi + base, g_vlo + base,
                  mask, bb * S_LEN, sb, 0, tid);
    asm volatile("cp.async.commit_group;");
    __syncthreads();

    uint32_t qfh[4][4], qfl[4][4];
    {
        int i = lane & 15;
        int prow = (i < 8) ? (w * 8 + i) : (64 + w * 8 + (i - 8));
        int kb = ((lane >> 4) << 3);
#pragma unroll
        for (int ks = 0; ks < 4; ks++) {
            uint32_t off = (uint32_t)(prow * 144 + (ks * 16 + kb) * 2);
            ldmatrix_x4(qfh[ks], sb + ATT_Q + off);
            ldmatrix_x4(qfl[ks], sb + ATT_QL + off);
        }
    }
    const int row0 = q0 + w * 8 + g;
    const int row1 = q0 + 64 + w * 8 + g;

    float oacc[8][4] = {};
    float l0 = 0.f, l1 = 0.f, mo0 = -1e30f, mo1 = -1e30f;

    for (int t = 0; t < ntile; t++) {
        if (t + 1 < ntile) {
            attn_issue_kv(g_khi + base, g_klo + base, g_vhi + base, g_vlo + base,
                          mask, bb * S_LEN, sb, t + 1, tid);
            asm volatile("cp.async.commit_group;");
            asm volatile("cp.async.wait_group 1;");
        } else {
            asm volatile("cp.async.wait_group 0;");
        }
        __syncthreads();
        const uint32_t bufb = sb + ATT_BUF0 + (t & 1) * ATT_BUFSZ;
        const int k0 = t << 7;

        float sc[16][4] = {};
#pragma unroll
        for (int ks = 0; ks < 4; ks++) {
#pragma unroll
            for (int ntp = 0; ntp < 8; ntp++) {
                uint32_t kh[4], kl[4];
                int row = ntp * 16 + ((lane >> 4) << 3) + (lane & 7);
                int kb = ks * 16 + (((lane >> 3) & 1) << 3);
                uint32_t off = (uint32_t)(row * 144 + kb * 2);
                ldmatrix_x4(kh, bufb + off);
                ldmatrix_x4(kl, bufb + 18432 + off);
#pragma unroll
                for (int hf = 0; hf < 2; hf++)
                    mma16816(sc[2 * ntp + hf], qfh[ks], kh + 2 * hf);
#pragma unroll
                for (int hf = 0; hf < 2; hf++)
                    mma16816(sc[2 * ntp + hf], qfh[ks], kl + 2 * hf);
#pragma unroll
                for (int hf = 0; hf < 2; hf++)
                    mma16816(sc[2 * ntp + hf], qfl[ks], kh + 2 * hf);
            }
        }

        const int* Ms = (const int*)(sm_ + ATT_BUF0 + (t & 1) * ATT_BUFSZ + 73728);
        uint32_t pb[4];
        pb[0] = __ballot_sync(0xffffffffu, Ms[lane] != 0);
        pb[1] = __ballot_sync(0xffffffffu, Ms[lane + 32] != 0);
        pb[2] = __ballot_sync(0xffffffffu, Ms[lane + 64] != 0);
        pb[3] = __ballot_sync(0xffffffffu, Ms[lane + 96] != 0);
        if ((pb[0] & pb[1] & pb[2] & pb[3]) != 0xffffffffu) {
#pragma unroll
            for (int nt = 0; nt < 16; nt++)
#pragma unroll
                for (int j = 0; j < 2; j++) {
                    int cl = nt * 8 + tg * 2 + j;
                    if (!((pb[cl >> 5] >> (cl & 31)) & 1)) {
                        sc[nt][j] = -1e30f;
                        sc[nt][2 + j] = -1e30f;
                    }
                }
        }
        if (k0 + 127 > row0) {
#pragma unroll
            for (int nt = 0; nt < 16; nt++)
#pragma unroll
                for (int j = 0; j < 2; j++) {
                    int cg = k0 + nt * 8 + tg * 2 + j;
                    if (cg > row0) sc[nt][j] = -1e30f;
                    if (cg > row1) sc[nt][2 + j] = -1e30f;
                }
        }

        float mx0 = -1e30f, mx1 = -1e30f;
#pragma unroll
        for (int nt = 0; nt < 16; nt++) {
            mx0 = fmaxf(mx0, fmaxf(sc[nt][0], sc[nt][1]));
            mx1 = fmaxf(mx1, fmaxf(sc[nt][2], sc[nt][3]));
        }
        mx0 = fmaxf(mx0, __shfl_xor_sync(0xffffffffu, mx0, 1));
        mx0 = fmaxf(mx0, __shfl_xor_sync(0xffffffffu, mx0, 2));
        mx1 = fmaxf(mx1, __shfl_xor_sync(0xffffffffu, mx1, 1));
        mx1 = fmaxf(mx1, __shfl_xor_sync(0xffffffffu, mx1, 2));
        float mn0 = fmaxf(mo0, mx0), mn1 = fmaxf(mo1, mx1);
        float al0 = ex2(mo0 - mn0), al1 = ex2(mo1 - mn1);
        float rs0 = 0.f, rs1 = 0.f;
#pragma unroll
        for (int nt = 0; nt < 16; nt++) {
            sc[nt][0] = ex2(sc[nt][0] - mn0);
            sc[nt][1] = ex2(sc[nt][1] - mn0);
            sc[nt][2] = ex2(sc[nt][2] - mn1);
            sc[nt][3] = ex2(sc[nt][3] - mn1);
            rs0 += sc[nt][0] + sc[nt][1];
            rs1 += sc[nt][2] + sc[nt][3];
        }
        rs0 += __shfl_xor_sync(0xffffffffu, rs0, 1);
        rs0 += __shfl_xor_sync(0xffffffffu, rs0, 2);
        rs1 += __shfl_xor_sync(0xffffffffu, rs1, 1);
        rs1 += __shfl_xor_sync(0xffffffffu, rs1, 2);
        l0 = l0 * al0 + rs0;
        l1 = l1 * al1 + rs1;
        mo0 = mn0; mo1 = mn1;
#pragma unroll
        for (int nt = 0; nt < 8; nt++) {
            oacc[nt][0] *= al0; oacc[nt][1] *= al0;
            oacc[nt][2] *= al1; oacc[nt][3] *= al1;
        }

#pragma unroll
        for (int ks = 0; ks < 8; ks++) {
            uint32_t pa[4], pl[4];
            split2(sc[2 * ks][0], sc[2 * ks][1], pa[0], pl[0]);
            split2(sc[2 * ks][2], sc[2 * ks][3], pa[1], pl[1]);
            split2(sc[2 * ks + 1][0], sc[2 * ks + 1][1], pa[2], pl[2]);
            split2(sc[2 * ks + 1][2], sc[2 * ks + 1][3], pa[3], pl[3]);
#pragma unroll
            for (int dtp = 0; dtp < 4; dtp++) {
                uint32_t vh[4], vl[4];
                int rkv = ks * 16 + ((lane >> 3) & 1) * 8 + (lane & 7);
                int cd = dtp * 16 + (lane >> 4) * 8;
                uint32_t off = (uint32_t)(rkv * 144 + cd * 2);
                ldmatrix_x4_trans(vh, bufb + 36864 + off);
                ldmatrix_x4_trans(vl, bufb + 55296 + off);
#pragma unroll
                for (int hf = 0; hf < 2; hf++)
                    mma16816(oacc[2 * dtp + hf], pa, vh + 2 * hf);
#pragma unroll
                for (int hf = 0; hf < 2; hf++)
                    mma16816(oacc[2 * dtp + hf], pa, vl + 2 * hf);
#pragma unroll
                for (int hf = 0; hf < 2; hf++)
                    mma16816(oacc[2 * dtp + hf], pl, vh + 2 * hf);
            }
        }
        __syncthreads();
    }

    float inv0 = 1.0f / l0, inv1 = 1.0f / l1;
    __nv_bfloat16* dh0 = g_chi + ((size_t)(bb * S_LEN + row0)) * E_DIM + hh * 64;
    __nv_bfloat16* dl0 = g_clo + ((size_t)(bb * S_LEN + row0)) * E_DIM + hh * 64;
    __nv_bfloat16* dh1 = g_chi + ((size_t)(bb * S_LEN + row1)) * E_DIM + hh * 64;
    __nv_bfloat16* dl1 = g_clo + ((size_t)(bb * S_LEN + row1)) * E_DIM + hh * 64;
#pragma unroll
    for (int nt = 0; nt < 8; nt++) {
        int d = nt * 8 + tg * 2;
        uint32_t hv, lv;
        split2(oacc[nt][0] * inv0, oacc[nt][1] * inv0, hv, lv);
        *(uint32_t*)(dh0 + d) = hv;
        *(uint32_t*)(dl0 + d) = lv;
        split2(oacc[nt][2] * inv1, oacc[nt][3] * inv1, hv, lv);
        *(uint32_t*)(dh1 + d) = hv;
        *(uint32_t*)(dl1 + d) = lv;
    }
}

// ---------------------------------------------------------------------------
extern "C" void kernel_launch(void* const* d_in, const int* in_sizes, int n_in,
                              void* d_out, int out_size) {
    const float* x    = (const float*)d_in[0];
    const int*   mask = (const int*)d_in[1];
    const float* Wq   = (const float*)d_in[2];
    const float* bq   = (const float*)d_in[3];
    const float* Wk   = (const float*)d_in[4];
    const float* bk   = (const float*)d_in[5];
    const float* Wv   = (const float*)d_in[6];
    const float* bv   = (const float*)d_in[7];
    const float* Wo   = (const float*)d_in[8];
    const float* bo   = (const float*)d_in[9];
    float* out = (float*)d_out;

    __nv_bfloat16 *pxhi, *pxlo;
    cudaGetSymbolAddress((void**)&pxhi, g_xhi);
    cudaGetSymbolAddress((void**)&pxlo, g_xlo);

    rope_table_kernel<<<(S_LEN * 32 + 255) / 256, 256>>>(bq, bk, bv);

    const int n4 = M_ROWS * E_DIM / 4;
    cvt_split_kernel<<<(n4 + 255) / 256, 256>>>(
        (const float4*)x, (__nv_bfloat162*)pxhi, (__nv_bfloat162*)pxlo, n4);

    cvt_transpose4_kernel<<<dim3(32, 32, 4), 256>>>(Wq, Wk, Wv, Wo);

    cudaFuncSetAttribute(tgemm_qkv_kernel, cudaFuncAttributeMaxDynamicSharedMemorySize, GSMEM);
    cudaFuncSetAttribute(tgemm_out_kernel, cudaFuncAttributeMaxDynamicSharedMemorySize, GSMEM);
    cudaFuncSetAttribute(attn_kernel, cudaFuncAttributeMaxDynamicSharedMemorySize, ATT_SMEM);

    tgemm_qkv_kernel<<<dim3(E_DIM / 128, M_ROWS / 128, 3), 256, GSMEM>>>();

    attn_kernel<<<dim3(S_LEN / 128, BATCH * N_HEADS), 256, ATT_SMEM>>>(mask);

    tgemm_out_kernel<<<dim3(E_DIM / 128, M_ROWS / 128), 256, GSMEM>>>(bo, out);
}

// round 8
// speedup vs baseline: 2.9395x; 1.0039x over previous
#include <cuda_runtime.h>
#include <cuda_bf16.h>
#include <math.h>
#include <stdint.h>

#define S_LEN 2048
#define E_DIM 1024
#define N_HEADS 16
#define HD 64
#define BATCH 2
#define M_ROWS 4096
#define SCALE_Q 0.18033688011112042f   // 0.125 * log2(e)

// ---------------- scratch ---------------------------------------------------
__device__ __align__(256) float g_cos[S_LEN * 32];
__device__ __align__(256) float g_sin[S_LEN * 32];
__device__ __align__(256) float g_bias[3 * E_DIM];
__device__ __align__(256) __nv_bfloat16 g_xhi[(size_t)M_ROWS * E_DIM];
__device__ __align__(256) __nv_bfloat16 g_xlo[(size_t)M_ROWS * E_DIM];
__device__ __align__(256) __nv_bfloat16 g_chi[(size_t)M_ROWS * E_DIM];
__device__ __align__(256) __nv_bfloat16 g_clo[(size_t)M_ROWS * E_DIM];
__device__ __align__(256) __nv_bfloat16 g_qhi[(size_t)M_ROWS * E_DIM];
__device__ __align__(256) __nv_bfloat16 g_qlo[(size_t)M_ROWS * E_DIM];
__device__ __align__(256) __nv_bfloat16 g_khi[(size_t)M_ROWS * E_DIM];
__device__ __align__(256) __nv_bfloat16 g_klo[(size_t)M_ROWS * E_DIM];
__device__ __align__(256) __nv_bfloat16 g_vhi[(size_t)M_ROWS * E_DIM];
__device__ __align__(256) __nv_bfloat16 g_vlo[(size_t)M_ROWS * E_DIM];
__device__ __align__(256) __nv_bfloat16 g_wthi[4][(size_t)E_DIM * E_DIM];  // [N][K]
__device__ __align__(256) __nv_bfloat16 g_wtlo[4][(size_t)E_DIM * E_DIM];

// ---------------- helpers ---------------------------------------------------
__device__ __forceinline__ uint32_t smem_u32(const void* p) {
    uint32_t a;
    asm("{ .reg .u64 t; cvta.to.shared.u64 t, %1; cvt.u32.u64 %0, t; }"
        : "=r"(a) : "l"(p));
    return a;
}
__device__ __forceinline__ void ldmatrix_x4(uint32_t* r, uint32_t addr) {
    asm volatile("ldmatrix.sync.aligned.m8n8.x4.shared.b16 {%0,%1,%2,%3}, [%4];"
                 : "=r"(r[0]), "=r"(r[1]), "=r"(r[2]), "=r"(r[3]) : "r"(addr));
}
__device__ __forceinline__ void ldmatrix_x4_trans(uint32_t* r, uint32_t addr) {
    asm volatile("ldmatrix.sync.aligned.m8n8.x4.trans.shared.b16 {%0,%1,%2,%3}, [%4];"
                 : "=r"(r[0]), "=r"(r[1]), "=r"(r[2]), "=r"(r[3]) : "r"(addr));
}
__device__ __forceinline__ void mma16816(float* c, const uint32_t* a, const uint32_t* b) {
    asm("mma.sync.aligned.m16n8k16.row.col.f32.bf16.bf16.f32 "
        "{%0,%1,%2,%3}, {%4,%5,%6,%7}, {%8,%9}, {%0,%1,%2,%3};"
        : "+f"(c[0]), "+f"(c[1]), "+f"(c[2]), "+f"(c[3])
        : "r"(a[0]), "r"(a[1]), "r"(a[2]), "r"(a[3]), "r"(b[0]), "r"(b[1]));
}
__device__ __forceinline__ void cp_async16(uint32_t dst, const void* src) {
    asm volatile("cp.async.cg.shared.global [%0], [%1], 16;" :: "r"(dst), "l"(src));
}
__device__ __forceinline__ float ex2(float x) {
    float y;
    asm("ex2.approx.f32 %0, %1;" : "=f"(y) : "f"(x));
    return y;
}
__device__ __forceinline__ void split2(float x, float y, uint32_t& h, uint32_t& l) {
    __nv_bfloat162 hb = __floats2bfloat162_rn(x, y);
    float2 hf = __bfloat1622float2(hb);
    __nv_bfloat162 lb = __floats2bfloat162_rn(x - hf.x, y - hf.y);
    h = *(uint32_t*)&hb;
    l = *(uint32_t*)&lb;
}

// ---------------------------------------------------------------------------
__global__ void rope_table_kernel(const float* __restrict__ bq,
                                  const float* __restrict__ bk,
                                  const float* __restrict__ bv) {
    int i = blockIdx.x * blockDim.x + threadIdx.x;
    if (i < 3 * E_DIM) {
        const float* b = (i < E_DIM) ? bq : (i < 2 * E_DIM) ? bk : bv;
        g_bias[i] = b[i & (E_DIM - 1)];
    }
    if (i >= S_LEN * 32) return;
    int s = i >> 5, j = i & 31;
    float inv = (float)pow(10000.0, -(double)j / 32.0);
    float th = (float)s * inv;
    g_cos[i] = cosf(th);
    g_sin[i] = sinf(th);
}

__global__ void cvt_split_kernel(const float4* __restrict__ src,
                                 __nv_bfloat162* __restrict__ hi,
                                 __nv_bfloat162* __restrict__ lo, int n4) {
    int i = blockIdx.x * blockDim.x + threadIdx.x;
    if (i >= n4) return;
    float4 v = src[i];
    __nv_bfloat162 h01 = __floats2bfloat162_rn(v.x, v.y);
    __nv_bfloat162 h23 = __floats2bfloat162_rn(v.z, v.w);
    float2 f01 = __bfloat1622float2(h01);
    float2 f23 = __bfloat1622float2(h23);
    hi[2 * i] = h01;
    hi[2 * i + 1] = h23;
    lo[2 * i] = __floats2bfloat162_rn(v.x - f01.x, v.y - f01.y);
    lo[2 * i + 1] = __floats2bfloat162_rn(v.z - f23.x, v.w - f23.y);
}

__global__ void cvt_transpose4_kernel(const float* __restrict__ W0,
                                      const float* __restrict__ W1,
                                      const float* __restrict__ W2,
                                      const float* __restrict__ W3) {
    __shared__ float t[32][33];
    const float* Ws[4] = {W0, W1, W2, W3};
    const float* W = Ws[blockIdx.z];
    __nv_bfloat16* thiz = g_wthi[blockIdx.z];
    __nv_bfloat16* tloz = g_wtlo[blockIdx.z];
    int bx = blockIdx.x, by = blockIdx.y;
    int tid = threadIdx.x;
#pragma unroll
    for (int it = 0; it < 4; it++) {
        int idx = tid + it * 256;
        int r = idx >> 5, c = idx & 31;
        t[r][c] = W[(size_t)(by * 32 + r) * E_DIM + bx * 32 + c];
    }
    __syncthreads();
#pragma unroll
    for (int it = 0; it < 4; it++) {
        int idx = tid + it * 256;
        int r = idx >> 5, c = idx & 31;
        float x = t[c][r];
        __nv_bfloat16 h = __float2bfloat16(x);
        size_t o = (size_t)(bx * 32 + r) * E_DIM + by * 32 + c;
        thiz[o] = h;
        tloz[o] = __float2bfloat16(x - __bfloat162float(h));
    }
}

// ---------------------------------------------------------------------------
// Split-bf16 mma.sync GEMM mainloop. 128x128 tile, BK=64, 8 warps (4x2).
// ONE __syncthreads per chunk: wait(0); sync; prefetch c+1; compute c.
// ---------------------------------------------------------------------------
#define TSTRIDE 72                       // bf16 per smem row (64 + 8 pad)
#define TILE_BYTES (128 * TSTRIDE * 2)   // 18432
#define NCHUNK 16
#define GSMEM (2 * 4 * TILE_BYTES)       // 147456

__device__ __forceinline__ void load_chunk_async(
    const __nv_bfloat16* __restrict__ Ahi, const __nv_bfloat16* __restrict__ Alo,
    const __nv_bfloat16* __restrict__ Bhi, const __nv_bfloat16* __restrict__ Blo,
    int m0, int n0, int k0, uint32_t st, int tid) {
    const __nv_bfloat16* srcs[4] = {Ahi, Alo, Bhi, Blo};
    int r0s[4] = {m0, m0, n0, n0};
#pragma unroll
    for (int tno = 0; tno < 4; tno++) {
        uint32_t sdst = st + tno * TILE_BYTES;
        const __nv_bfloat16* src = srcs[tno];
        int row0 = r0s[tno];
#pragma unroll
        for (int it = 0; it < 4; it++) {
            int idx = tid + it * 256;            // 0..1023
            int r = idx >> 3, seg = idx & 7;
            cp_async16(sdst + (uint32_t)(r * 144 + seg * 16),
                       src + (size_t)(row0 + r) * E_DIM + k0 + seg * 8);
        }
    }
}

__device__ __forceinline__ void gemm_mainloop(
    const __nv_bfloat16* __restrict__ Ahi, const __nv_bfloat16* __restrict__ Alo,
    const __nv_bfloat16* __restrict__ Bthi, const __nv_bfloat16* __restrict__ Btlo,
    int m0, int n0, uint32_t sbase, int tid, int wm, int wn, int lane,
    float acc[2][8][4]) {

    load_chunk_async(Ahi, Alo, Bthi, Btlo, m0, n0, 0, sbase, tid);
    asm volatile("cp.async.commit_group;");

    for (int c = 0; c < NCHUNK; c++) {
        asm volatile("cp.async.wait_group 0;");
        __syncthreads();   // publishes chunk c; guards overwrite of buf (c+1)&1
        if (c + 1 < NCHUNK) {
            load_chunk_async(Ahi, Alo, Bthi, Btlo, m0, n0, (c + 1) << 6,
                             sbase + ((c + 1) & 1) * 4 * TILE_BYTES, tid);
            asm volatile("cp.async.commit_group;");
        }

        const uint32_t st = sbase + (c & 1) * 4 * TILE_BYTES;
        const uint32_t Ahi_s = st, Alo_s = st + TILE_BYTES;
        const uint32_t Bhi_s = st + 2 * TILE_BYTES, Blo_s = st + 3 * TILE_BYTES;

#pragma unroll
        for (int ks = 0; ks < 4; ks++) {
            uint32_t ah[2][4], al[2][4];
#pragma unroll
            for (int mt = 0; mt < 2; mt++) {
                int row = wm * 32 + mt * 16 + (lane & 15);
                int kb = ks * 16 + ((lane >> 4) << 3);
                uint32_t off = (uint32_t)(row * 144 + kb * 2);
                ldmatrix_x4(ah[mt], Ahi_s + off);
                ldmatrix_x4(al[mt], Alo_s + off);
            }
#pragma unroll
            for (int np = 0; np < 4; np++) {
                uint32_t bh[4], bl[4];
                int row = wn * 64 + np * 16 + ((lane >> 4) << 3) + (lane & 7);
                int kb = ks * 16 + (((lane >> 3) & 1) << 3);
                uint32_t off = (uint32_t)(row * 144 + kb * 2);
                ldmatrix_x4(bh, Bhi_s + off);
                ldmatrix_x4(bl, Blo_s + off);
#pragma unroll
                for (int half = 0; half < 2; half++)
#pragma unroll
                    for (int mt = 0; mt < 2; mt++)
                        mma16816(acc[mt][2 * np + half], ah[mt], bh + 2 * half);
#pragma unroll
                for (int half = 0; half < 2; half++)
#pragma unroll
                    for (int mt = 0; mt < 2; mt++)
                        mma16816(acc[mt][2 * np + half], ah[mt], bl + 2 * half);
#pragma unroll
                for (int half = 0; half < 2; half++)
#pragma unroll
                    for (int mt = 0; mt < 2; mt++)
                        mma16816(acc[mt][2 * np + half], al[mt], bh + 2 * half);
            }
        }
    }
}

// Fused QKV projection: z = 0:Q(+RoPE+scale) 1:K(+RoPE) 2:V
__global__ __launch_bounds__(256)
void tgemm_qkv_kernel() {
    extern __shared__ __align__(1024) char dsm[];
    const uint32_t sbase = smem_u32(dsm);
    const int tid = threadIdx.x;
    const int wid = tid >> 5, lane = tid & 31;
    const int wm = wid & 3, wn = wid >> 2;
    const int g = lane >> 2, tg = lane & 3;
    const int m0 = blockIdx.y << 7, n0 = blockIdx.x << 7;
    const int z = blockIdx.z;

    const __nv_bfloat16* Bthi = g_wthi[z];
    const __nv_bfloat16* Btlo = g_wtlo[z];
    const float* bias = g_bias + (z << 10);
    __nv_bfloat16* Chi = (z == 0) ? g_qhi : (z == 1) ? g_khi : g_vhi;
    __nv_bfloat16* Clo = (z == 0) ? g_qlo : (z == 1) ? g_klo : g_vlo;

    float acc[2][8][4] = {};
    gemm_mainloop(g_xhi, g_xlo, Bthi, Btlo, m0, n0, sbase, tid, wm, wn, lane, acc);

#pragma unroll
    for (int mt = 0; mt < 2; mt++) {
#pragma unroll
        for (int h2 = 0; h2 < 2; h2++) {
            int m = m0 + wm * 32 + mt * 16 + g + h2 * 8;
            int bb = m >> 11, s = m & (S_LEN - 1);
            int h = (n0 + wn * 64) >> 6;
            size_t rb = (((size_t)(bb * N_HEADS + h)) * S_LEN + s) << 6;
            float vals[8][2];
#pragma unroll
            for (int nt = 0; nt < 8; nt++) {
                int col = nt * 8 + tg * 2;
                float2 bv = *(const float2*)&bias[n0 + wn * 64 + col];
                vals[nt][0] = acc[mt][nt][h2 * 2 + 0] + bv.x;
                vals[nt][1] = acc[mt][nt][h2 * 2 + 1] + bv.y;
            }
            if (z < 2) {
#pragma unroll
                for (int nt = 0; nt < 4; nt++) {
#pragma unroll
                    for (int jj = 0; jj < 2; jj++) {
                        int d = nt * 8 + tg * 2 + jj;
                        float cth = g_cos[(s << 5) + d];
                        float sth = g_sin[(s << 5) + d];
                        float lo = vals[nt][jj], hi = vals[nt + 4][jj];
                        vals[nt][jj]     = fmaf(lo, cth, -hi * sth);
                        vals[nt + 4][jj] = fmaf(hi, cth,  lo * sth);
                    }
                }
            }
            if (z == 0) {
#pragma unroll
                for (int nt = 0; nt < 8; nt++) {
                    vals[nt][0] *= SCALE_Q;
                    vals[nt][1] *= SCALE_Q;
                }
            }
#pragma unroll
            for (int nt = 0; nt < 8; nt++) {
                uint32_t hv, lv;
                split2(vals[nt][0], vals[nt][1], hv, lv);
                *(uint32_t*)(Chi + rb + nt * 8 + tg * 2) = hv;
                *(uint32_t*)(Clo + rb + nt * 8 + tg * 2) = lv;
            }
        }
    }
}

// Output projection
__global__ __launch_bounds__(256)
void tgemm_out_kernel(const float* __restrict__ bias, float* __restrict__ C) {
    extern __shared__ __align__(1024) char dsm[];
    const uint32_t sbase = smem_u32(dsm);
    const int tid = threadIdx.x;
    const int wid = tid >> 5, lane = tid & 31;
    const int wm = wid & 3, wn = wid >> 2;
    const int g = lane >> 2, tg = lane & 3;
    const int m0 = blockIdx.y << 7, n0 = blockIdx.x << 7;

    float acc[2][8][4] = {};
    gemm_mainloop(g_chi, g_clo, g_wthi[3], g_wtlo[3], m0, n0, sbase, tid, wm, wn, lane, acc);

#pragma unroll
    for (int mt = 0; mt < 2; mt++) {
#pragma unroll
        for (int h2 = 0; h2 < 2; h2++) {
            int m = m0 + wm * 32 + mt * 16 + g + h2 * 8;
            float* dst = &C[(size_t)m * E_DIM + n0 + wn * 64];
#pragma unroll
            for (int nt = 0; nt < 8; nt++) {
                int col = nt * 8 + tg * 2;
                float2 bv = *(const float2*)&bias[n0 + wn * 64 + col];
                *(float2*)&dst[col] = make_float2(acc[mt][nt][h2 * 2 + 0] + bv.x,
                                                  acc[mt][nt][h2 * 2 + 1] + bv.y);
            }
        }
    }
}

// ---------------------------------------------------------------------------
// Tensorized flash attention. Q-tile 128, KV-tile 128, 8 warps.
// One __syncthreads per KV tile (wait 0; sync; prefetch t+1; compute t).
// ---------------------------------------------------------------------------
#define ATT_Q    0
#define ATT_QL   18432
#define ATT_BUF0 36864
#define ATT_BUFSZ 74240
#define ATT_SMEM (36864 + 2 * ATT_BUFSZ)

__device__ __forceinline__ void attn_issue_kv(
    const __nv_bfloat16* khi, const __nv_bfloat16* klo,
    const __nv_bfloat16* vhi, const __nv_bfloat16* vlo,
    const int* mask, int mask_off, uint32_t sb, int t, int tid) {
    uint32_t bufb = sb + ATT_BUF0 + (t & 1) * ATT_BUFSZ;
    int k0 = t << 7;
    const __nv_bfloat16* srcs[4] = {khi, klo, vhi, vlo};
#pragma unroll
    for (int i = 0; i < 16; i++) {
        int idx = tid + i * 256;
        int arr = idx >> 10;
        int r = (idx >> 3) & 127, seg = idx & 7;
        cp_async16(bufb + arr * 18432 + (uint32_t)(r * 144 + seg * 16),
                   srcs[arr] + (size_t)(k0 + r) * HD + seg * 8);
    }
    if (tid < 32)
        cp_async16(bufb + 73728 + tid * 16, mask + mask_off + k0 + tid * 4);
}

__global__ __launch_bounds__(256)
void attn_kernel(const int* __restrict__ mask) {
    extern __shared__ __align__(1024) char sm_[];
    const uint32_t sb = smem_u32(sm_);
    const int tid = threadIdx.x, w = tid >> 5, lane = tid & 31;
    const int g = lane >> 2, tg = lane & 3;
    const int qt = gridDim.x - 1 - blockIdx.x;
    const int bh = blockIdx.y, bb = bh >> 4, hh = bh & 15;
    const int q0 = qt << 7;
    const size_t base = (size_t)bh * S_LEN * HD;

    {
        const __nv_bfloat16* s0 = g_qhi + base + (size_t)q0 * HD;
        const __nv_bfloat16* s1 = g_qlo + base + (size_t)q0 * HD;
#pragma unroll
        for (int i = 0; i < 8; i++) {
            int idx = tid + i * 256;
            int arr = idx >> 10;
            int r = (idx >> 3) & 127, seg = idx & 7;
            uint4 v = *(const uint4*)((arr ? s1 : s0) + (size_t)r * HD + seg * 8);
            *(uint4*)(sm_ + (arr ? ATT_QL : ATT_Q) + r * 144 + seg * 16) = v;
        }
    }

    const int ntile = qt + 1;
    attn_issue_kv(g_khi + base, g_klo + base, g_vhi + base, g_vlo + base,
                  mask, bb * S_LEN, sb, 0, tid);
    asm volatile("cp.async.commit_group;");
    __syncthreads();   // Q visible for ldmatrix

    uint32_t qfh[4][4], qfl[4][4];
    {
        int i = lane & 15;
        int prow = (i < 8) ? (w * 8 + i) : (64 + w * 8 + (i - 8));
        int kb = ((lane >> 4) << 3);
#pragma unroll
        for (int ks = 0; ks < 4; ks++) {
            uint32_t off = (uint32_t)(prow * 144 + (ks * 16 + kb) * 2);
            ldmatrix_x4(qfh[ks], sb + ATT_Q + off);
            ldmatrix_x4(qfl[ks], sb + ATT_QL + off);
        }
    }
    const int row0 = q0 + w * 8 + g;
    const int row1 = q0 + 64 + w * 8 + g;

    float oacc[8][4] = {};
    float l0 = 0.f, l1 = 0.f, mo0 = -1e30f, mo1 = -1e30f;

    for (int t = 0; t < ntile; t++) {
        asm volatile("cp.async.wait_group 0;");
        __syncthreads();   // publishes KV tile t; guards overwrite of buf (t+1)&1
        if (t + 1 < ntile) {
            attn_issue_kv(g_khi + base, g_klo + base, g_vhi + base, g_vlo + base,
                          mask, bb * S_LEN, sb, t + 1, tid);
            asm volatile("cp.async.commit_group;");
        }
        const uint32_t bufb = sb + ATT_BUF0 + (t & 1) * ATT_BUFSZ;
        const int k0 = t << 7;

        float sc[16][4] = {};
#pragma unroll
        for (int ks = 0; ks < 4; ks++) {
#pragma unroll
            for (int ntp = 0; ntp < 8; ntp++) {
                uint32_t kh[4], kl[4];
                int row = ntp * 16 + ((lane >> 4) << 3) + (lane & 7);
                int kb = ks * 16 + (((lane >> 3) & 1) << 3);
                uint32_t off = (uint32_t)(row * 144 + kb * 2);
                ldmatrix_x4(kh, bufb + off);
                ldmatrix_x4(kl, bufb + 18432 + off);
#pragma unroll
                for (int hf = 0; hf < 2; hf++)
                    mma16816(sc[2 * ntp + hf], qfh[ks], kh + 2 * hf);
#pragma unroll
                for (int hf = 0; hf < 2; hf++)
                    mma16816(sc[2 * ntp + hf], qfh[ks], kl + 2 * hf);
#pragma unroll
                for (int hf = 0; hf < 2; hf++)
                    mma16816(sc[2 * ntp + hf], qfl[ks], kh + 2 * hf);
            }
        }

        const int* Ms = (const int*)(sm_ + ATT_BUF0 + (t & 1) * ATT_BUFSZ + 73728);
        uint32_t pb[4];
        pb[0] = __ballot_sync(0xffffffffu, Ms[lane] != 0);
        pb[1] = __ballot_sync(0xffffffffu, Ms[lane + 32] != 0);
        pb[2] = __ballot_sync(0xffffffffu, Ms[lane + 64] != 0);
        pb[3] = __ballot_sync(0xffffffffu, Ms[lane + 96] != 0);
        if ((pb[0] & pb[1] & pb[2] & pb[3]) != 0xffffffffu) {
#pragma unroll
            for (int nt = 0; nt < 16; nt++)
#pragma unroll
                for (int j = 0; j < 2; j++) {
                    int cl = nt * 8 + tg * 2 + j;
                    if (!((pb[cl >> 5] >> (cl & 31)) & 1)) {
                        sc[nt][j] = -1e30f;
                        sc[nt][2 + j] = -1e30f;
                    }
                }
        }
        if (k0 + 127 > row0) {
#pragma unroll
            for (int nt = 0; nt < 16; nt++)
#pragma unroll
                for (int j = 0; j < 2; j++) {
                    int cg = k0 + nt * 8 + tg * 2 + j;
                    if (cg > row0) sc[nt][j] = -1e30f;
                    if (cg > row1) sc[nt][2 + j] = -1e30f;
                }
        }

        float mx0 = -1e30f, mx1 = -1e30f;
#pragma unroll
        for (int nt = 0; nt < 16; nt++) {
            mx0 = fmaxf(mx0, fmaxf(sc[nt][0], sc[nt][1]));
            mx1 = fmaxf(mx1, fmaxf(sc[nt][2], sc[nt][3]));
        }
        mx0 = fmaxf(mx0, __shfl_xor_sync(0xffffffffu, mx0, 1));
        mx0 = fmaxf(mx0, __shfl_xor_sync(0xffffffffu, mx0, 2));
        mx1 = fmaxf(mx1, __shfl_xor_sync(0xffffffffu, mx1, 1));
        mx1 = fmaxf(mx1, __shfl_xor_sync(0xffffffffu, mx1, 2));
        float mn0 = fmaxf(mo0, mx0), mn1 = fmaxf(mo1, mx1);
        float al0 = ex2(mo0 - mn0), al1 = ex2(mo1 - mn1);
        float rs0 = 0.f, rs1 = 0.f;
#pragma unroll
        for (int nt = 0; nt < 16; nt++) {
            sc[nt][0] = ex2(sc[nt][0] - mn0);
            sc[nt][1] = ex2(sc[nt][1] - mn0);
            sc[nt][2] = ex2(sc[nt][2] - mn1);
            sc[nt][3] = ex2(sc[nt][3] - mn1);
            rs0 += sc[nt][0] + sc[nt][1];
            rs1 += sc[nt][2] + sc[nt][3];
        }
        rs0 += __shfl_xor_sync(0xffffffffu, rs0, 1);
        rs0 += __shfl_xor_sync(0xffffffffu, rs0, 2);
        rs1 += __shfl_xor_sync(0xffffffffu, rs1, 1);
        rs1 += __shfl_xor_sync(0xffffffffu, rs1, 2);
        l0 = l0 * al0 + rs0;
        l1 = l1 * al1 + rs1;
        mo0 = mn0; mo1 = mn1;
#pragma unroll
        for (int nt = 0; nt < 8; nt++) {
            oacc[nt][0] *= al0; oacc[nt][1] *= al0;
            oacc[nt][2] *= al1; oacc[nt][3] *= al1;
        }

#pragma unroll
        for (int ks = 0; ks < 8; ks++) {
            uint32_t pa[4], pl[4];
            split2(sc[2 * ks][0], sc[2 * ks][1], pa[0], pl[0]);
            split2(sc[2 * ks][2], sc[2 * ks][3], pa[1], pl[1]);
            split2(sc[2 * ks + 1][0], sc[2 * ks + 1][1], pa[2], pl[2]);
            split2(sc[2 * ks + 1][2], sc[2 * ks + 1][3], pa[3], pl[3]);
#pragma unroll
            for (int dtp = 0; dtp < 4; dtp++) {
                uint32_t vh[4], vl[4];
                int rkv = ks * 16 + ((lane >> 3) & 1) * 8 + (lane & 7);
                int cd = dtp * 16 + (lane >> 4) * 8;
                uint32_t off = (uint32_t)(rkv * 144 + cd * 2);
                ldmatrix_x4_trans(vh, bufb + 36864 + off);
                ldmatrix_x4_trans(vl, bufb + 55296 + off);
#pragma unroll
                for (int hf = 0; hf < 2; hf++)
                    mma16816(oacc[2 * dtp + hf], pa, vh + 2 * hf);
#pragma unroll
                for (int hf = 0; hf < 2; hf++)
                    mma16816(oacc[2 * dtp + hf], pa, vl + 2 * hf);
#pragma unroll
                for (int hf = 0; hf < 2; hf++)
                    mma16816(oacc[2 * dtp + hf], pl, vh + 2 * hf);
            }
        }
    }

    float inv0 = 1.0f / l0, inv1 = 1.0f / l1;
    __nv_bfloat16* dh0 = g_chi + ((size_t)(bb * S_LEN + row0)) * E_DIM + hh * 64;
    __nv_bfloat16* dl0 = g_clo + ((size_t)(bb * S_LEN + row0)) * E_DIM + hh * 64;
    __nv_bfloat16* dh1 = g_chi + ((size_t)(bb * S_LEN + row1)) * E_DIM + hh * 64;
    __nv_bfloat16* dl1 = g_clo + ((size_t)(bb * S_LEN + row1)) * E_DIM + hh * 64;
#pragma unroll
    for (int nt = 0; nt < 8; nt++) {
        int d = nt * 8 + tg * 2;
        uint32_t hv, lv;
        split2(oacc[nt][0] * inv0, oacc[nt][1] * inv0, hv, lv);
        *(uint32_t*)(dh0 + d) = hv;
        *(uint32_t*)(dl0 + d) = lv;
        split2(oacc[nt][2] * inv1, oacc[nt][3] * inv1, hv, lv);
        *(uint32_t*)(dh1 + d) = hv;
        *(uint32_t*)(dl1 + d) = lv;
    }
}

// ---------------------------------------------------------------------------
extern "C" void kernel_launch(void* const* d_in, const int* in_sizes, int n_in,
                              void* d_out, int out_size) {
    const float* x    = (const float*)d_in[0];
    const int*   mask = (const int*)d_in[1];
    const float* Wq   = (const float*)d_in[2];
    const float* bq   = (const float*)d_in[3];
    const float* Wk   = (const float*)d_in[4];
    const float* bk   = (const float*)d_in[5];
    const float* Wv   = (const float*)d_in[6];
    const float* bv   = (const float*)d_in[7];
    const float* Wo   = (const float*)d_in[8];
    const float* bo   = (const float*)d_in[9];
    float* out = (float*)d_out;

    __nv_bfloat16 *pxhi, *pxlo;
    cudaGetSymbolAddress((void**)&pxhi, g_xhi);
    cudaGetSymbolAddress((void**)&pxlo, g_xlo);

    rope_table_kernel<<<(S_LEN * 32 + 255) / 256, 256>>>(bq, bk, bv);

    const int n4 = M_ROWS * E_DIM / 4;
    cvt_split_kernel<<<(n4 + 255) / 256, 256>>>(
        (const float4*)x, (__nv_bfloat162*)pxhi, (__nv_bfloat162*)pxlo, n4);

    cvt_transpose4_kernel<<<dim3(32, 32, 4), 256>>>(Wq, Wk, Wv, Wo);

    cudaFuncSetAttribute(tgemm_qkv_kernel, cudaFuncAttributeMaxDynamicSharedMemorySize, GSMEM);
    cudaFuncSetAttribute(tgemm_out_kernel, cudaFuncAttributeMaxDynamicSharedMemorySize, GSMEM);
    cudaFuncSetAttribute(attn_kernel, cudaFuncAttributeMaxDynamicSharedMemorySize, ATT_SMEM);

    tgemm_qkv_kernel<<<dim3(E_DIM / 128, M_ROWS / 128, 3), 256, GSMEM>>>();

    attn_kernel<<<dim3(S_LEN / 128, BATCH * N_HEADS), 256, ATT_SMEM>>>(mask);

    tgemm_out_kernel<<<dim3(E_DIM / 128, M_ROWS / 128), 256, GSMEM>>>(bo, out);
}

// round 9
// speedup vs baseline: 3.0314x; 1.0313x over previous
#include <cuda_runtime.h>
#include <cuda_bf16.h>
#include <math.h>
#include <stdint.h>

#define S_LEN 2048
#define E_DIM 1024
#define N_HEADS 16
#define HD 64
#define BATCH 2
#define M_ROWS 4096
#define SCALE_Q 0.18033688011112042f   // 0.125 * log2(e)

// ---------------- scratch ---------------------------------------------------
__device__ __align__(256) float g_cos[S_LEN * 32];
__device__ __align__(256) float g_sin[S_LEN * 32];
__device__ __align__(256) float g_bias[3 * E_DIM];
__device__ __align__(256) __nv_bfloat16 g_xhi[(size_t)M_ROWS * E_DIM];
__device__ __align__(256) __nv_bfloat16 g_xlo[(size_t)M_ROWS * E_DIM];
__device__ __align__(256) __nv_bfloat16 g_chi[(size_t)M_ROWS * E_DIM];
__device__ __align__(256) __nv_bfloat16 g_clo[(size_t)M_ROWS * E_DIM];
__device__ __align__(256) __nv_bfloat16 g_qhi[(size_t)M_ROWS * E_DIM];
__device__ __align__(256) __nv_bfloat16 g_qlo[(size_t)M_ROWS * E_DIM];
__device__ __align__(256) __nv_bfloat16 g_khi[(size_t)M_ROWS * E_DIM];
__device__ __align__(256) __nv_bfloat16 g_klo[(size_t)M_ROWS * E_DIM];
__device__ __align__(256) __nv_bfloat16 g_vhi[(size_t)M_ROWS * E_DIM];
__device__ __align__(256) __nv_bfloat16 g_vlo[(size_t)M_ROWS * E_DIM];
__device__ __align__(256) __nv_bfloat16 g_wthi[4][(size_t)E_DIM * E_DIM];  // [N][K]
__device__ __align__(256) __nv_bfloat16 g_wtlo[4][(size_t)E_DIM * E_DIM];

// ---------------- helpers ---------------------------------------------------
__device__ __forceinline__ uint32_t smem_u32(const void* p) {
    uint32_t a;
    asm("{ .reg .u64 t; cvta.to.shared.u64 t, %1; cvt.u32.u64 %0, t; }"
        : "=r"(a) : "l"(p));
    return a;
}
__device__ __forceinline__ void ldmatrix_x4(uint32_t* r, uint32_t addr) {
    asm volatile("ldmatrix.sync.aligned.m8n8.x4.shared.b16 {%0,%1,%2,%3}, [%4];"
                 : "=r"(r[0]), "=r"(r[1]), "=r"(r[2]), "=r"(r[3]) : "r"(addr));
}
__device__ __forceinline__ void ldmatrix_x4_trans(uint32_t* r, uint32_t addr) {
    asm volatile("ldmatrix.sync.aligned.m8n8.x4.trans.shared.b16 {%0,%1,%2,%3}, [%4];"
                 : "=r"(r[0]), "=r"(r[1]), "=r"(r[2]), "=r"(r[3]) : "r"(addr));
}
__device__ __forceinline__ void mma16816(float* c, const uint32_t* a, const uint32_t* b) {
    asm("mma.sync.aligned.m16n8k16.row.col.f32.bf16.bf16.f32 "
        "{%0,%1,%2,%3}, {%4,%5,%6,%7}, {%8,%9}, {%0,%1,%2,%3};"
        : "+f"(c[0]), "+f"(c[1]), "+f"(c[2]), "+f"(c[3])
        : "r"(a[0]), "r"(a[1]), "r"(a[2]), "r"(a[3]), "r"(b[0]), "r"(b[1]));
}
__device__ __forceinline__ void cp_async16(uint32_t dst, const void* src) {
    asm volatile("cp.async.cg.shared.global [%0], [%1], 16;" :: "r"(dst), "l"(src));
}
__device__ __forceinline__ float ex2(float x) {
    float y;
    asm("ex2.approx.f32 %0, %1;" : "=f"(y) : "f"(x));
    return y;
}
__device__ __forceinline__ void split2(float x, float y, uint32_t& h, uint32_t& l) {
    __nv_bfloat162 hb = __floats2bfloat162_rn(x, y);
    float2 hf = __bfloat1622float2(hb);
    __nv_bfloat162 lb = __floats2bfloat162_rn(x - hf.x, y - hf.y);
    h = *(uint32_t*)&hb;
    l = *(uint32_t*)&lb;
}

// ---------------------------------------------------------------------------
__global__ void rope_table_kernel(const float* __restrict__ bq,
                                  const float* __restrict__ bk,
                                  const float* __restrict__ bv) {
    int i = blockIdx.x * blockDim.x + threadIdx.x;
    if (i < 3 * E_DIM) {
        const float* b = (i < E_DIM) ? bq : (i < 2 * E_DIM) ? bk : bv;
        g_bias[i] = b[i & (E_DIM - 1)];
    }
    if (i >= S_LEN * 32) return;
    int s = i >> 5, j = i & 31;
    float inv = (float)pow(10000.0, -(double)j / 32.0);
    float th = (float)s * inv;
    g_cos[i] = cosf(th);
    g_sin[i] = sinf(th);
}

__global__ void cvt_split_kernel(const float4* __restrict__ src,
                                 __nv_bfloat162* __restrict__ hi,
                                 __nv_bfloat162* __restrict__ lo, int n4) {
    int i = blockIdx.x * blockDim.x + threadIdx.x;
    if (i >= n4) return;
    float4 v = src[i];
    __nv_bfloat162 h01 = __floats2bfloat162_rn(v.x, v.y);
    __nv_bfloat162 h23 = __floats2bfloat162_rn(v.z, v.w);
    float2 f01 = __bfloat1622float2(h01);
    float2 f23 = __bfloat1622float2(h23);
    hi[2 * i] = h01;
    hi[2 * i + 1] = h23;
    lo[2 * i] = __floats2bfloat162_rn(v.x - f01.x, v.y - f01.y);
    lo[2 * i + 1] = __floats2bfloat162_rn(v.z - f23.x, v.w - f23.y);
}

__global__ void cvt_transpose4_kernel(const float* __restrict__ W0,
                                      const float* __restrict__ W1,
                                      const float* __restrict__ W2,
                                      const float* __restrict__ W3) {
    __shared__ float t[32][33];
    const float* Ws[4] = {W0, W1, W2, W3};
    const float* W = Ws[blockIdx.z];
    __nv_bfloat16* thiz = g_wthi[blockIdx.z];
    __nv_bfloat16* tloz = g_wtlo[blockIdx.z];
    int bx = blockIdx.x, by = blockIdx.y;
    int tid = threadIdx.x;
#pragma unroll
    for (int it = 0; it < 4; it++) {
        int idx = tid + it * 256;
        int r = idx >> 5, c = idx & 31;
        t[r][c] = W[(size_t)(by * 32 + r) * E_DIM + bx * 32 + c];
    }
    __syncthreads();
#pragma unroll
    for (int it = 0; it < 4; it++) {
        int idx = tid + it * 256;
        int r = idx >> 5, c = idx & 31;
        float x = t[c][r];
        __nv_bfloat16 h = __float2bfloat16(x);
        size_t o = (size_t)(bx * 32 + r) * E_DIM + by * 32 + c;
        thiz[o] = h;
        tloz[o] = __float2bfloat16(x - __bfloat162float(h));
    }
}

// ---------------------------------------------------------------------------
// Split-bf16 mma.sync GEMM. CTA tile 256x128, BK=64, 8 warps (4x2),
// warp tile 64x64 (2x better smem-read amortization than 32x64).
// ---------------------------------------------------------------------------
#define A_TB 36864                      // 256 rows * 144 B
#define B_TB 18432                      // 128 rows * 144 B
#define BUF_BYTES (2 * A_TB + 2 * B_TB) // 110592
#define GSMEM (2 * BUF_BYTES)           // 221184
#define NCHUNK 16

__device__ __forceinline__ void load_chunk_async(
    const __nv_bfloat16* __restrict__ Ahi, const __nv_bfloat16* __restrict__ Alo,
    const __nv_bfloat16* __restrict__ Bhi, const __nv_bfloat16* __restrict__ Blo,
    int m0, int n0, int k0, uint32_t st, int tid) {
    // A: 256 rows x 64 bf16 (8 x 16B segs per row), hi + lo
#pragma unroll
    for (int it = 0; it < 8; it++) {
        int idx = tid + it * 256;            // 0..2047
        int r = idx >> 3, seg = idx & 7;
        uint32_t off = (uint32_t)(r * 144 + seg * 16);
        const size_t go = (size_t)(m0 + r) * E_DIM + k0 + seg * 8;
        cp_async16(st + off, Ahi + go);
        cp_async16(st + A_TB + off, Alo + go);
    }
    // B: 128 rows, hi + lo
#pragma unroll
    for (int it = 0; it < 4; it++) {
        int idx = tid + it * 256;            // 0..1023
        int r = idx >> 3, seg = idx & 7;
        uint32_t off = (uint32_t)(r * 144 + seg * 16);
        const size_t go = (size_t)(n0 + r) * E_DIM + k0 + seg * 8;
        cp_async16(st + 2 * A_TB + off, Bhi + go);
        cp_async16(st + 2 * A_TB + B_TB + off, Blo + go);
    }
}

__device__ __forceinline__ void gemm_mainloop(
    const __nv_bfloat16* __restrict__ Ahi, const __nv_bfloat16* __restrict__ Alo,
    const __nv_bfloat16* __restrict__ Bthi, const __nv_bfloat16* __restrict__ Btlo,
    int m0, int n0, uint32_t sbase, int tid, int wm, int wn, int lane,
    float acc[4][8][4]) {

    load_chunk_async(Ahi, Alo, Bthi, Btlo, m0, n0, 0, sbase, tid);
    asm volatile("cp.async.commit_group;");

    for (int c = 0; c < NCHUNK; c++) {
        asm volatile("cp.async.wait_group 0;");
        __syncthreads();   // publishes chunk c; guards overwrite of buf (c+1)&1
        if (c + 1 < NCHUNK) {
            load_chunk_async(Ahi, Alo, Bthi, Btlo, m0, n0, (c + 1) << 6,
                             sbase + ((c + 1) & 1) * BUF_BYTES, tid);
            asm volatile("cp.async.commit_group;");
        }

        const uint32_t st = sbase + (c & 1) * BUF_BYTES;
        const uint32_t Ahi_s = st, Alo_s = st + A_TB;
        const uint32_t Bhi_s = st + 2 * A_TB, Blo_s = st + 2 * A_TB + B_TB;

#pragma unroll
        for (int ks = 0; ks < 4; ks++) {
            uint32_t ah[4][4], al[4][4];
#pragma unroll
            for (int mt = 0; mt < 4; mt++) {
                int row = wm * 64 + mt * 16 + (lane & 15);
                int kb = ks * 16 + ((lane >> 4) << 3);
                uint32_t off = (uint32_t)(row * 144 + kb * 2);
                ldmatrix_x4(ah[mt], Ahi_s + off);
                ldmatrix_x4(al[mt], Alo_s + off);
            }
#pragma unroll
            for (int np = 0; np < 4; np++) {
                uint32_t bh[4], bl[4];
                int row = wn * 64 + np * 16 + ((lane >> 4) << 3) + (lane & 7);
                int kb = ks * 16 + (((lane >> 3) & 1) << 3);
                uint32_t off = (uint32_t)(row * 144 + kb * 2);
                ldmatrix_x4(bh, Bhi_s + off);
                ldmatrix_x4(bl, Blo_s + off);
#pragma unroll
                for (int half = 0; half < 2; half++)
#pragma unroll
                    for (int mt = 0; mt < 4; mt++)
                        mma16816(acc[mt][2 * np + half], ah[mt], bh + 2 * half);
#pragma unroll
                for (int half = 0; half < 2; half++)
#pragma unroll
                    for (int mt = 0; mt < 4; mt++)
                        mma16816(acc[mt][2 * np + half], ah[mt], bl + 2 * half);
#pragma unroll
                for (int half = 0; half < 2; half++)
#pragma unroll
                    for (int mt = 0; mt < 4; mt++)
                        mma16816(acc[mt][2 * np + half], al[mt], bh + 2 * half);
            }
        }
    }
}

// Fused QKV projection: z = 0:Q(+RoPE+scale) 1:K(+RoPE) 2:V
__global__ __launch_bounds__(256)
void tgemm_qkv_kernel() {
    extern __shared__ __align__(1024) char dsm[];
    const uint32_t sbase = smem_u32(dsm);
    const int tid = threadIdx.x;
    const int wid = tid >> 5, lane = tid & 31;
    const int wm = wid & 3, wn = wid >> 2;
    const int g = lane >> 2, tg = lane & 3;
    const int m0 = blockIdx.y << 8, n0 = blockIdx.x << 7;
    const int z = blockIdx.z;

    const __nv_bfloat16* Bthi = g_wthi[z];
    const __nv_bfloat16* Btlo = g_wtlo[z];
    const float* bias = g_bias + (z << 10);
    __nv_bfloat16* Chi = (z == 0) ? g_qhi : (z == 1) ? g_khi : g_vhi;
    __nv_bfloat16* Clo = (z == 0) ? g_qlo : (z == 1) ? g_klo : g_vlo;

    float acc[4][8][4] = {};
    gemm_mainloop(g_xhi, g_xlo, Bthi, Btlo, m0, n0, sbase, tid, wm, wn, lane, acc);

    const int h = (n0 + wn * 64) >> 6;
#pragma unroll
    for (int mt = 0; mt < 4; mt++) {
#pragma unroll
        for (int h2 = 0; h2 < 2; h2++) {
            int m = m0 + wm * 64 + mt * 16 + g + h2 * 8;
            int bb = m >> 11, s = m & (S_LEN - 1);
            size_t rb = (((size_t)(bb * N_HEADS + h)) * S_LEN + s) << 6;
            float vals[8][2];
#pragma unroll
            for (int nt = 0; nt < 8; nt++) {
                int col = nt * 8 + tg * 2;
                float2 bv = *(const float2*)&bias[n0 + wn * 64 + col];
                vals[nt][0] = acc[mt][nt][h2 * 2 + 0] + bv.x;
                vals[nt][1] = acc[mt][nt][h2 * 2 + 1] + bv.y;
            }
            if (z < 2) {
#pragma unroll
                for (int nt = 0; nt < 4; nt++) {
#pragma unroll
                    for (int jj = 0; jj < 2; jj++) {
                        int d = nt * 8 + tg * 2 + jj;
                        float cth = g_cos[(s << 5) + d];
                        float sth = g_sin[(s << 5) + d];
                        float lo = vals[nt][jj], hi = vals[nt + 4][jj];
                        vals[nt][jj]     = fmaf(lo, cth, -hi * sth);
                        vals[nt + 4][jj] = fmaf(hi, cth,  lo * sth);
                    }
                }
            }
            if (z == 0) {
#pragma unroll
                for (int nt = 0; nt < 8; nt++) {
                    vals[nt][0] *= SCALE_Q;
                    vals[nt][1] *= SCALE_Q;
                }
            }
#pragma unroll
            for (int nt = 0; nt < 8; nt++) {
                uint32_t hv, lv;
                split2(vals[nt][0], vals[nt][1], hv, lv);
                *(uint32_t*)(Chi + rb + nt * 8 + tg * 2) = hv;
                *(uint32_t*)(Clo + rb + nt * 8 + tg * 2) = lv;
            }
        }
    }
}

// Output projection
__global__ __launch_bounds__(256)
void tgemm_out_kernel(const float* __restrict__ bias, float* __restrict__ C) {
    extern __shared__ __align__(1024) char dsm[];
    const uint32_t sbase = smem_u32(dsm);
    const int tid = threadIdx.x;
    const int wid = tid >> 5, lane = tid & 31;
    const int wm = wid & 3, wn = wid >> 2;
    const int g = lane >> 2, tg = lane & 3;
    const int m0 = blockIdx.y << 8, n0 = blockIdx.x << 7;

    float acc[4][8][4] = {};
    gemm_mainloop(g_chi, g_clo, g_wthi[3], g_wtlo[3], m0, n0, sbase, tid, wm, wn, lane, acc);

#pragma unroll
    for (int mt = 0; mt < 4; mt++) {
#pragma unroll
        for (int h2 = 0; h2 < 2; h2++) {
            int m = m0 + wm * 64 + mt * 16 + g + h2 * 8;
            float* dst = &C[(size_t)m * E_DIM + n0 + wn * 64];
#pragma unroll
            for (int nt = 0; nt < 8; nt++) {
                int col = nt * 8 + tg * 2;
                float2 bv = *(const float2*)&bias[n0 + wn * 64 + col];
                *(float2*)&dst[col] = make_float2(acc[mt][nt][h2 * 2 + 0] + bv.x,
                                                  acc[mt][nt][h2 * 2 + 1] + bv.y);
            }
        }
    }
}

// ---------------------------------------------------------------------------
// Tensorized flash attention. Q-tile 128, KV-tile 128, 8 warps. (unchanged)
// ---------------------------------------------------------------------------
#define ATT_Q    0
#define ATT_QL   18432
#define ATT_BUF0 36864
#define ATT_BUFSZ 74240
#define ATT_SMEM (36864 + 2 * ATT_BUFSZ)

__device__ __forceinline__ void attn_issue_kv(
    const __nv_bfloat16* khi, const __nv_bfloat16* klo,
    const __nv_bfloat16* vhi, const __nv_bfloat16* vlo,
    const int* mask, int mask_off, uint32_t sb, int t, int tid) {
    uint32_t bufb = sb + ATT_BUF0 + (t & 1) * ATT_BUFSZ;
    int k0 = t << 7;
    const __nv_bfloat16* srcs[4] = {khi, klo, vhi, vlo};
#pragma unroll
    for (int i = 0; i < 16; i++) {
        int idx = tid + i * 256;
        int arr = idx >> 10;
        int r = (idx >> 3) & 127, seg = idx & 7;
        cp_async16(bufb + arr * 18432 + (uint32_t)(r * 144 + seg * 16),
                   srcs[arr] + (size_t)(k0 + r) * HD + seg * 8);
    }
    if (tid < 32)
        cp_async16(bufb + 73728 + tid * 16, mask + mask_off + k0 + tid * 4);
}

__global__ __launch_bounds__(256)
void attn_kernel(const int* __restrict__ mask) {
    extern __shared__ __align__(1024) char sm_[];
    const uint32_t sb = smem_u32(sm_);
    const int tid = threadIdx.x, w = tid >> 5, lane = tid & 31;
    const int g = lane >> 2, tg = lane & 3;
    const int qt = gridDim.x - 1 - blockIdx.x;
    const int bh = blockIdx.y, bb = bh >> 4, hh = bh & 15;
    const int q0 = qt << 7;
    const size_t base = (size_t)bh * S_LEN * HD;

    {
        const __nv_bfloat16* s0 = g_qhi + base + (size_t)q0 * HD;
        const __nv_bfloat16* s1 = g_qlo + base + (size_t)q0 * HD;
#pragma unroll
        for (int i = 0; i < 8; i++) {
            int idx = tid + i * 256;
            int arr = idx >> 10;
            int r = (idx >> 3) & 127, seg = idx & 7;
            uint4 v = *(const uint4*)((arr ? s1 : s0) + (size_t)r * HD + seg * 8);
            *(uint4*)(sm_ + (arr ? ATT_QL : ATT_Q) + r * 144 + seg * 16) = v;
        }
    }

    const int ntile = qt + 1;
    attn_issue_kv(g_khi + base, g_klo + base, g_vhi + base, g_vlo + base,
                  mask, bb * S_LEN, sb, 0, tid);
    asm volatile("cp.async.commit_group;");
    __syncthreads();

    uint32_t qfh[4][4], qfl[4][4];
    {
        int i = lane & 15;
        int prow = (i < 8) ? (w * 8 + i) : (64 + w * 8 + (i - 8));
        int kb = ((lane >> 4) << 3);
#pragma unroll
        for (int ks = 0; ks < 4; ks++) {
            uint32_t off = (uint32_t)(prow * 144 + (ks * 16 + kb) * 2);
            ldmatrix_x4(qfh[ks], sb + ATT_Q + off);
            ldmatrix_x4(qfl[ks], sb + ATT_QL + off);
        }
    }
    const int row0 = q0 + w * 8 + g;
    const int row1 = q0 + 64 + w * 8 + g;

    float oacc[8][4] = {};
    float l0 = 0.f, l1 = 0.f, mo0 = -1e30f, mo1 = -1e30f;

    for (int t = 0; t < ntile; t++) {
        asm volatile("cp.async.wait_group 0;");
        __syncthreads();
        if (t + 1 < ntile) {
            attn_issue_kv(g_khi + base, g_klo + base, g_vhi + base, g_vlo + base,
                          mask, bb * S_LEN, sb, t + 1, tid);
            asm volatile("cp.async.commit_group;");
        }
        const uint32_t bufb = sb + ATT_BUF0 + (t & 1) * ATT_BUFSZ;
        const int k0 = t << 7;

        float sc[16][4] = {};
#pragma unroll
        for (int ks = 0; ks < 4; ks++) {
#pragma unroll
            for (int ntp = 0; ntp < 8; ntp++) {
                uint32_t kh[4], kl[4];
                int row = ntp * 16 + ((lane >> 4) << 3) + (lane & 7);
                int kb = ks * 16 + (((lane >> 3) & 1) << 3);
                uint32_t off = (uint32_t)(row * 144 + kb * 2);
                ldmatrix_x4(kh, bufb + off);
                ldmatrix_x4(kl, bufb + 18432 + off);
#pragma unroll
                for (int hf = 0; hf < 2; hf++)
                    mma16816(sc[2 * ntp + hf], qfh[ks], kh + 2 * hf);
#pragma unroll
                for (int hf = 0; hf < 2; hf++)
                    mma16816(sc[2 * ntp + hf], qfh[ks], kl + 2 * hf);
#pragma unroll
                for (int hf = 0; hf < 2; hf++)
                    mma16816(sc[2 * ntp + hf], qfl[ks], kh + 2 * hf);
            }
        }

        const int* Ms = (const int*)(sm_ + ATT_BUF0 + (t & 1) * ATT_BUFSZ + 73728);
        uint32_t pb[4];
        pb[0] = __ballot_sync(0xffffffffu, Ms[lane] != 0);
        pb[1] = __ballot_sync(0xffffffffu, Ms[lane + 32] != 0);
        pb[2] = __ballot_sync(0xffffffffu, Ms[lane + 64] != 0);
        pb[3] = __ballot_sync(0xffffffffu, Ms[lane + 96] != 0);
        if ((pb[0] & pb[1] & pb[2] & pb[3]) != 0xffffffffu) {
#pragma unroll
            for (int nt = 0; nt < 16; nt++)
#pragma unroll
                for (int j = 0; j < 2; j++) {
                    int cl = nt * 8 + tg * 2 + j;
                    if (!((pb[cl >> 5] >> (cl & 31)) & 1)) {
                        sc[nt][j] = -1e30f;
                        sc[nt][2 + j] = -1e30f;
                    }
                }
        }
        if (k0 + 127 > row0) {
#pragma unroll
            for (int nt = 0; nt < 16; nt++)
#pragma unroll
                for (int j = 0; j < 2; j++) {
                    int cg = k0 + nt * 8 + tg * 2 + j;
                    if (cg > row0) sc[nt][j] = -1e30f;
                    if (cg > row1) sc[nt][2 + j] = -1e30f;
                }
        }

        float mx0 = -1e30f, mx1 = -1e30f;
#pragma unroll
        for (int nt = 0; nt < 16; nt++) {
            mx0 = fmaxf(mx0, fmaxf(sc[nt][0], sc[nt][1]));
            mx1 = fmaxf(mx1, fmaxf(sc[nt][2], sc[nt][3]));
        }
        mx0 = fmaxf(mx0, __shfl_xor_sync(0xffffffffu, mx0, 1));
        mx0 = fmaxf(mx0, __shfl_xor_sync(0xffffffffu, mx0, 2));
        mx1 = fmaxf(mx1, __shfl_xor_sync(0xffffffffu, mx1, 1));
        mx1 = fmaxf(mx1, __shfl_xor_sync(0xffffffffu, mx1, 2));
        float mn0 = fmaxf(mo0, mx0), mn1 = fmaxf(mo1, mx1);
        float al0 = ex2(mo0 - mn0), al1 = ex2(mo1 - mn1);
        float rs0 = 0.f, rs1 = 0.f;
#pragma unroll
        for (int nt = 0; nt < 16; nt++) {
            sc[nt][0] = ex2(sc[nt][0] - mn0);
            sc[nt][1] = ex2(sc[nt][1] - mn0);
            sc[nt][2] = ex2(sc[nt][2] - mn1);
            sc[nt][3] = ex2(sc[nt][3] - mn1);
            rs0 += sc[nt][0] + sc[nt][1];
            rs1 += sc[nt][2] + sc[nt][3];
        }
        rs0 += __shfl_xor_sync(0xffffffffu, rs0, 1);
        rs0 += __shfl_xor_sync(0xffffffffu, rs0, 2);
        rs1 += __shfl_xor_sync(0xffffffffu, rs1, 1);
        rs1 += __shfl_xor_sync(0xffffffffu, rs1, 2);
        l0 = l0 * al0 + rs0;
        l1 = l1 * al1 + rs1;
        mo0 = mn0; mo1 = mn1;
#pragma unroll
        for (int nt = 0; nt < 8; nt++) {
            oacc[nt][0] *= al0; oacc[nt][1] *= al0;
            oacc[nt][2] *= al1; oacc[nt][3] *= al1;
        }

#pragma unroll
        for (int ks = 0; ks < 8; ks++) {
            uint32_t pa[4], pl[4];
            split2(sc[2 * ks][0], sc[2 * ks][1], pa[0], pl[0]);
            split2(sc[2 * ks][2], sc[2 * ks][3], pa[1], pl[1]);
            split2(sc[2 * ks + 1][0], sc[2 * ks + 1][1], pa[2], pl[2]);
            split2(sc[2 * ks + 1][2], sc[2 * ks + 1][3], pa[3], pl[3]);
#pragma unroll
            for (int dtp = 0; dtp < 4; dtp++) {
                uint32_t vh[4], vl[4];
                int rkv = ks * 16 + ((lane >> 3) & 1) * 8 + (lane & 7);
                int cd = dtp * 16 + (lane >> 4) * 8;
                uint32_t off = (uint32_t)(rkv * 144 + cd * 2);
                ldmatrix_x4_trans(vh, bufb + 36864 + off);
                ldmatrix_x4_trans(vl, bufb + 55296 + off);
#pragma unroll
                for (int hf = 0; hf < 2; hf++)
                    mma16816(oacc[2 * dtp + hf], pa, vh + 2 * hf);
#pragma unroll
                for (int hf = 0; hf < 2; hf++)
                    mma16816(oacc[2 * dtp + hf], pa, vl + 2 * hf);
#pragma unroll
                for (int hf = 0; hf < 2; hf++)
                    mma16816(oacc[2 * dtp + hf], pl, vh + 2 * hf);
            }
        }
    }

    float inv0 = 1.0f / l0, inv1 = 1.0f / l1;
    __nv_bfloat16* dh0 = g_chi + ((size_t)(bb * S_LEN + row0)) * E_DIM + hh * 64;
    __nv_bfloat16* dl0 = g_clo + ((size_t)(bb * S_LEN + row0)) * E_DIM + hh * 64;
    __nv_bfloat16* dh1 = g_chi + ((size_t)(bb * S_LEN + row1)) * E_DIM + hh * 64;
    __nv_bfloat16* dl1 = g_clo + ((size_t)(bb * S_LEN + row1)) * E_DIM + hh * 64;
#pragma unroll
    for (int nt = 0; nt < 8; nt++) {
        int d = nt * 8 + tg * 2;
        uint32_t hv, lv;
        split2(oacc[nt][0] * inv0, oacc[nt][1] * inv0, hv, lv);
        *(uint32_t*)(dh0 + d) = hv;
        *(uint32_t*)(dl0 + d) = lv;
        split2(oacc[nt][2] * inv1, oacc[nt][3] * inv1, hv, lv);
        *(uint32_t*)(dh1 + d) = hv;
        *(uint32_t*)(dl1 + d) = lv;
    }
}

// ---------------------------------------------------------------------------
extern "C" void kernel_launch(void* const* d_in, const int* in_sizes, int n_in,
                              void* d_out, int out_size) {
    const float* x    = (const float*)d_in[0];
    const int*   mask = (const int*)d_in[1];
    const float* Wq   = (const float*)d_in[2];
    const float* bq   = (const float*)d_in[3];
    const float* Wk   = (const float*)d_in[4];
    const float* bk   = (const float*)d_in[5];
    const float* Wv   = (const float*)d_in[6];
    const float* bv   = (const float*)d_in[7];
    const float* Wo   = (const float*)d_in[8];
    const float* bo   = (const float*)d_in[9];
    float* out = (float*)d_out;

    __nv_bfloat16 *pxhi, *pxlo;
    cudaGetSymbolAddress((void**)&pxhi, g_xhi);
    cudaGetSymbolAddress((void**)&pxlo, g_xlo);

    rope_table_kernel<<<(S_LEN * 32 + 255) / 256, 256>>>(bq, bk, bv);

    const int n4 = M_ROWS * E_DIM / 4;
    cvt_split_kernel<<<(n4 + 255) / 256, 256>>>(
        (const float4*)x, (__nv_bfloat162*)pxhi, (__nv_bfloat162*)pxlo, n4);

    cvt_transpose4_kernel<<<dim3(32, 32, 4), 256>>>(Wq, Wk, Wv, Wo);

    cudaFuncSetAttribute(tgemm_qkv_kernel, cudaFuncAttributeMaxDynamicSharedMemorySize, GSMEM);
    cudaFuncSetAttribute(tgemm_out_kernel, cudaFuncAttributeMaxDynamicSharedMemorySize, GSMEM);
    cudaFuncSetAttribute(attn_kernel, cudaFuncAttributeMaxDynamicSharedMemorySize, ATT_SMEM);

    tgemm_qkv_kernel<<<dim3(E_DIM / 128, M_ROWS / 256, 3), 256, GSMEM>>>();

    attn_kernel<<<dim3(S_LEN / 128, BATCH * N_HEADS), 256, ATT_SMEM>>>(mask);

    tgemm_out_kernel<<<dim3(E_DIM / 128, M_ROWS / 256), 256, GSMEM>>>(bo, out);
}